// round 6
// baseline (speedup 1.0000x reference)
#include <cuda_runtime.h>
#include <cuda_bf16.h>
#include <math.h>
#include <stdint.h>

// ---------------- problem constants ----------------
#define B_   2
#define S_   4096
#define D_   512
#define BPL_ 4
#define H_   16
#define DQK_ 64
#define DLAT_ 1024
#define LQ_  (S_ / BPL_)          // 1024
#define EPS_ 1.1920929e-07f

// ---------------- scratch (device globals; no allocation allowed) ----------------
__device__ float g_qproj [B_ * LQ_ * H_ * DQK_];
__device__ float g_kvproj[B_ * S_ * 2 * H_ * DQK_];

// bf16 hi/lo split operands
__device__ __nv_bfloat16 g_normh[B_ * S_ * D_], g_norml[B_ * S_ * D_];
__device__ __nv_bfloat16 g_xh   [B_ * S_ * D_], g_xl   [B_ * S_ * D_];
__device__ __nv_bfloat16 g_wqh  [BPL_ * D_ * H_ * DQK_],  g_wql  [BPL_ * D_ * H_ * DQK_];
__device__ __nv_bfloat16 g_wkvh [D_ * 2 * H_ * DQK_],     g_wkvl [D_ * 2 * H_ * DQK_];
__device__ __nv_bfloat16 g_wouth[H_ * DQK_ * DLAT_],      g_woutl[H_ * DQK_ * DLAT_];
__device__ __nv_bfloat16 g_wbyph[BPL_ * D_ * DLAT_],      g_wbypl[BPL_ * D_ * DLAT_];
__device__ __nv_bfloat16 g_attnh[B_ * LQ_ * H_ * DQK_],   g_attnl[B_ * LQ_ * H_ * DQK_];

// bf16 hi/lo q,k,v for mma flash
__device__ __nv_bfloat16 g_qh[B_ * H_ * LQ_ * DQK_], g_ql[B_ * H_ * LQ_ * DQK_];
__device__ __nv_bfloat16 g_kh[B_ * H_ * S_ * DQK_],  g_kl[B_ * H_ * S_ * DQK_];
__device__ __nv_bfloat16 g_vh[B_ * H_ * S_ * DQK_],  g_vl[B_ * H_ * S_ * DQK_];

// ---------------- helpers ----------------
__device__ __forceinline__ uint32_t smem_to_u32(const void* p) {
    uint32_t a;
    asm("{ .reg .u64 t; cvta.to.shared.u64 t, %1; cvt.u32.u64 %0, t; }" : "=r"(a) : "l"(p));
    return a;
}

#define CP_ASYNC16(dst, src) \
    asm volatile("cp.async.cg.shared.global [%0], [%1], 16;" :: "r"(dst), "l"(src))
#define CP_COMMIT()  asm volatile("cp.async.commit_group;" ::: "memory")
#define CP_WAIT0()   asm volatile("cp.async.wait_group 0;" ::: "memory")
#define CP_WAIT1()   asm volatile("cp.async.wait_group 1;" ::: "memory")
#define CP_WAIT2()   asm volatile("cp.async.wait_group 2;" ::: "memory")
#define CP_WAIT3()   asm volatile("cp.async.wait_group 3;" ::: "memory")

__device__ __forceinline__ void ldmA(uint32_t* r, uint32_t addr) {
    asm volatile("ldmatrix.sync.aligned.m8n8.x4.shared.b16 {%0,%1,%2,%3}, [%4];"
                 : "=r"(r[0]), "=r"(r[1]), "=r"(r[2]), "=r"(r[3]) : "r"(addr));
}
__device__ __forceinline__ void ldmBT(uint32_t* r, uint32_t addr) {
    asm volatile("ldmatrix.sync.aligned.m8n8.x4.trans.shared.b16 {%0,%1,%2,%3}, [%4];"
                 : "=r"(r[0]), "=r"(r[1]), "=r"(r[2]), "=r"(r[3]) : "r"(addr));
}
__device__ __forceinline__ void mma16816(float* d, const uint32_t* a, const uint32_t* b) {
    asm volatile(
        "mma.sync.aligned.m16n8k16.row.col.f32.bf16.bf16.f32 "
        "{%0,%1,%2,%3}, {%4,%5,%6,%7}, {%8,%9}, {%0,%1,%2,%3};"
        : "+f"(d[0]), "+f"(d[1]), "+f"(d[2]), "+f"(d[3])
        : "r"(a[0]), "r"(a[1]), "r"(a[2]), "r"(a[3]), "r"(b[0]), "r"(b[1]));
}
__device__ __forceinline__ void mma2(float* d, const uint32_t* a, uint32_t b0, uint32_t b1) {
    asm volatile(
        "mma.sync.aligned.m16n8k16.row.col.f32.bf16.bf16.f32 "
        "{%0,%1,%2,%3}, {%4,%5,%6,%7}, {%8,%9}, {%0,%1,%2,%3};"
        : "+f"(d[0]), "+f"(d[1]), "+f"(d[2]), "+f"(d[3])
        : "r"(a[0]), "r"(a[1]), "r"(a[2]), "r"(a[3]), "r"(b0), "r"(b1));
}

__device__ __forceinline__ uint32_t packbf(float x, float y) {
    union { __nv_bfloat162 b; uint32_t u; } c;
    c.b = __halves2bfloat162(__float2bfloat16(x), __float2bfloat16(y));
    return c.u;
}

__device__ __forceinline__ void split4(float4 v, uint2& hi, uint2& lo) {
    __nv_bfloat16 hx = __float2bfloat16(v.x);
    __nv_bfloat16 hy = __float2bfloat16(v.y);
    __nv_bfloat16 hz = __float2bfloat16(v.z);
    __nv_bfloat16 hw = __float2bfloat16(v.w);
    union { __nv_bfloat162 b[2]; uint2 u; } c;
    c.b[0] = __halves2bfloat162(hx, hy);
    c.b[1] = __halves2bfloat162(hz, hw);
    hi = c.u;
    c.b[0] = __halves2bfloat162(__float2bfloat16(v.x - __bfloat162float(hx)),
                                __float2bfloat16(v.y - __bfloat162float(hy)));
    c.b[1] = __halves2bfloat162(__float2bfloat16(v.z - __bfloat162float(hz)),
                                __float2bfloat16(v.w - __bfloat162float(hw)));
    lo = c.u;
}

// ---------------- elementwise split: fp32 -> bf16 hi/lo ----------------
__global__ __launch_bounds__(256) void split_kernel(
    const float* __restrict__ src, __nv_bfloat16* __restrict__ hi,
    __nv_bfloat16* __restrict__ lo, int n4)
{
    int i = blockIdx.x * blockDim.x + threadIdx.x;
    if (i >= n4) return;
    float4 v = ((const float4*)src)[i];
    uint2 h, l;
    split4(v, h, l);
    ((uint2*)hi)[i] = h;
    ((uint2*)lo)[i] = l;
}

// ---------------- RMSNorm (fused hi/lo split output) ----------------
__global__ __launch_bounds__(128) void rmsnorm_kernel(
    const float* __restrict__ x, const float* __restrict__ w,
    __nv_bfloat16* __restrict__ hi, __nv_bfloat16* __restrict__ lo)
{
    int row = blockIdx.x;
    const float4* xr = (const float4*)(x + (size_t)row * D_);
    const float4* wr = (const float4*)w;
    int tid = threadIdx.x;

    float4 v = xr[tid];
    float s = v.x * v.x + v.y * v.y + v.z * v.z + v.w * v.w;
    #pragma unroll
    for (int o = 16; o > 0; o >>= 1) s += __shfl_xor_sync(0xffffffffu, s, o);
    __shared__ float red[4];
    int warp = tid >> 5, lane = tid & 31;
    if (lane == 0) red[warp] = s;
    __syncthreads();
    float total = red[0] + red[1] + red[2] + red[3];
    float inv = rsqrtf(total / (float)D_ + EPS_);
    float4 wv = wr[tid];
    float4 o4 = make_float4(v.x * inv * wv.x, v.y * inv * wv.y,
                            v.z * inv * wv.z, v.w * inv * wv.w);
    uint2 h, l;
    split4(o4, h, l);
    int idx = row * (D_ / 4) + tid;
    ((uint2*)hi)[idx] = h;
    ((uint2*)lo)[idx] = l;
}

// ---------------- split-bf16 mma.sync GEMM (4-stage cp.async pipeline) ----------------
#define BKF  32
#define ASTR 40
#define BSTR 136
#define GSTAGES 4
#define A_STG_B (128 * ASTR * 2)           // 10240
#define B_STG_B (BKF * BSTR * 2)           // 8704
#define STG_B   (A_STG_B + B_STG_B)        // 18944
#define GM_SMEM (GSTAGES * STG_B)          // 75776

__global__ __launch_bounds__(256) void gemm_mma(
    int M, int N, int K,
    const __nv_bfloat16* __restrict__ Ahi, const __nv_bfloat16* __restrict__ Alo,
    const __nv_bfloat16* __restrict__ Bhi, const __nv_bfloat16* __restrict__ Blo,
    const float* __restrict__ bias, float* __restrict__ C, int accum)
{
    extern __shared__ char gsm[];
    const uint32_t sBase = smem_to_u32(gsm);

    const int tid = threadIdx.x;
    const int wid = tid >> 5, lane = tid & 31;
    const int mBase = blockIdx.y * 128;
    const int nBase = blockIdx.x * 128;
    const int warpM = (wid >> 1) * 32;
    const int warpN = (wid & 1) * 64;

    const int cpk = K / BKF;
    const int total = 3 * cpk;

    const int arow0 = tid >> 2, aseg = (tid & 3) * 8;
    const int brow0 = tid >> 4, bseg = (tid & 15) * 8;

    float acc[2][8][4];
    #pragma unroll
    for (int mi = 0; mi < 2; mi++)
        #pragma unroll
        for (int ni = 0; ni < 8; ni++)
            #pragma unroll
            for (int c = 0; c < 4; c++) acc[mi][ni][c] = 0.0f;

    auto issue = [&](int chunk) {
        int buf = chunk & (GSTAGES - 1);
        int term = chunk / cpk;
        int k0 = (chunk - term * cpk) * BKF;
        const __nv_bfloat16* Asrc = (term < 2) ? Ahi : Alo;
        const __nv_bfloat16* Bsrc = (term == 1) ? Blo : Bhi;
        uint32_t da = sBase + buf * STG_B;
        uint32_t db = da + A_STG_B;
        const __nv_bfloat16* aptr = Asrc + (size_t)mBase * K + k0 + aseg;
        const __nv_bfloat16* bptr = Bsrc + (size_t)k0 * N + nBase + bseg;
        #pragma unroll
        for (int it = 0; it < 2; it++) {
            int row = arow0 + it * 64;
            CP_ASYNC16(da + row * (ASTR * 2) + aseg * 2, aptr + (size_t)row * K);
        }
        #pragma unroll
        for (int it = 0; it < 2; it++) {
            int row = brow0 + it * 16;
            CP_ASYNC16(db + row * (BSTR * 2) + bseg * 2, bptr + (size_t)row * N);
        }
        CP_COMMIT();
    };

    issue(0); issue(1); issue(2);

    for (int i = 0; i < total; i++) {
        if (i + 3 < total) issue(i + 3);   // overwrites buf (i-1)&3: protected by trailing sync

        if (i + 3 < total)      CP_WAIT3();
        else if (i + 2 < total) CP_WAIT2();
        else if (i + 1 < total) CP_WAIT1();
        else                    CP_WAIT0();
        __syncthreads();

        const uint32_t aBase = sBase + (i & (GSTAGES - 1)) * STG_B;
        const uint32_t bBase = aBase + A_STG_B;

        #pragma unroll
        for (int kk = 0; kk < 2; kk++) {
            uint32_t afrag[2][4];
            #pragma unroll
            for (int mi = 0; mi < 2; mi++) {
                uint32_t addr = aBase
                    + (warpM + mi * 16 + (lane & 15)) * (ASTR * 2)
                    + ((lane >> 4) << 4) + kk * 32;
                ldmA(afrag[mi], addr);
            }
            uint32_t bfrag[4][4];
            #pragma unroll
            for (int p = 0; p < 4; p++) {
                int grp = lane >> 3, r = lane & 7;
                uint32_t addr = bBase
                    + (kk * 16 + (grp & 1) * 8 + r) * (BSTR * 2)
                    + (warpN + p * 16 + (grp >> 1) * 8) * 2;
                ldmBT(bfrag[p], addr);
            }
            #pragma unroll
            for (int mi = 0; mi < 2; mi++)
                #pragma unroll
                for (int ni = 0; ni < 8; ni++)
                    mma16816(acc[mi][ni], afrag[mi], &bfrag[ni >> 1][(ni & 1) * 2]);
        }
        __syncthreads();
    }

    #pragma unroll
    for (int mi = 0; mi < 2; mi++) {
        #pragma unroll
        for (int ni = 0; ni < 8; ni++) {
            int r0 = mBase + warpM + mi * 16 + (lane >> 2);
            int c  = nBase + warpN + ni * 8 + (lane & 3) * 2;
            float2 v0 = make_float2(acc[mi][ni][0], acc[mi][ni][1]);
            float2 v1 = make_float2(acc[mi][ni][2], acc[mi][ni][3]);
            if (bias) {
                float2 bb = *(const float2*)(bias + c);
                v0.x += bb.x; v0.y += bb.y;
                v1.x += bb.x; v1.y += bb.y;
            }
            float* p0 = C + (size_t)r0 * N + c;
            float* p1 = C + (size_t)(r0 + 8) * N + c;
            if (accum) {
                float2 c0 = *(float2*)p0, c1 = *(float2*)p1;
                v0.x += c0.x; v0.y += c0.y;
                v1.x += c1.x; v1.y += c1.y;
            }
            *(float2*)p0 = v0;
            *(float2*)p1 = v1;
        }
    }
}

// ---------------- RoPE: emit bf16 hi/lo directly ----------------
__device__ __forceinline__ float inv_freq_f(int d)
{
    return (float)pow(10000.0, -(double)d / 32.0);
}

__device__ __forceinline__ void store_hl(__nv_bfloat16* hi, __nv_bfloat16* lo,
                                         size_t idx, float v)
{
    __nv_bfloat16 h = __float2bfloat16(v);
    hi[idx] = h;
    lo[idx] = __float2bfloat16(v - __bfloat162float(h));
}

__global__ __launch_bounds__(256) void rope_q_kernel(
    const float* __restrict__ qp,
    __nv_bfloat16* __restrict__ qhi, __nv_bfloat16* __restrict__ qlo)
{
    int idx = blockIdx.x * blockDim.x + threadIdx.x;
    int d  = idx & 31;
    int h  = (idx >> 5) & 15;
    int qi = (idx >> 9) & 1023;
    int b  = idx >> 19;
    const float* src = qp + ((size_t)(b * LQ_ + qi) * (H_ * DQK_)) + h * DQK_;
    float x1 = src[d], x2 = src[d + 32];
    float pos = (float)(qi * BPL_);
    float ang = pos * inv_freq_f(d);
    float c = cosf(ang), s = sinf(ang);
    size_t base = (((size_t)(b * H_ + h) * LQ_) + qi) * DQK_;
    store_hl(qhi, qlo, base + d,      (x1 * c - x2 * s) * 0.125f);
    store_hl(qhi, qlo, base + d + 32, (x1 * s + x2 * c) * 0.125f);
}

__global__ __launch_bounds__(256) void rope_k_kernel(
    const float* __restrict__ kvp,
    __nv_bfloat16* __restrict__ khi, __nv_bfloat16* __restrict__ klo)
{
    int idx = blockIdx.x * blockDim.x + threadIdx.x;
    int d  = idx & 31;
    int h  = (idx >> 5) & 15;
    int s  = (idx >> 9) & 4095;
    int b  = idx >> 21;
    const float* src = kvp + ((size_t)(b * S_ + s) * (2 * H_ * DQK_)) + h * DQK_;
    float x1 = src[d], x2 = src[d + 32];
    float pos = (float)s;
    float ang = pos * inv_freq_f(d);
    float c = cosf(ang), sn = sinf(ang);
    size_t base = (((size_t)(b * H_ + h) * S_) + s) * DQK_;
    store_hl(khi, klo, base + d,      x1 * c - x2 * sn);
    store_hl(khi, klo, base + d + 32, x1 * sn + x2 * c);
}

__global__ __launch_bounds__(256) void vtrans_kernel(
    const float* __restrict__ kvp,
    __nv_bfloat16* __restrict__ vhi, __nv_bfloat16* __restrict__ vlo)
{
    int idx = blockIdx.x * blockDim.x + threadIdx.x;
    int d4 = idx & 15;
    int h  = (idx >> 4) & 15;
    int s  = (idx >> 8) & 4095;
    int b  = idx >> 20;
    const float4* src = (const float4*)(kvp + ((size_t)(b * S_ + s) * (2 * H_ * DQK_))
                                        + H_ * DQK_ + h * DQK_);
    float4 v = src[d4];
    uint2 hi, lo;
    split4(v, hi, lo);
    size_t base = (((size_t)(b * H_ + h) * S_) + s) * DQK_;
    ((uint2*)(vhi + base))[d4] = hi;
    ((uint2*)(vlo + base))[d4] = lo;
}

// ---------------- flash attention via mma.sync (split-bf16 3-term) ----------------
#define FSTG 36864
#define FSMEM (2 * FSTG)

__global__ __launch_bounds__(256) void flash_mma(
    const __nv_bfloat16* __restrict__ qh, const __nv_bfloat16* __restrict__ ql,
    const __nv_bfloat16* __restrict__ kh, const __nv_bfloat16* __restrict__ kl,
    const __nv_bfloat16* __restrict__ vh, const __nv_bfloat16* __restrict__ vl,
    __nv_bfloat16* __restrict__ oh, __nv_bfloat16* __restrict__ ol)
{
    extern __shared__ char sm[];
    const uint32_t sb = smem_to_u32(sm);
    const int tid = threadIdx.x, wid = tid >> 5, lane = tid & 31;
    const int bh = blockIdx.y;
    const int q0 = blockIdx.x * 128;
    const int warpM = wid * 16;
    const size_t qoff = ((size_t)bh * LQ_ + q0) * DQK_;
    const size_t koff = (size_t)bh * S_ * DQK_;

    {
        #pragma unroll
        for (int it = 0; it < 4; it++) {
            int e = it * 256 + tid;
            int row = e >> 3, seg = (e & 7) * 8;
            const size_t g = qoff + (size_t)row * DQK_ + seg;
            CP_ASYNC16(sb + FSTG + row * 144 + seg * 2, qh + g);
            CP_ASYNC16(sb + FSTG + 18432 + row * 144 + seg * 2, ql + g);
        }
        CP_COMMIT();
    }

    auto issueKV = [&](int tile, int stage) {
        int sk = tile * 64;
        uint32_t dst = sb + stage * FSTG;
        #pragma unroll
        for (int it = 0; it < 2; it++) {
            int e = it * 256 + tid;
            int row = e >> 3, seg = (e & 7) * 8;
            size_t g = koff + (size_t)(sk + row) * DQK_ + seg;
            uint32_t so = row * 144 + seg * 2;
            CP_ASYNC16(dst + so,         kh + g);
            CP_ASYNC16(dst + 9216 + so,  kl + g);
            CP_ASYNC16(dst + 18432 + so, vh + g);
            CP_ASYNC16(dst + 27648 + so, vl + g);
        }
    };

    issueKV(0, 0); CP_COMMIT();
    CP_WAIT1(); __syncthreads();

    uint32_t Qh[4][4], Ql[4][4];
    #pragma unroll
    for (int kt = 0; kt < 4; kt++) {
        uint32_t ad = sb + FSTG + (warpM + (lane & 15)) * 144 + ((lane >> 4) << 4) + kt * 32;
        ldmA(Qh[kt], ad);
        ldmA(Ql[kt], ad + 18432);
    }
    __syncthreads();
    issueKV(1, 1); CP_COMMIT();

    float acc[8][4];
    #pragma unroll
    for (int n = 0; n < 8; n++)
        #pragma unroll
        for (int c = 0; c < 4; c++) acc[n][c] = 0.0f;
    float m0 = -1e30f, m1 = -1e30f, l0 = 0.0f, l1 = 0.0f;

    for (int i = 0; i < S_ / 64; i++) {
        CP_WAIT1(); __syncthreads();
        const uint32_t kb = sb + (i & 1) * FSTG;

        float sc[8][4];
        #pragma unroll
        for (int n = 0; n < 8; n++)
            #pragma unroll
            for (int c = 0; c < 4; c++) sc[n][c] = 0.0f;

        #pragma unroll
        for (int kt = 0; kt < 4; kt++) {
            uint32_t Bh[4][4], Bl[4][4];
            #pragma unroll
            for (int p = 0; p < 4; p++) {
                uint32_t ad = kb + (p * 16 + (lane & 15)) * 144 + ((lane >> 4) << 4) + kt * 32;
                ldmA(Bh[p], ad);
                ldmA(Bl[p], ad + 9216);
            }
            #pragma unroll
            for (int ni = 0; ni < 8; ni++) {
                int g = ni >> 1, s = ni & 1;
                mma2(sc[ni], Qh[kt], Bh[g][s], Bh[g][s + 2]);
                mma2(sc[ni], Qh[kt], Bl[g][s], Bl[g][s + 2]);
                mma2(sc[ni], Ql[kt], Bh[g][s], Bh[g][s + 2]);
            }
        }

        float r0 = -1e30f, r1 = -1e30f;
        #pragma unroll
        for (int ni = 0; ni < 8; ni++) {
            r0 = fmaxf(r0, fmaxf(sc[ni][0], sc[ni][1]));
            r1 = fmaxf(r1, fmaxf(sc[ni][2], sc[ni][3]));
        }
        r0 = fmaxf(r0, __shfl_xor_sync(0xffffffffu, r0, 1));
        r0 = fmaxf(r0, __shfl_xor_sync(0xffffffffu, r0, 2));
        r1 = fmaxf(r1, __shfl_xor_sync(0xffffffffu, r1, 1));
        r1 = fmaxf(r1, __shfl_xor_sync(0xffffffffu, r1, 2));
        float mn0 = fmaxf(m0, r0), mn1 = fmaxf(m1, r1);
        float c0 = __expf(m0 - mn0), c1 = __expf(m1 - mn1);
        l0 *= c0; l1 *= c1;
        #pragma unroll
        for (int ni = 0; ni < 8; ni++) {
            acc[ni][0] *= c0; acc[ni][1] *= c0;
            acc[ni][2] *= c1; acc[ni][3] *= c1;
        }
        m0 = mn0; m1 = mn1;

        #pragma unroll
        for (int kt = 0; kt < 4; kt++) {
            uint32_t ph[4], pl[4];
            #pragma unroll
            for (int j = 0; j < 2; j++) {
                int ni = 2 * kt + j;
                float p0 = __expf(sc[ni][0] - m0);
                float p1 = __expf(sc[ni][1] - m0);
                float p2 = __expf(sc[ni][2] - m1);
                float p3 = __expf(sc[ni][3] - m1);
                l0 += p0 + p1; l1 += p2 + p3;
                float h0 = __bfloat162float(__float2bfloat16(p0));
                float h1 = __bfloat162float(__float2bfloat16(p1));
                float h2 = __bfloat162float(__float2bfloat16(p2));
                float h3 = __bfloat162float(__float2bfloat16(p3));
                ph[2 * j]     = packbf(h0, h1);
                ph[2 * j + 1] = packbf(h2, h3);
                pl[2 * j]     = packbf(p0 - h0, p1 - h1);
                pl[2 * j + 1] = packbf(p2 - h2, p3 - h3);
            }
            uint32_t Vh[4][4], Vl[4][4];
            int grp = lane >> 3, rr = lane & 7;
            #pragma unroll
            for (int p = 0; p < 4; p++) {
                uint32_t ad = kb + 18432
                    + (kt * 16 + (grp & 1) * 8 + rr) * 144
                    + (p * 16 + (grp >> 1) * 8) * 2;
                ldmBT(Vh[p], ad);
                ldmBT(Vl[p], ad + 9216);
            }
            #pragma unroll
            for (int nv = 0; nv < 8; nv++) {
                int g = nv >> 1, s = (nv & 1) * 2;
                mma2(acc[nv], ph, Vh[g][s], Vh[g][s + 1]);
                mma2(acc[nv], ph, Vl[g][s], Vl[g][s + 1]);
                mma2(acc[nv], pl, Vh[g][s], Vh[g][s + 1]);
            }
        }

        __syncthreads();
        if (i + 2 < S_ / 64) issueKV(i + 2, i & 1);
        CP_COMMIT();
    }

    l0 += __shfl_xor_sync(0xffffffffu, l0, 1);
    l0 += __shfl_xor_sync(0xffffffffu, l0, 2);
    l1 += __shfl_xor_sync(0xffffffffu, l1, 1);
    l1 += __shfl_xor_sync(0xffffffffu, l1, 2);
    float i0 = 1.0f / l0, i1 = 1.0f / l1;

    int b = bh >> 4, h = bh & 15;
    int row0 = q0 + warpM + (lane >> 2);
    size_t ob0 = (size_t)(b * LQ_ + row0) * (H_ * DQK_) + h * DQK_;
    size_t ob1 = ob0 + (size_t)8 * (H_ * DQK_);
    #pragma unroll
    for (int nv = 0; nv < 8; nv++) {
        int col = nv * 8 + (lane & 3) * 2;
        float a0 = acc[nv][0] * i0, a1 = acc[nv][1] * i0;
        float a2 = acc[nv][2] * i1, a3 = acc[nv][3] * i1;
        float h0 = __bfloat162float(__float2bfloat16(a0));
        float h1 = __bfloat162float(__float2bfloat16(a1));
        float h2 = __bfloat162float(__float2bfloat16(a2));
        float h3 = __bfloat162float(__float2bfloat16(a3));
        *(uint32_t*)(oh + ob0 + col) = packbf(a0, a1);
        *(uint32_t*)(ol + ob0 + col) = packbf(a0 - h0, a1 - h1);
        *(uint32_t*)(oh + ob1 + col) = packbf(a2, a3);
        *(uint32_t*)(ol + ob1 + col) = packbf(a2 - h2, a3 - h3);
    }
}

// ---------------- launch ----------------
extern "C" void kernel_launch(void* const* d_in, const int* in_sizes, int n_in,
                              void* d_out, int out_size)
{
    (void)in_sizes; (void)n_in; (void)out_size;
    const float* x      = (const float*)d_in[0];
    const float* norm_w = (const float*)d_in[1];
    const float* wq_w   = (const float*)d_in[2];
    const float* wq_b   = (const float*)d_in[3];
    const float* wkv_w  = (const float*)d_in[4];
    const float* wkv_b  = (const float*)d_in[5];
    const float* wout_w = (const float*)d_in[6];
    const float* wout_b = (const float*)d_in[7];
    const float* wbyp_w = (const float*)d_in[8];
    float* out = (float*)d_out;

    float *p_qproj, *p_kvproj;
    cudaGetSymbolAddress((void**)&p_qproj,  g_qproj);
    cudaGetSymbolAddress((void**)&p_kvproj, g_kvproj);

    __nv_bfloat16 *nh, *nl, *xh, *xl, *wqh, *wql, *wkvh, *wkvl, *wouth, *woutl,
                  *wbyph, *wbypl, *ath, *atl, *pqh, *pql, *pkh, *pkl, *pvh, *pvl;
    cudaGetSymbolAddress((void**)&nh,    g_normh);
    cudaGetSymbolAddress((void**)&nl,    g_norml);
    cudaGetSymbolAddress((void**)&xh,    g_xh);
    cudaGetSymbolAddress((void**)&xl,    g_xl);
    cudaGetSymbolAddress((void**)&wqh,   g_wqh);
    cudaGetSymbolAddress((void**)&wql,   g_wql);
    cudaGetSymbolAddress((void**)&wkvh,  g_wkvh);
    cudaGetSymbolAddress((void**)&wkvl,  g_wkvl);
    cudaGetSymbolAddress((void**)&wouth, g_wouth);
    cudaGetSymbolAddress((void**)&woutl, g_woutl);
    cudaGetSymbolAddress((void**)&wbyph, g_wbyph);
    cudaGetSymbolAddress((void**)&wbypl, g_wbypl);
    cudaGetSymbolAddress((void**)&ath,   g_attnh);
    cudaGetSymbolAddress((void**)&atl,   g_attnl);
    cudaGetSymbolAddress((void**)&pqh,   g_qh);
    cudaGetSymbolAddress((void**)&pql,   g_ql);
    cudaGetSymbolAddress((void**)&pkh,   g_kh);
    cudaGetSymbolAddress((void**)&pkl,   g_kl);
    cudaGetSymbolAddress((void**)&pvh,   g_vh);
    cudaGetSymbolAddress((void**)&pvl,   g_vl);

    cudaFuncSetAttribute(flash_mma, cudaFuncAttributeMaxDynamicSharedMemorySize, FSMEM);
    cudaFuncSetAttribute(gemm_mma, cudaFuncAttributeMaxDynamicSharedMemorySize, GM_SMEM);

    // 1. RMSNorm with fused hi/lo split
    rmsnorm_kernel<<<B_ * S_, 128>>>(x, norm_w, nh, nl);

    // 2. operand splits
    split_kernel<<<(B_ * S_ * D_ / 4) / 256, 256>>>(x, xh, xl, B_ * S_ * D_ / 4);
    split_kernel<<<(BPL_ * D_ * H_ * DQK_ / 4) / 256, 256>>>(wq_w, wqh, wql, BPL_ * D_ * H_ * DQK_ / 4);
    split_kernel<<<(D_ * 2 * H_ * DQK_ / 4) / 256, 256>>>(wkv_w, wkvh, wkvl, D_ * 2 * H_ * DQK_ / 4);
    split_kernel<<<(H_ * DQK_ * DLAT_ / 4) / 256, 256>>>(wout_w, wouth, woutl, H_ * DQK_ * DLAT_ / 4);
    split_kernel<<<(BPL_ * D_ * DLAT_ / 4) / 256, 256>>>(wbyp_w, wbyph, wbypl, BPL_ * D_ * DLAT_ / 4);

    // 3. Q projection
    gemm_mma<<<dim3((H_ * DQK_) / 128, (B_ * LQ_) / 128), 256, GM_SMEM>>>(
        B_ * LQ_, H_ * DQK_, BPL_ * D_, nh, nl, wqh, wql, wq_b, p_qproj, 0);

    // 4. KV projection
    gemm_mma<<<dim3((2 * H_ * DQK_) / 128, (B_ * S_) / 128), 256, GM_SMEM>>>(
        B_ * S_, 2 * H_ * DQK_, D_, nh, nl, wkvh, wkvl, wkv_b, p_kvproj, 0);

    // 5. RoPE + transposes -> bf16 hi/lo
    rope_q_kernel<<<(B_ * LQ_ * H_ * 32) / 256, 256>>>(p_qproj, pqh, pql);
    rope_k_kernel<<<(B_ * S_ * H_ * 32) / 256, 256>>>(p_kvproj, pkh, pkl);
    vtrans_kernel<<<(B_ * S_ * H_ * 16) / 256, 256>>>(p_kvproj, pvh, pvl);

    // 6. Flash attention (tensor cores) -> attn hi/lo
    flash_mma<<<dim3(LQ_ / 128, B_ * H_), 256, FSMEM>>>(
        pqh, pql, pkh, pkl, pvh, pvl, ath, atl);

    // 7. Bypass GEMM
    gemm_mma<<<dim3(DLAT_ / 128, (B_ * LQ_) / 128), 256, GM_SMEM>>>(
        B_ * LQ_, DLAT_, BPL_ * D_, xh, xl, wbyph, wbypl, nullptr, out, 0);

    // 8. Out projection (accumulate)
    gemm_mma<<<dim3(DLAT_ / 128, (B_ * LQ_) / 128), 256, GM_SMEM>>>(
        B_ * LQ_, DLAT_, H_ * DQK_, ath, atl, wouth, woutl, wout_b, out, 1);
}

// round 7
// speedup vs baseline: 1.4012x; 1.4012x over previous
#include <cuda_runtime.h>
#include <cuda_bf16.h>
#include <cuda_fp16.h>
#include <math.h>
#include <stdint.h>

// ---------------- problem constants ----------------
#define B_   2
#define S_   4096
#define D_   512
#define BPL_ 4
#define H_   16
#define DQK_ 64
#define DLAT_ 1024
#define LQ_  (S_ / BPL_)          // 1024
#define EPS_ 1.1920929e-07f

// ---------------- scratch (device globals; no allocation allowed) ----------------
__device__ float g_qproj [B_ * LQ_ * H_ * DQK_];
__device__ float g_kvproj[B_ * S_ * 2 * H_ * DQK_];

// fp16 operands (quantize-A / exact-B scheme)
__device__ __half g_nh  [B_ * S_ * D_];                                   // normalized, single fp16
__device__ __half g_wqh [BPL_ * D_ * H_ * DQK_], g_wql [BPL_ * D_ * H_ * DQK_];
__device__ __half g_wkvh[D_ * 2 * H_ * DQK_],    g_wkvl[D_ * 2 * H_ * DQK_];
__device__ __half g_qh  [B_ * H_ * LQ_ * DQK_];                           // single fp16 (pre-scaled)
__device__ __half g_kh  [B_ * H_ * S_ * DQK_],   g_kl  [B_ * H_ * S_ * DQK_];
__device__ __half g_vh  [B_ * H_ * S_ * DQK_],   g_vl  [B_ * H_ * S_ * DQK_];

// bf16 hi/lo operands for the 3-term final GEMMs (bypass + out-proj)
__device__ __nv_bfloat16 g_xh   [B_ * S_ * D_], g_xl   [B_ * S_ * D_];
__device__ __nv_bfloat16 g_wouth[H_ * DQK_ * DLAT_],  g_woutl[H_ * DQK_ * DLAT_];
__device__ __nv_bfloat16 g_wbyph[BPL_ * D_ * DLAT_],  g_wbypl[BPL_ * D_ * DLAT_];
__device__ __nv_bfloat16 g_attnh[B_ * LQ_ * H_ * DQK_], g_attnl[B_ * LQ_ * H_ * DQK_];

// ---------------- helpers ----------------
__device__ __forceinline__ uint32_t smem_to_u32(const void* p) {
    uint32_t a;
    asm("{ .reg .u64 t; cvta.to.shared.u64 t, %1; cvt.u32.u64 %0, t; }" : "=r"(a) : "l"(p));
    return a;
}

#define CP_ASYNC16(dst, src) \
    asm volatile("cp.async.cg.shared.global [%0], [%1], 16;" :: "r"(dst), "l"(src))
#define CP_COMMIT()  asm volatile("cp.async.commit_group;" ::: "memory")
#define CP_WAIT0()   asm volatile("cp.async.wait_group 0;" ::: "memory")
#define CP_WAIT1()   asm volatile("cp.async.wait_group 1;" ::: "memory")

__device__ __forceinline__ void ldmA(uint32_t* r, uint32_t addr) {
    asm volatile("ldmatrix.sync.aligned.m8n8.x4.shared.b16 {%0,%1,%2,%3}, [%4];"
                 : "=r"(r[0]), "=r"(r[1]), "=r"(r[2]), "=r"(r[3]) : "r"(addr));
}
__device__ __forceinline__ void ldmBT(uint32_t* r, uint32_t addr) {
    asm volatile("ldmatrix.sync.aligned.m8n8.x4.trans.shared.b16 {%0,%1,%2,%3}, [%4];"
                 : "=r"(r[0]), "=r"(r[1]), "=r"(r[2]), "=r"(r[3]) : "r"(addr));
}
// bf16 mma
__device__ __forceinline__ void mma16816(float* d, const uint32_t* a, const uint32_t* b) {
    asm volatile(
        "mma.sync.aligned.m16n8k16.row.col.f32.bf16.bf16.f32 "
        "{%0,%1,%2,%3}, {%4,%5,%6,%7}, {%8,%9}, {%0,%1,%2,%3};"
        : "+f"(d[0]), "+f"(d[1]), "+f"(d[2]), "+f"(d[3])
        : "r"(a[0]), "r"(a[1]), "r"(a[2]), "r"(a[3]), "r"(b[0]), "r"(b[1]));
}
// fp16 mma
__device__ __forceinline__ void mma16816h(float* d, const uint32_t* a, uint32_t b0, uint32_t b1) {
    asm volatile(
        "mma.sync.aligned.m16n8k16.row.col.f32.f16.f16.f32 "
        "{%0,%1,%2,%3}, {%4,%5,%6,%7}, {%8,%9}, {%0,%1,%2,%3};"
        : "+f"(d[0]), "+f"(d[1]), "+f"(d[2]), "+f"(d[3])
        : "r"(a[0]), "r"(a[1]), "r"(a[2]), "r"(a[3]), "r"(b0), "r"(b1));
}

__device__ __forceinline__ uint32_t packbf(float x, float y) {
    union { __nv_bfloat162 b; uint32_t u; } c;
    c.b = __halves2bfloat162(__float2bfloat16(x), __float2bfloat16(y));
    return c.u;
}
__device__ __forceinline__ uint32_t packhf(float x, float y) {
    union { __half2 h; uint32_t u; } c;
    c.h = __halves2half2(__float2half(x), __float2half(y));
    return c.u;
}

__device__ __forceinline__ void split4(float4 v, uint2& hi, uint2& lo) {
    __nv_bfloat16 hx = __float2bfloat16(v.x);
    __nv_bfloat16 hy = __float2bfloat16(v.y);
    __nv_bfloat16 hz = __float2bfloat16(v.z);
    __nv_bfloat16 hw = __float2bfloat16(v.w);
    union { __nv_bfloat162 b[2]; uint2 u; } c;
    c.b[0] = __halves2bfloat162(hx, hy);
    c.b[1] = __halves2bfloat162(hz, hw);
    hi = c.u;
    c.b[0] = __halves2bfloat162(__float2bfloat16(v.x - __bfloat162float(hx)),
                                __float2bfloat16(v.y - __bfloat162float(hy)));
    c.b[1] = __halves2bfloat162(__float2bfloat16(v.z - __bfloat162float(hz)),
                                __float2bfloat16(v.w - __bfloat162float(hw)));
    lo = c.u;
}

__device__ __forceinline__ void split4h(float4 v, uint2& hi, uint2& lo) {
    __half hx = __float2half(v.x);
    __half hy = __float2half(v.y);
    __half hz = __float2half(v.z);
    __half hw = __float2half(v.w);
    union { __half2 h[2]; uint2 u; } c;
    c.h[0] = __halves2half2(hx, hy);
    c.h[1] = __halves2half2(hz, hw);
    hi = c.u;
    c.h[0] = __halves2half2(__float2half(v.x - __half2float(hx)),
                            __float2half(v.y - __half2float(hy)));
    c.h[1] = __halves2half2(__float2half(v.z - __half2float(hz)),
                            __float2half(v.w - __half2float(hw)));
    lo = c.u;
}

__device__ __forceinline__ uint2 conv4h(float4 v) {
    union { __half2 h[2]; uint2 u; } c;
    c.h[0] = __halves2half2(__float2half(v.x), __float2half(v.y));
    c.h[1] = __halves2half2(__float2half(v.z), __float2half(v.w));
    return c.u;
}

// ---------------- elementwise kernels ----------------
__global__ __launch_bounds__(256) void split_kernel(           // bf16 hi/lo
    const float* __restrict__ src, __nv_bfloat16* __restrict__ hi,
    __nv_bfloat16* __restrict__ lo, int n4)
{
    int i = blockIdx.x * blockDim.x + threadIdx.x;
    if (i >= n4) return;
    float4 v = ((const float4*)src)[i];
    uint2 h, l;
    split4(v, h, l);
    ((uint2*)hi)[i] = h;
    ((uint2*)lo)[i] = l;
}

__global__ __launch_bounds__(256) void splith_kernel(          // fp16 hi/lo
    const float* __restrict__ src, __half* __restrict__ hi,
    __half* __restrict__ lo, int n4)
{
    int i = blockIdx.x * blockDim.x + threadIdx.x;
    if (i >= n4) return;
    float4 v = ((const float4*)src)[i];
    uint2 h, l;
    split4h(v, h, l);
    ((uint2*)hi)[i] = h;
    ((uint2*)lo)[i] = l;
}

// RMSNorm -> single fp16
__global__ __launch_bounds__(128) void rmsnorm_kernel(
    const float* __restrict__ x, const float* __restrict__ w,
    __half* __restrict__ outh)
{
    int row = blockIdx.x;
    const float4* xr = (const float4*)(x + (size_t)row * D_);
    const float4* wr = (const float4*)w;
    int tid = threadIdx.x;

    float4 v = xr[tid];
    float s = v.x * v.x + v.y * v.y + v.z * v.z + v.w * v.w;
    #pragma unroll
    for (int o = 16; o > 0; o >>= 1) s += __shfl_xor_sync(0xffffffffu, s, o);
    __shared__ float red[4];
    int warp = tid >> 5, lane = tid & 31;
    if (lane == 0) red[warp] = s;
    __syncthreads();
    float total = red[0] + red[1] + red[2] + red[3];
    float inv = rsqrtf(total / (float)D_ + EPS_);
    float4 wv = wr[tid];
    float4 o4 = make_float4(v.x * inv * wv.x, v.y * inv * wv.y,
                            v.z * inv * wv.z, v.w * inv * wv.w);
    ((uint2*)outh)[row * (D_ / 4) + tid] = conv4h(o4);
}

// ---------------- fp16 2-term GEMM: C = Ah@(Bh+Bl) + bias ----------------
// A single fp16 (quantized activations), B fp16 hi/lo. CTA 128x128, K-chunk 32.
#define BKF  32
#define ASTR 40
#define BSTR 136
#define G2_A_B (128 * ASTR * 2)            // 10240
#define G2_B_B (BKF * BSTR * 2)            // 8704
#define G2_STG (G2_A_B + 2 * G2_B_B)       // 27648
#define G2_SMEM (2 * G2_STG)               // 55296

__global__ __launch_bounds__(256) void gemm_f16(
    int M, int N, int K,
    const __half* __restrict__ A,
    const __half* __restrict__ Bh, const __half* __restrict__ Bl,
    const float* __restrict__ bias, float* __restrict__ C)
{
    extern __shared__ char gsm[];
    const uint32_t sBase = smem_to_u32(gsm);

    const int tid = threadIdx.x;
    const int wid = tid >> 5, lane = tid & 31;
    const int mBase = blockIdx.y * 128;
    const int nBase = blockIdx.x * 128;
    const int warpM = (wid >> 1) * 32;
    const int warpN = (wid & 1) * 64;

    const int cpk = K / BKF;

    const int arow0 = tid >> 2, aseg = (tid & 3) * 8;
    const int brow0 = tid >> 4, bseg = (tid & 15) * 8;

    float acc[2][8][4];
    #pragma unroll
    for (int mi = 0; mi < 2; mi++)
        #pragma unroll
        for (int ni = 0; ni < 8; ni++)
            #pragma unroll
            for (int c = 0; c < 4; c++) acc[mi][ni][c] = 0.0f;

    auto issue = [&](int chunk) {
        int buf = chunk & 1;
        int k0 = chunk * BKF;
        uint32_t da  = sBase + buf * G2_STG;
        uint32_t dbh = da + G2_A_B;
        uint32_t dbl = dbh + G2_B_B;
        const __half* aptr  = A  + (size_t)mBase * K + k0 + aseg;
        const __half* bhptr = Bh + (size_t)k0 * N + nBase + bseg;
        const __half* blptr = Bl + (size_t)k0 * N + nBase + bseg;
        #pragma unroll
        for (int it = 0; it < 2; it++) {
            int row = arow0 + it * 64;
            CP_ASYNC16(da + row * (ASTR * 2) + aseg * 2, aptr + (size_t)row * K);
        }
        #pragma unroll
        for (int it = 0; it < 2; it++) {
            int row = brow0 + it * 16;
            CP_ASYNC16(dbh + row * (BSTR * 2) + bseg * 2, bhptr + (size_t)row * N);
            CP_ASYNC16(dbl + row * (BSTR * 2) + bseg * 2, blptr + (size_t)row * N);
        }
        CP_COMMIT();
    };

    issue(0);

    for (int i = 0; i < cpk; i++) {
        if (i + 1 < cpk) { issue(i + 1); CP_WAIT1(); }
        else             { CP_WAIT0(); }
        __syncthreads();

        const uint32_t aBase  = sBase + (i & 1) * G2_STG;
        const uint32_t bhBase = aBase + G2_A_B;
        const uint32_t blBase = bhBase + G2_B_B;

        #pragma unroll
        for (int kk = 0; kk < 2; kk++) {
            uint32_t afrag[2][4];
            #pragma unroll
            for (int mi = 0; mi < 2; mi++) {
                uint32_t addr = aBase
                    + (warpM + mi * 16 + (lane & 15)) * (ASTR * 2)
                    + ((lane >> 4) << 4) + kk * 32;
                ldmA(afrag[mi], addr);
            }
            uint32_t bh[4][4], bl[4][4];
            int grp = lane >> 3, r = lane & 7;
            #pragma unroll
            for (int p = 0; p < 4; p++) {
                uint32_t off = (kk * 16 + (grp & 1) * 8 + r) * (BSTR * 2)
                    + (warpN + p * 16 + (grp >> 1) * 8) * 2;
                ldmBT(bh[p], bhBase + off);
                ldmBT(bl[p], blBase + off);
            }
            #pragma unroll
            for (int mi = 0; mi < 2; mi++)
                #pragma unroll
                for (int ni = 0; ni < 8; ni++) {
                    int g = ni >> 1, s = (ni & 1) * 2;
                    mma16816h(acc[mi][ni], afrag[mi], bh[g][s], bh[g][s + 1]);
                    mma16816h(acc[mi][ni], afrag[mi], bl[g][s], bl[g][s + 1]);
                }
        }
        __syncthreads();
    }

    #pragma unroll
    for (int mi = 0; mi < 2; mi++) {
        #pragma unroll
        for (int ni = 0; ni < 8; ni++) {
            int r0 = mBase + warpM + mi * 16 + (lane >> 2);
            int c  = nBase + warpN + ni * 8 + (lane & 3) * 2;
            float2 v0 = make_float2(acc[mi][ni][0], acc[mi][ni][1]);
            float2 v1 = make_float2(acc[mi][ni][2], acc[mi][ni][3]);
            float2 bb = *(const float2*)(bias + c);
            v0.x += bb.x; v0.y += bb.y;
            v1.x += bb.x; v1.y += bb.y;
            *(float2*)(C + (size_t)r0 * N + c) = v0;
            *(float2*)(C + (size_t)(r0 + 8) * N + c) = v1;
        }
    }
}

// ---------------- bf16 3-term GEMM (R5 version, for bypass + out-proj) ----------------
__global__ __launch_bounds__(256) void gemm_mma(
    int M, int N, int K,
    const __nv_bfloat16* __restrict__ Ahi, const __nv_bfloat16* __restrict__ Alo,
    const __nv_bfloat16* __restrict__ Bhi, const __nv_bfloat16* __restrict__ Blo,
    const float* __restrict__ bias, float* __restrict__ C, int accum)
{
    __shared__ __nv_bfloat16 As[2][128 * ASTR];
    __shared__ __nv_bfloat16 Bs[2][BKF * BSTR];

    const int tid = threadIdx.x;
    const int wid = tid >> 5, lane = tid & 31;
    const int mBase = blockIdx.y * 128;
    const int nBase = blockIdx.x * 128;
    const int warpM = (wid >> 1) * 32;
    const int warpN = (wid & 1) * 64;

    const uint32_t sA0 = smem_to_u32(As[0]);
    const uint32_t sB0 = smem_to_u32(Bs[0]);
    const uint32_t aStageB = 128 * ASTR * 2;
    const uint32_t bStageB = BKF * BSTR * 2;

    const int cpk = K / BKF;
    const int total = 3 * cpk;

    const int arow0 = tid >> 2, aseg = (tid & 3) * 8;
    const int brow0 = tid >> 4, bseg = (tid & 15) * 8;

    float acc[2][8][4];
    #pragma unroll
    for (int mi = 0; mi < 2; mi++)
        #pragma unroll
        for (int ni = 0; ni < 8; ni++)
            #pragma unroll
            for (int c = 0; c < 4; c++) acc[mi][ni][c] = 0.0f;

    auto issue = [&](int chunk, int buf) {
        int term = chunk / cpk;
        int k0 = (chunk - term * cpk) * BKF;
        const __nv_bfloat16* Asrc = (term < 2) ? Ahi : Alo;
        const __nv_bfloat16* Bsrc = (term == 1) ? Blo : Bhi;
        uint32_t da = sA0 + buf * aStageB;
        uint32_t db = sB0 + buf * bStageB;
        const __nv_bfloat16* aptr = Asrc + (size_t)mBase * K + k0 + aseg;
        const __nv_bfloat16* bptr = Bsrc + (size_t)k0 * N + nBase + bseg;
        #pragma unroll
        for (int it = 0; it < 2; it++) {
            int row = arow0 + it * 64;
            CP_ASYNC16(da + row * (ASTR * 2) + aseg * 2, aptr + (size_t)row * K);
        }
        #pragma unroll
        for (int it = 0; it < 2; it++) {
            int row = brow0 + it * 16;
            CP_ASYNC16(db + row * (BSTR * 2) + bseg * 2, bptr + (size_t)row * N);
        }
        CP_COMMIT();
    };

    issue(0, 0);

    for (int i = 0; i < total; i++) {
        if (i + 1 < total) { issue(i + 1, (i + 1) & 1); CP_WAIT1(); }
        else               { CP_WAIT0(); }
        __syncthreads();

        const int buf = i & 1;
        const uint32_t aBase = sA0 + buf * aStageB;
        const uint32_t bBase = sB0 + buf * bStageB;

        #pragma unroll
        for (int kk = 0; kk < 2; kk++) {
            uint32_t afrag[2][4];
            #pragma unroll
            for (int mi = 0; mi < 2; mi++) {
                uint32_t addr = aBase
                    + (warpM + mi * 16 + (lane & 15)) * (ASTR * 2)
                    + ((lane >> 4) << 4) + kk * 32;
                ldmA(afrag[mi], addr);
            }
            uint32_t bfrag[4][4];
            #pragma unroll
            for (int p = 0; p < 4; p++) {
                int grp = lane >> 3, r = lane & 7;
                uint32_t addr = bBase
                    + (kk * 16 + (grp & 1) * 8 + r) * (BSTR * 2)
                    + (warpN + p * 16 + (grp >> 1) * 8) * 2;
                ldmBT(bfrag[p], addr);
            }
            #pragma unroll
            for (int mi = 0; mi < 2; mi++)
                #pragma unroll
                for (int ni = 0; ni < 8; ni++)
                    mma16816(acc[mi][ni], afrag[mi], &bfrag[ni >> 1][(ni & 1) * 2]);
        }
        __syncthreads();
    }

    #pragma unroll
    for (int mi = 0; mi < 2; mi++) {
        #pragma unroll
        for (int ni = 0; ni < 8; ni++) {
            int r0 = mBase + warpM + mi * 16 + (lane >> 2);
            int c  = nBase + warpN + ni * 8 + (lane & 3) * 2;
            float2 v0 = make_float2(acc[mi][ni][0], acc[mi][ni][1]);
            float2 v1 = make_float2(acc[mi][ni][2], acc[mi][ni][3]);
            if (bias) {
                float2 bb = *(const float2*)(bias + c);
                v0.x += bb.x; v0.y += bb.y;
                v1.x += bb.x; v1.y += bb.y;
            }
            float* p0 = C + (size_t)r0 * N + c;
            float* p1 = C + (size_t)(r0 + 8) * N + c;
            if (accum) {
                float2 c0 = *(float2*)p0, c1 = *(float2*)p1;
                v0.x += c0.x; v0.y += c0.y;
                v1.x += c1.x; v1.y += c1.y;
            }
            *(float2*)p0 = v0;
            *(float2*)p1 = v1;
        }
    }
}

// ---------------- RoPE: emit fp16 ----------------
__device__ __forceinline__ float inv_freq_f(int d)
{
    return (float)pow(10000.0, -(double)d / 32.0);
}

__global__ __launch_bounds__(256) void rope_q_kernel(
    const float* __restrict__ qp, __half* __restrict__ qh)
{
    int idx = blockIdx.x * blockDim.x + threadIdx.x;
    int d  = idx & 31;
    int h  = (idx >> 5) & 15;
    int qi = (idx >> 9) & 1023;
    int b  = idx >> 19;
    const float* src = qp + ((size_t)(b * LQ_ + qi) * (H_ * DQK_)) + h * DQK_;
    float x1 = src[d], x2 = src[d + 32];
    float pos = (float)(qi * BPL_);
    float ang = pos * inv_freq_f(d);
    float c = cosf(ang), s = sinf(ang);
    size_t base = (((size_t)(b * H_ + h) * LQ_) + qi) * DQK_;
    qh[base + d]      = __float2half((x1 * c - x2 * s) * 0.125f);
    qh[base + d + 32] = __float2half((x1 * s + x2 * c) * 0.125f);
}

__global__ __launch_bounds__(256) void rope_k_kernel(
    const float* __restrict__ kvp,
    __half* __restrict__ khi, __half* __restrict__ klo)
{
    int idx = blockIdx.x * blockDim.x + threadIdx.x;
    int d  = idx & 31;
    int h  = (idx >> 5) & 15;
    int s  = (idx >> 9) & 4095;
    int b  = idx >> 21;
    const float* src = kvp + ((size_t)(b * S_ + s) * (2 * H_ * DQK_)) + h * DQK_;
    float x1 = src[d], x2 = src[d + 32];
    float pos = (float)s;
    float ang = pos * inv_freq_f(d);
    float c = cosf(ang), sn = sinf(ang);
    size_t base = (((size_t)(b * H_ + h) * S_) + s) * DQK_;
    float v0 = x1 * c - x2 * sn;
    float v1 = x1 * sn + x2 * c;
    __half h0 = __float2half(v0), h1 = __float2half(v1);
    khi[base + d]      = h0;
    klo[base + d]      = __float2half(v0 - __half2float(h0));
    khi[base + d + 32] = h1;
    klo[base + d + 32] = __float2half(v1 - __half2float(h1));
}

__global__ __launch_bounds__(256) void vtrans_kernel(
    const float* __restrict__ kvp,
    __half* __restrict__ vhi, __half* __restrict__ vlo)
{
    int idx = blockIdx.x * blockDim.x + threadIdx.x;
    int d4 = idx & 15;
    int h  = (idx >> 4) & 15;
    int s  = (idx >> 8) & 4095;
    int b  = idx >> 20;
    const float4* src = (const float4*)(kvp + ((size_t)(b * S_ + s) * (2 * H_ * DQK_))
                                        + H_ * DQK_ + h * DQK_);
    float4 v = src[d4];
    uint2 hi, lo;
    split4h(v, hi, lo);
    size_t base = (((size_t)(b * H_ + h) * S_) + s) * DQK_;
    ((uint2*)(vhi + base))[d4] = hi;
    ((uint2*)(vlo + base))[d4] = lo;
}

// ---------------- flash attention via fp16 mma (2-term) ----------------
// smem per stage: khi,klo,vhi,vlo each 64 rows x 144B = 9216B -> 36864B; 2 stages.
#define FSTG 36864
#define FSMEM (2 * FSTG)

__global__ __launch_bounds__(256) void flash_mma(
    const __half* __restrict__ qh,
    const __half* __restrict__ kh, const __half* __restrict__ kl,
    const __half* __restrict__ vh, const __half* __restrict__ vl,
    __nv_bfloat16* __restrict__ oh, __nv_bfloat16* __restrict__ ol)
{
    extern __shared__ char sm[];
    const uint32_t sb = smem_to_u32(sm);
    const int tid = threadIdx.x, wid = tid >> 5, lane = tid & 31;
    const int bh = blockIdx.y;
    const int q0 = blockIdx.x * 128;
    const int warpM = wid * 16;
    const size_t qoff = ((size_t)bh * LQ_ + q0) * DQK_;
    const size_t koff = (size_t)bh * S_ * DQK_;

    // Q (hi only) -> stage1 region (consumed before tile1 overwrites it)
    {
        #pragma unroll
        for (int it = 0; it < 4; it++) {
            int e = it * 256 + tid;
            int row = e >> 3, seg = (e & 7) * 8;
            CP_ASYNC16(sb + FSTG + row * 144 + seg * 2, qh + qoff + (size_t)row * DQK_ + seg);
        }
        CP_COMMIT();
    }

    auto issueKV = [&](int tile, int stage) {
        int sk = tile * 64;
        uint32_t dst = sb + stage * FSTG;
        #pragma unroll
        for (int it = 0; it < 2; it++) {
            int e = it * 256 + tid;
            int row = e >> 3, seg = (e & 7) * 8;
            size_t g = koff + (size_t)(sk + row) * DQK_ + seg;
            uint32_t so = row * 144 + seg * 2;
            CP_ASYNC16(dst + so,         kh + g);
            CP_ASYNC16(dst + 9216 + so,  kl + g);
            CP_ASYNC16(dst + 18432 + so, vh + g);
            CP_ASYNC16(dst + 27648 + so, vl + g);
        }
    };

    issueKV(0, 0); CP_COMMIT();
    CP_WAIT1(); __syncthreads();

    uint32_t Qf[4][4];
    #pragma unroll
    for (int kt = 0; kt < 4; kt++) {
        uint32_t ad = sb + FSTG + (warpM + (lane & 15)) * 144 + ((lane >> 4) << 4) + kt * 32;
        ldmA(Qf[kt], ad);
    }
    __syncthreads();
    issueKV(1, 1); CP_COMMIT();

    float acc[8][4];
    #pragma unroll
    for (int n = 0; n < 8; n++)
        #pragma unroll
        for (int c = 0; c < 4; c++) acc[n][c] = 0.0f;
    float m0 = -1e30f, m1 = -1e30f, l0 = 0.0f, l1 = 0.0f;

    for (int i = 0; i < S_ / 64; i++) {
        CP_WAIT1(); __syncthreads();
        const uint32_t kb = sb + (i & 1) * FSTG;

        // scores = Q@(Kh + Kl)
        float sc[8][4];
        #pragma unroll
        for (int n = 0; n < 8; n++)
            #pragma unroll
            for (int c = 0; c < 4; c++) sc[n][c] = 0.0f;

        #pragma unroll
        for (int kt = 0; kt < 4; kt++) {
            uint32_t Bh[4][4], Bl[4][4];
            #pragma unroll
            for (int p = 0; p < 4; p++) {
                uint32_t ad = kb + (p * 16 + (lane & 15)) * 144 + ((lane >> 4) << 4) + kt * 32;
                ldmA(Bh[p], ad);
                ldmA(Bl[p], ad + 9216);
            }
            #pragma unroll
            for (int ni = 0; ni < 8; ni++) {
                int g = ni >> 1, s = ni & 1;
                mma16816h(sc[ni], Qf[kt], Bh[g][s], Bh[g][s + 2]);
                mma16816h(sc[ni], Qf[kt], Bl[g][s], Bl[g][s + 2]);
            }
        }

        // online softmax (rows: lane>>2 and +8)
        float r0 = -1e30f, r1 = -1e30f;
        #pragma unroll
        for (int ni = 0; ni < 8; ni++) {
            r0 = fmaxf(r0, fmaxf(sc[ni][0], sc[ni][1]));
            r1 = fmaxf(r1, fmaxf(sc[ni][2], sc[ni][3]));
        }
        r0 = fmaxf(r0, __shfl_xor_sync(0xffffffffu, r0, 1));
        r0 = fmaxf(r0, __shfl_xor_sync(0xffffffffu, r0, 2));
        r1 = fmaxf(r1, __shfl_xor_sync(0xffffffffu, r1, 1));
        r1 = fmaxf(r1, __shfl_xor_sync(0xffffffffu, r1, 2));
        float mn0 = fmaxf(m0, r0), mn1 = fmaxf(m1, r1);
        float c0 = __expf(m0 - mn0), c1 = __expf(m1 - mn1);
        l0 *= c0; l1 *= c1;
        #pragma unroll
        for (int ni = 0; ni < 8; ni++) {
            acc[ni][0] *= c0; acc[ni][1] *= c0;
            acc[ni][2] *= c1; acc[ni][3] *= c1;
        }
        m0 = mn0; m1 = mn1;

        // P = fp16(exp(sc - m)); acc += P@(Vh + Vl)
        #pragma unroll
        for (int kt = 0; kt < 4; kt++) {
            uint32_t ph[4];
            #pragma unroll
            for (int j = 0; j < 2; j++) {
                int ni = 2 * kt + j;
                float p0 = __expf(sc[ni][0] - m0);
                float p1 = __expf(sc[ni][1] - m0);
                float p2 = __expf(sc[ni][2] - m1);
                float p3 = __expf(sc[ni][3] - m1);
                l0 += p0 + p1; l1 += p2 + p3;
                ph[2 * j]     = packhf(p0, p1);
                ph[2 * j + 1] = packhf(p2, p3);
            }
            uint32_t Vh[4][4], Vl[4][4];
            int grp = lane >> 3, rr = lane & 7;
            #pragma unroll
            for (int p = 0; p < 4; p++) {
                uint32_t ad = kb + 18432
                    + (kt * 16 + (grp & 1) * 8 + rr) * 144
                    + (p * 16 + (grp >> 1) * 8) * 2;
                ldmBT(Vh[p], ad);
                ldmBT(Vl[p], ad + 9216);
            }
            #pragma unroll
            for (int nv = 0; nv < 8; nv++) {
                int g = nv >> 1, s = (nv & 1) * 2;
                mma16816h(acc[nv], ph, Vh[g][s], Vh[g][s + 1]);
                mma16816h(acc[nv], ph, Vl[g][s], Vl[g][s + 1]);
            }
        }

        __syncthreads();
        if (i + 2 < S_ / 64) issueKV(i + 2, i & 1);
        CP_COMMIT();
    }

    l0 += __shfl_xor_sync(0xffffffffu, l0, 1);
    l0 += __shfl_xor_sync(0xffffffffu, l0, 2);
    l1 += __shfl_xor_sync(0xffffffffu, l1, 1);
    l1 += __shfl_xor_sync(0xffffffffu, l1, 2);
    float i0 = 1.0f / l0, i1 = 1.0f / l1;

    int b = bh >> 4, h = bh & 15;
    int row0 = q0 + warpM + (lane >> 2);
    size_t ob0 = (size_t)(b * LQ_ + row0) * (H_ * DQK_) + h * DQK_;
    size_t ob1 = ob0 + (size_t)8 * (H_ * DQK_);
    #pragma unroll
    for (int nv = 0; nv < 8; nv++) {
        int col = nv * 8 + (lane & 3) * 2;
        float a0 = acc[nv][0] * i0, a1 = acc[nv][1] * i0;
        float a2 = acc[nv][2] * i1, a3 = acc[nv][3] * i1;
        float h0 = __bfloat162float(__float2bfloat16(a0));
        float h1 = __bfloat162float(__float2bfloat16(a1));
        float h2 = __bfloat162float(__float2bfloat16(a2));
        float h3 = __bfloat162float(__float2bfloat16(a3));
        *(uint32_t*)(oh + ob0 + col) = packbf(a0, a1);
        *(uint32_t*)(ol + ob0 + col) = packbf(a0 - h0, a1 - h1);
        *(uint32_t*)(oh + ob1 + col) = packbf(a2, a3);
        *(uint32_t*)(ol + ob1 + col) = packbf(a2 - h2, a3 - h3);
    }
}

// ---------------- launch ----------------
extern "C" void kernel_launch(void* const* d_in, const int* in_sizes, int n_in,
                              void* d_out, int out_size)
{
    (void)in_sizes; (void)n_in; (void)out_size;
    const float* x      = (const float*)d_in[0];
    const float* norm_w = (const float*)d_in[1];
    const float* wq_w   = (const float*)d_in[2];
    const float* wq_b   = (const float*)d_in[3];
    const float* wkv_w  = (const float*)d_in[4];
    const float* wkv_b  = (const float*)d_in[5];
    const float* wout_w = (const float*)d_in[6];
    const float* wout_b = (const float*)d_in[7];
    const float* wbyp_w = (const float*)d_in[8];
    float* out = (float*)d_out;

    float *p_qproj, *p_kvproj;
    cudaGetSymbolAddress((void**)&p_qproj,  g_qproj);
    cudaGetSymbolAddress((void**)&p_kvproj, g_kvproj);

    __half *nh, *wqh, *wql, *wkvh, *wkvl, *pqh, *pkh, *pkl, *pvh, *pvl;
    cudaGetSymbolAddress((void**)&nh,    g_nh);
    cudaGetSymbolAddress((void**)&wqh,   g_wqh);
    cudaGetSymbolAddress((void**)&wql,   g_wql);
    cudaGetSymbolAddress((void**)&wkvh,  g_wkvh);
    cudaGetSymbolAddress((void**)&wkvl,  g_wkvl);
    cudaGetSymbolAddress((void**)&pqh,   g_qh);
    cudaGetSymbolAddress((void**)&pkh,   g_kh);
    cudaGetSymbolAddress((void**)&pkl,   g_kl);
    cudaGetSymbolAddress((void**)&pvh,   g_vh);
    cudaGetSymbolAddress((void**)&pvl,   g_vl);

    __nv_bfloat16 *xh, *xl, *wouth, *woutl, *wbyph, *wbypl, *ath, *atl;
    cudaGetSymbolAddress((void**)&xh,    g_xh);
    cudaGetSymbolAddress((void**)&xl,    g_xl);
    cudaGetSymbolAddress((void**)&wouth, g_wouth);
    cudaGetSymbolAddress((void**)&woutl, g_woutl);
    cudaGetSymbolAddress((void**)&wbyph, g_wbyph);
    cudaGetSymbolAddress((void**)&wbypl, g_wbypl);
    cudaGetSymbolAddress((void**)&ath,   g_attnh);
    cudaGetSymbolAddress((void**)&atl,   g_attnl);

    cudaFuncSetAttribute(flash_mma, cudaFuncAttributeMaxDynamicSharedMemorySize, FSMEM);
    cudaFuncSetAttribute(gemm_f16, cudaFuncAttributeMaxDynamicSharedMemorySize, G2_SMEM);

    // 1. RMSNorm -> single fp16
    rmsnorm_kernel<<<B_ * S_, 128>>>(x, norm_w, nh);

    // 2. operand splits
    splith_kernel<<<(BPL_ * D_ * H_ * DQK_ / 4) / 256, 256>>>(wq_w, wqh, wql, BPL_ * D_ * H_ * DQK_ / 4);
    splith_kernel<<<(D_ * 2 * H_ * DQK_ / 4) / 256, 256>>>(wkv_w, wkvh, wkvl, D_ * 2 * H_ * DQK_ / 4);
    split_kernel<<<(B_ * S_ * D_ / 4) / 256, 256>>>(x, xh, xl, B_ * S_ * D_ / 4);
    split_kernel<<<(H_ * DQK_ * DLAT_ / 4) / 256, 256>>>(wout_w, wouth, woutl, H_ * DQK_ * DLAT_ / 4);
    split_kernel<<<(BPL_ * D_ * DLAT_ / 4) / 256, 256>>>(wbyp_w, wbyph, wbypl, BPL_ * D_ * DLAT_ / 4);

    // 3. Q projection (fp16 2-term)
    gemm_f16<<<dim3((H_ * DQK_) / 128, (B_ * LQ_) / 128), 256, G2_SMEM>>>(
        B_ * LQ_, H_ * DQK_, BPL_ * D_, nh, wqh, wql, wq_b, p_qproj);

    // 4. KV projection (fp16 2-term)
    gemm_f16<<<dim3((2 * H_ * DQK_) / 128, (B_ * S_) / 128), 256, G2_SMEM>>>(
        B_ * S_, 2 * H_ * DQK_, D_, nh, wkvh, wkvl, wkv_b, p_kvproj);

    // 5. RoPE + transposes -> fp16
    rope_q_kernel<<<(B_ * LQ_ * H_ * 32) / 256, 256>>>(p_qproj, pqh);
    rope_k_kernel<<<(B_ * S_ * H_ * 32) / 256, 256>>>(p_kvproj, pkh, pkl);
    vtrans_kernel<<<(B_ * S_ * H_ * 16) / 256, 256>>>(p_kvproj, pvh, pvl);

    // 6. Flash attention (fp16 2-term) -> attn bf16 hi/lo
    flash_mma<<<dim3(LQ_ / 128, B_ * H_), 256, FSMEM>>>(
        pqh, pkh, pkl, pvh, pvl, ath, atl);

    // 7. Bypass GEMM (bf16 3-term)
    gemm_mma<<<dim3(DLAT_ / 128, (B_ * LQ_) / 128), 256>>>(
        B_ * LQ_, DLAT_, BPL_ * D_, xh, xl, wbyph, wbypl, nullptr, out, 0);

    // 8. Out projection (bf16 3-term, accumulate)
    gemm_mma<<<dim3(DLAT_ / 128, (B_ * LQ_) / 128), 256>>>(
        B_ * LQ_, DLAT_, H_ * DQK_, ath, atl, wouth, woutl, wout_b, out, 1);
}

// round 8
// speedup vs baseline: 1.7719x; 1.2645x over previous
#include <cuda_runtime.h>
#include <cuda_bf16.h>
#include <cuda_fp16.h>
#include <math.h>
#include <stdint.h>

// ---------------- problem constants ----------------
#define B_   2
#define S_   4096
#define D_   512
#define BPL_ 4
#define H_   16
#define DQK_ 64
#define DLAT_ 1024
#define LQ_  (S_ / BPL_)          // 1024
#define EPS_ 1.1920929e-07f

// ---------------- scratch (device globals; no allocation allowed) ----------------
__device__ float g_qproj [B_ * LQ_ * H_ * DQK_];
__device__ float g_kvproj[B_ * S_ * 2 * H_ * DQK_];

// fp16 operands (attention path, single precision term)
__device__ __half g_nh  [B_ * S_ * D_];
__device__ __half g_wqh [BPL_ * D_ * H_ * DQK_];
__device__ __half g_wkvh[D_ * 2 * H_ * DQK_];
__device__ __half g_qh  [B_ * H_ * LQ_ * DQK_];          // pre-scaled by 0.125
__device__ __half g_kh  [B_ * H_ * S_ * DQK_];
__device__ __half g_vh  [B_ * H_ * S_ * DQK_];

// bf16 hi/lo operands for the 3-term final GEMMs (bypass + out-proj)
__device__ __nv_bfloat16 g_xh   [B_ * S_ * D_], g_xl   [B_ * S_ * D_];
__device__ __nv_bfloat16 g_wouth[H_ * DQK_ * DLAT_],  g_woutl[H_ * DQK_ * DLAT_];
__device__ __nv_bfloat16 g_wbyph[BPL_ * D_ * DLAT_],  g_wbypl[BPL_ * D_ * DLAT_];
__device__ __nv_bfloat16 g_attnh[B_ * LQ_ * H_ * DQK_], g_attnl[B_ * LQ_ * H_ * DQK_];

// ---------------- helpers ----------------
__device__ __forceinline__ uint32_t smem_to_u32(const void* p) {
    uint32_t a;
    asm("{ .reg .u64 t; cvta.to.shared.u64 t, %1; cvt.u32.u64 %0, t; }" : "=r"(a) : "l"(p));
    return a;
}

#define CP_ASYNC16(dst, src) \
    asm volatile("cp.async.cg.shared.global [%0], [%1], 16;" :: "r"(dst), "l"(src))
#define CP_COMMIT()  asm volatile("cp.async.commit_group;" ::: "memory")
#define CP_WAIT0()   asm volatile("cp.async.wait_group 0;" ::: "memory")
#define CP_WAIT1()   asm volatile("cp.async.wait_group 1;" ::: "memory")

__device__ __forceinline__ void ldmA(uint32_t* r, uint32_t addr) {
    asm volatile("ldmatrix.sync.aligned.m8n8.x4.shared.b16 {%0,%1,%2,%3}, [%4];"
                 : "=r"(r[0]), "=r"(r[1]), "=r"(r[2]), "=r"(r[3]) : "r"(addr));
}
__device__ __forceinline__ void ldmBT(uint32_t* r, uint32_t addr) {
    asm volatile("ldmatrix.sync.aligned.m8n8.x4.trans.shared.b16 {%0,%1,%2,%3}, [%4];"
                 : "=r"(r[0]), "=r"(r[1]), "=r"(r[2]), "=r"(r[3]) : "r"(addr));
}
// bf16 mma
__device__ __forceinline__ void mma16816(float* d, const uint32_t* a, const uint32_t* b) {
    asm volatile(
        "mma.sync.aligned.m16n8k16.row.col.f32.bf16.bf16.f32 "
        "{%0,%1,%2,%3}, {%4,%5,%6,%7}, {%8,%9}, {%0,%1,%2,%3};"
        : "+f"(d[0]), "+f"(d[1]), "+f"(d[2]), "+f"(d[3])
        : "r"(a[0]), "r"(a[1]), "r"(a[2]), "r"(a[3]), "r"(b[0]), "r"(b[1]));
}
// fp16 mma
__device__ __forceinline__ void mma16816h(float* d, const uint32_t* a, uint32_t b0, uint32_t b1) {
    asm volatile(
        "mma.sync.aligned.m16n8k16.row.col.f32.f16.f16.f32 "
        "{%0,%1,%2,%3}, {%4,%5,%6,%7}, {%8,%9}, {%0,%1,%2,%3};"
        : "+f"(d[0]), "+f"(d[1]), "+f"(d[2]), "+f"(d[3])
        : "r"(a[0]), "r"(a[1]), "r"(a[2]), "r"(a[3]), "r"(b0), "r"(b1));
}

__device__ __forceinline__ uint32_t packbf(float x, float y) {
    union { __nv_bfloat162 b; uint32_t u; } c;
    c.b = __halves2bfloat162(__float2bfloat16(x), __float2bfloat16(y));
    return c.u;
}
__device__ __forceinline__ uint32_t packhf(float x, float y) {
    union { __half2 h; uint32_t u; } c;
    c.h = __halves2half2(__float2half(x), __float2half(y));
    return c.u;
}

__device__ __forceinline__ void split4(float4 v, uint2& hi, uint2& lo) {
    __nv_bfloat16 hx = __float2bfloat16(v.x);
    __nv_bfloat16 hy = __float2bfloat16(v.y);
    __nv_bfloat16 hz = __float2bfloat16(v.z);
    __nv_bfloat16 hw = __float2bfloat16(v.w);
    union { __nv_bfloat162 b[2]; uint2 u; } c;
    c.b[0] = __halves2bfloat162(hx, hy);
    c.b[1] = __halves2bfloat162(hz, hw);
    hi = c.u;
    c.b[0] = __halves2bfloat162(__float2bfloat16(v.x - __bfloat162float(hx)),
                                __float2bfloat16(v.y - __bfloat162float(hy)));
    c.b[1] = __halves2bfloat162(__float2bfloat16(v.z - __bfloat162float(hz)),
                                __float2bfloat16(v.w - __bfloat162float(hw)));
    lo = c.u;
}

__device__ __forceinline__ uint2 conv4h(float4 v) {
    union { __half2 h[2]; uint2 u; } c;
    c.h[0] = __halves2half2(__float2half(v.x), __float2half(v.y));
    c.h[1] = __halves2half2(__float2half(v.z), __float2half(v.w));
    return c.u;
}

// ---------------- elementwise kernels ----------------
__global__ __launch_bounds__(256) void split_kernel(           // bf16 hi/lo
    const float* __restrict__ src, __nv_bfloat16* __restrict__ hi,
    __nv_bfloat16* __restrict__ lo, int n4)
{
    int i = blockIdx.x * blockDim.x + threadIdx.x;
    if (i >= n4) return;
    float4 v = ((const float4*)src)[i];
    uint2 h, l;
    split4(v, h, l);
    ((uint2*)hi)[i] = h;
    ((uint2*)lo)[i] = l;
}

__global__ __launch_bounds__(256) void convh_kernel(           // fp32 -> fp16
    const float* __restrict__ src, __half* __restrict__ dst, int n4)
{
    int i = blockIdx.x * blockDim.x + threadIdx.x;
    if (i >= n4) return;
    ((uint2*)dst)[i] = conv4h(((const float4*)src)[i]);
}

// RMSNorm -> single fp16
__global__ __launch_bounds__(128) void rmsnorm_kernel(
    const float* __restrict__ x, const float* __restrict__ w,
    __half* __restrict__ outh)
{
    int row = blockIdx.x;
    const float4* xr = (const float4*)(x + (size_t)row * D_);
    const float4* wr = (const float4*)w;
    int tid = threadIdx.x;

    float4 v = xr[tid];
    float s = v.x * v.x + v.y * v.y + v.z * v.z + v.w * v.w;
    #pragma unroll
    for (int o = 16; o > 0; o >>= 1) s += __shfl_xor_sync(0xffffffffu, s, o);
    __shared__ float red[4];
    int warp = tid >> 5, lane = tid & 31;
    if (lane == 0) red[warp] = s;
    __syncthreads();
    float total = red[0] + red[1] + red[2] + red[3];
    float inv = rsqrtf(total / (float)D_ + EPS_);
    float4 wv = wr[tid];
    float4 o4 = make_float4(v.x * inv * wv.x, v.y * inv * wv.y,
                            v.z * inv * wv.z, v.w * inv * wv.w);
    ((uint2*)outh)[row * (D_ / 4) + tid] = conv4h(o4);
}

// ---------------- fp16 single-term GEMM: C = A@B + bias ----------------
#define BKF  32
#define ASTR 40
#define BSTR 136
#define G1_A_B (128 * ASTR * 2)            // 10240
#define G1_B_B (BKF * BSTR * 2)            // 8704
#define G1_STG (G1_A_B + G1_B_B)           // 18944
#define G1_SMEM (2 * G1_STG)               // 37888

__global__ __launch_bounds__(256) void gemm_f16(
    int M, int N, int K,
    const __half* __restrict__ A, const __half* __restrict__ Bm,
    const float* __restrict__ bias, float* __restrict__ C)
{
    extern __shared__ char gsm[];
    const uint32_t sBase = smem_to_u32(gsm);

    const int tid = threadIdx.x;
    const int wid = tid >> 5, lane = tid & 31;
    const int mBase = blockIdx.y * 128;
    const int nBase = blockIdx.x * 128;
    const int warpM = (wid >> 1) * 32;
    const int warpN = (wid & 1) * 64;

    const int cpk = K / BKF;

    const int arow0 = tid >> 2, aseg = (tid & 3) * 8;
    const int brow0 = tid >> 4, bseg = (tid & 15) * 8;

    float acc[2][8][4];
    #pragma unroll
    for (int mi = 0; mi < 2; mi++)
        #pragma unroll
        for (int ni = 0; ni < 8; ni++)
            #pragma unroll
            for (int c = 0; c < 4; c++) acc[mi][ni][c] = 0.0f;

    auto issue = [&](int chunk) {
        int buf = chunk & 1;
        int k0 = chunk * BKF;
        uint32_t da = sBase + buf * G1_STG;
        uint32_t db = da + G1_A_B;
        const __half* aptr = A  + (size_t)mBase * K + k0 + aseg;
        const __half* bptr = Bm + (size_t)k0 * N + nBase + bseg;
        #pragma unroll
        for (int it = 0; it < 2; it++) {
            int row = arow0 + it * 64;
            CP_ASYNC16(da + row * (ASTR * 2) + aseg * 2, aptr + (size_t)row * K);
        }
        #pragma unroll
        for (int it = 0; it < 2; it++) {
            int row = brow0 + it * 16;
            CP_ASYNC16(db + row * (BSTR * 2) + bseg * 2, bptr + (size_t)row * N);
        }
        CP_COMMIT();
    };

    issue(0);

    for (int i = 0; i < cpk; i++) {
        if (i + 1 < cpk) { issue(i + 1); CP_WAIT1(); }
        else             { CP_WAIT0(); }
        __syncthreads();

        const uint32_t aBase = sBase + (i & 1) * G1_STG;
        const uint32_t bBase = aBase + G1_A_B;

        #pragma unroll
        for (int kk = 0; kk < 2; kk++) {
            uint32_t afrag[2][4];
            #pragma unroll
            for (int mi = 0; mi < 2; mi++) {
                uint32_t addr = aBase
                    + (warpM + mi * 16 + (lane & 15)) * (ASTR * 2)
                    + ((lane >> 4) << 4) + kk * 32;
                ldmA(afrag[mi], addr);
            }
            uint32_t bf[4][4];
            int grp = lane >> 3, r = lane & 7;
            #pragma unroll
            for (int p = 0; p < 4; p++) {
                uint32_t addr = bBase
                    + (kk * 16 + (grp & 1) * 8 + r) * (BSTR * 2)
                    + (warpN + p * 16 + (grp >> 1) * 8) * 2;
                ldmBT(bf[p], addr);
            }
            #pragma unroll
            for (int mi = 0; mi < 2; mi++)
                #pragma unroll
                for (int ni = 0; ni < 8; ni++) {
                    int g = ni >> 1, s = (ni & 1) * 2;
                    mma16816h(acc[mi][ni], afrag[mi], bf[g][s], bf[g][s + 1]);
                }
        }
        __syncthreads();
    }

    #pragma unroll
    for (int mi = 0; mi < 2; mi++) {
        #pragma unroll
        for (int ni = 0; ni < 8; ni++) {
            int r0 = mBase + warpM + mi * 16 + (lane >> 2);
            int c  = nBase + warpN + ni * 8 + (lane & 3) * 2;
            float2 v0 = make_float2(acc[mi][ni][0], acc[mi][ni][1]);
            float2 v1 = make_float2(acc[mi][ni][2], acc[mi][ni][3]);
            float2 bb = *(const float2*)(bias + c);
            v0.x += bb.x; v0.y += bb.y;
            v1.x += bb.x; v1.y += bb.y;
            *(float2*)(C + (size_t)r0 * N + c) = v0;
            *(float2*)(C + (size_t)(r0 + 8) * N + c) = v1;
        }
    }
}

// ---------------- bf16 3-term GEMM (for bypass + out-proj) ----------------
__global__ __launch_bounds__(256) void gemm_mma(
    int M, int N, int K,
    const __nv_bfloat16* __restrict__ Ahi, const __nv_bfloat16* __restrict__ Alo,
    const __nv_bfloat16* __restrict__ Bhi, const __nv_bfloat16* __restrict__ Blo,
    const float* __restrict__ bias, float* __restrict__ C, int accum)
{
    __shared__ __nv_bfloat16 As[2][128 * ASTR];
    __shared__ __nv_bfloat16 Bs[2][BKF * BSTR];

    const int tid = threadIdx.x;
    const int wid = tid >> 5, lane = tid & 31;
    const int mBase = blockIdx.y * 128;
    const int nBase = blockIdx.x * 128;
    const int warpM = (wid >> 1) * 32;
    const int warpN = (wid & 1) * 64;

    const uint32_t sA0 = smem_to_u32(As[0]);
    const uint32_t sB0 = smem_to_u32(Bs[0]);
    const uint32_t aStageB = 128 * ASTR * 2;
    const uint32_t bStageB = BKF * BSTR * 2;

    const int cpk = K / BKF;
    const int total = 3 * cpk;

    const int arow0 = tid >> 2, aseg = (tid & 3) * 8;
    const int brow0 = tid >> 4, bseg = (tid & 15) * 8;

    float acc[2][8][4];
    #pragma unroll
    for (int mi = 0; mi < 2; mi++)
        #pragma unroll
        for (int ni = 0; ni < 8; ni++)
            #pragma unroll
            for (int c = 0; c < 4; c++) acc[mi][ni][c] = 0.0f;

    auto issue = [&](int chunk, int buf) {
        int term = chunk / cpk;
        int k0 = (chunk - term * cpk) * BKF;
        const __nv_bfloat16* Asrc = (term < 2) ? Ahi : Alo;
        const __nv_bfloat16* Bsrc = (term == 1) ? Blo : Bhi;
        uint32_t da = sA0 + buf * aStageB;
        uint32_t db = sB0 + buf * bStageB;
        const __nv_bfloat16* aptr = Asrc + (size_t)mBase * K + k0 + aseg;
        const __nv_bfloat16* bptr = Bsrc + (size_t)k0 * N + nBase + bseg;
        #pragma unroll
        for (int it = 0; it < 2; it++) {
            int row = arow0 + it * 64;
            CP_ASYNC16(da + row * (ASTR * 2) + aseg * 2, aptr + (size_t)row * K);
        }
        #pragma unroll
        for (int it = 0; it < 2; it++) {
            int row = brow0 + it * 16;
            CP_ASYNC16(db + row * (BSTR * 2) + bseg * 2, bptr + (size_t)row * N);
        }
        CP_COMMIT();
    };

    issue(0, 0);

    for (int i = 0; i < total; i++) {
        if (i + 1 < total) { issue(i + 1, (i + 1) & 1); CP_WAIT1(); }
        else               { CP_WAIT0(); }
        __syncthreads();

        const int buf = i & 1;
        const uint32_t aBase = sA0 + buf * aStageB;
        const uint32_t bBase = sB0 + buf * bStageB;

        #pragma unroll
        for (int kk = 0; kk < 2; kk++) {
            uint32_t afrag[2][4];
            #pragma unroll
            for (int mi = 0; mi < 2; mi++) {
                uint32_t addr = aBase
                    + (warpM + mi * 16 + (lane & 15)) * (ASTR * 2)
                    + ((lane >> 4) << 4) + kk * 32;
                ldmA(afrag[mi], addr);
            }
            uint32_t bfrag[4][4];
            #pragma unroll
            for (int p = 0; p < 4; p++) {
                int grp = lane >> 3, r = lane & 7;
                uint32_t addr = bBase
                    + (kk * 16 + (grp & 1) * 8 + r) * (BSTR * 2)
                    + (warpN + p * 16 + (grp >> 1) * 8) * 2;
                ldmBT(bfrag[p], addr);
            }
            #pragma unroll
            for (int mi = 0; mi < 2; mi++)
                #pragma unroll
                for (int ni = 0; ni < 8; ni++)
                    mma16816(acc[mi][ni], afrag[mi], &bfrag[ni >> 1][(ni & 1) * 2]);
        }
        __syncthreads();
    }

    #pragma unroll
    for (int mi = 0; mi < 2; mi++) {
        #pragma unroll
        for (int ni = 0; ni < 8; ni++) {
            int r0 = mBase + warpM + mi * 16 + (lane >> 2);
            int c  = nBase + warpN + ni * 8 + (lane & 3) * 2;
            float2 v0 = make_float2(acc[mi][ni][0], acc[mi][ni][1]);
            float2 v1 = make_float2(acc[mi][ni][2], acc[mi][ni][3]);
            if (bias) {
                float2 bb = *(const float2*)(bias + c);
                v0.x += bb.x; v0.y += bb.y;
                v1.x += bb.x; v1.y += bb.y;
            }
            float* p0 = C + (size_t)r0 * N + c;
            float* p1 = C + (size_t)(r0 + 8) * N + c;
            if (accum) {
                float2 c0 = *(float2*)p0, c1 = *(float2*)p1;
                v0.x += c0.x; v0.y += c0.y;
                v1.x += c1.x; v1.y += c1.y;
            }
            *(float2*)p0 = v0;
            *(float2*)p1 = v1;
        }
    }
}

// ---------------- RoPE: emit fp16 ----------------
__device__ __forceinline__ float inv_freq_f(int d)
{
    return (float)pow(10000.0, -(double)d / 32.0);
}

__global__ __launch_bounds__(256) void rope_q_kernel(
    const float* __restrict__ qp, __half* __restrict__ qh)
{
    int idx = blockIdx.x * blockDim.x + threadIdx.x;
    int d  = idx & 31;
    int h  = (idx >> 5) & 15;
    int qi = (idx >> 9) & 1023;
    int b  = idx >> 19;
    const float* src = qp + ((size_t)(b * LQ_ + qi) * (H_ * DQK_)) + h * DQK_;
    float x1 = src[d], x2 = src[d + 32];
    float pos = (float)(qi * BPL_);
    float ang = pos * inv_freq_f(d);
    float c = cosf(ang), s = sinf(ang);
    size_t base = (((size_t)(b * H_ + h) * LQ_) + qi) * DQK_;
    qh[base + d]      = __float2half((x1 * c - x2 * s) * 0.125f);
    qh[base + d + 32] = __float2half((x1 * s + x2 * c) * 0.125f);
}

__global__ __launch_bounds__(256) void rope_k_kernel(
    const float* __restrict__ kvp, __half* __restrict__ khi)
{
    int idx = blockIdx.x * blockDim.x + threadIdx.x;
    int d  = idx & 31;
    int h  = (idx >> 5) & 15;
    int s  = (idx >> 9) & 4095;
    int b  = idx >> 21;
    const float* src = kvp + ((size_t)(b * S_ + s) * (2 * H_ * DQK_)) + h * DQK_;
    float x1 = src[d], x2 = src[d + 32];
    float pos = (float)s;
    float ang = pos * inv_freq_f(d);
    float c = cosf(ang), sn = sinf(ang);
    size_t base = (((size_t)(b * H_ + h) * S_) + s) * DQK_;
    khi[base + d]      = __float2half(x1 * c - x2 * sn);
    khi[base + d + 32] = __float2half(x1 * sn + x2 * c);
}

__global__ __launch_bounds__(256) void vtrans_kernel(
    const float* __restrict__ kvp, __half* __restrict__ vhi)
{
    int idx = blockIdx.x * blockDim.x + threadIdx.x;
    int d4 = idx & 15;
    int h  = (idx >> 4) & 15;
    int s  = (idx >> 8) & 4095;
    int b  = idx >> 20;
    const float4* src = (const float4*)(kvp + ((size_t)(b * S_ + s) * (2 * H_ * DQK_))
                                        + H_ * DQK_ + h * DQK_);
    size_t base = (((size_t)(b * H_ + h) * S_) + s) * DQK_;
    ((uint2*)(vhi + base))[d4] = conv4h(src[d4]);
}

// ---------------- flash attention via fp16 mma (single-term) ----------------
// smem per stage: kh,vh each 64 rows x 144B = 9216B -> 18432B; 2 stages.
#define FSTG 18432
#define FSMEM (2 * FSTG)

__global__ __launch_bounds__(256) void flash_mma(
    const __half* __restrict__ qh,
    const __half* __restrict__ kh, const __half* __restrict__ vh,
    __nv_bfloat16* __restrict__ oh, __nv_bfloat16* __restrict__ ol)
{
    extern __shared__ char sm[];
    const uint32_t sb = smem_to_u32(sm);
    const int tid = threadIdx.x, wid = tid >> 5, lane = tid & 31;
    const int bh = blockIdx.y;
    const int q0 = blockIdx.x * 128;
    const int warpM = wid * 16;
    const size_t qoff = ((size_t)bh * LQ_ + q0) * DQK_;
    const size_t koff = (size_t)bh * S_ * DQK_;

    // Q -> stage1 region (consumed before tile1 overwrites it): 128 rows x 144B = 18432B
    {
        #pragma unroll
        for (int it = 0; it < 4; it++) {
            int e = it * 256 + tid;
            int row = e >> 3, seg = (e & 7) * 8;
            CP_ASYNC16(sb + FSTG + row * 144 + seg * 2, qh + qoff + (size_t)row * DQK_ + seg);
        }
        CP_COMMIT();
    }

    auto issueKV = [&](int tile, int stage) {
        int sk = tile * 64;
        uint32_t dst = sb + stage * FSTG;
        #pragma unroll
        for (int it = 0; it < 2; it++) {
            int e = it * 256 + tid;
            int row = e >> 3, seg = (e & 7) * 8;
            size_t g = koff + (size_t)(sk + row) * DQK_ + seg;
            uint32_t so = row * 144 + seg * 2;
            CP_ASYNC16(dst + so,        kh + g);
            CP_ASYNC16(dst + 9216 + so, vh + g);
        }
    };

    issueKV(0, 0); CP_COMMIT();
    CP_WAIT1(); __syncthreads();

    uint32_t Qf[4][4];
    #pragma unroll
    for (int kt = 0; kt < 4; kt++) {
        uint32_t ad = sb + FSTG + (warpM + (lane & 15)) * 144 + ((lane >> 4) << 4) + kt * 32;
        ldmA(Qf[kt], ad);
    }
    __syncthreads();
    issueKV(1, 1); CP_COMMIT();

    float acc[8][4];
    #pragma unroll
    for (int n = 0; n < 8; n++)
        #pragma unroll
        for (int c = 0; c < 4; c++) acc[n][c] = 0.0f;
    float m0 = -1e30f, m1 = -1e30f, l0 = 0.0f, l1 = 0.0f;

    for (int i = 0; i < S_ / 64; i++) {
        CP_WAIT1(); __syncthreads();
        const uint32_t kb = sb + (i & 1) * FSTG;

        // scores = Q@K^T
        float sc[8][4];
        #pragma unroll
        for (int n = 0; n < 8; n++)
            #pragma unroll
            for (int c = 0; c < 4; c++) sc[n][c] = 0.0f;

        #pragma unroll
        for (int kt = 0; kt < 4; kt++) {
            uint32_t Bh[4][4];
            #pragma unroll
            for (int p = 0; p < 4; p++) {
                uint32_t ad = kb + (p * 16 + (lane & 15)) * 144 + ((lane >> 4) << 4) + kt * 32;
                ldmA(Bh[p], ad);
            }
            #pragma unroll
            for (int ni = 0; ni < 8; ni++) {
                int g = ni >> 1, s = ni & 1;
                mma16816h(sc[ni], Qf[kt], Bh[g][s], Bh[g][s + 2]);
            }
        }

        // online softmax (rows: lane>>2 and +8)
        float r0 = -1e30f, r1 = -1e30f;
        #pragma unroll
        for (int ni = 0; ni < 8; ni++) {
            r0 = fmaxf(r0, fmaxf(sc[ni][0], sc[ni][1]));
            r1 = fmaxf(r1, fmaxf(sc[ni][2], sc[ni][3]));
        }
        r0 = fmaxf(r0, __shfl_xor_sync(0xffffffffu, r0, 1));
        r0 = fmaxf(r0, __shfl_xor_sync(0xffffffffu, r0, 2));
        r1 = fmaxf(r1, __shfl_xor_sync(0xffffffffu, r1, 1));
        r1 = fmaxf(r1, __shfl_xor_sync(0xffffffffu, r1, 2));
        float mn0 = fmaxf(m0, r0), mn1 = fmaxf(m1, r1);
        float c0 = __expf(m0 - mn0), c1 = __expf(m1 - mn1);
        l0 *= c0; l1 *= c1;
        #pragma unroll
        for (int ni = 0; ni < 8; ni++) {
            acc[ni][0] *= c0; acc[ni][1] *= c0;
            acc[ni][2] *= c1; acc[ni][3] *= c1;
        }
        m0 = mn0; m1 = mn1;

        // P = fp16(exp(sc - m)); acc += P@V
        #pragma unroll
        for (int kt = 0; kt < 4; kt++) {
            uint32_t ph[4];
            #pragma unroll
            for (int j = 0; j < 2; j++) {
                int ni = 2 * kt + j;
                float p0 = __expf(sc[ni][0] - m0);
                float p1 = __expf(sc[ni][1] - m0);
                float p2 = __expf(sc[ni][2] - m1);
                float p3 = __expf(sc[ni][3] - m1);
                l0 += p0 + p1; l1 += p2 + p3;
                ph[2 * j]     = packhf(p0, p1);
                ph[2 * j + 1] = packhf(p2, p3);
            }
            uint32_t Vf[4][4];
            int grp = lane >> 3, rr = lane & 7;
            #pragma unroll
            for (int p = 0; p < 4; p++) {
                uint32_t ad = kb + 9216
                    + (kt * 16 + (grp & 1) * 8 + rr) * 144
                    + (p * 16 + (grp >> 1) * 8) * 2;
                ldmBT(Vf[p], ad);
            }
            #pragma unroll
            for (int nv = 0; nv < 8; nv++) {
                int g = nv >> 1, s = (nv & 1) * 2;
                mma16816h(acc[nv], ph, Vf[g][s], Vf[g][s + 1]);
            }
        }

        __syncthreads();
        if (i + 2 < S_ / 64) issueKV(i + 2, i & 1);
        CP_COMMIT();
    }

    l0 += __shfl_xor_sync(0xffffffffu, l0, 1);
    l0 += __shfl_xor_sync(0xffffffffu, l0, 2);
    l1 += __shfl_xor_sync(0xffffffffu, l1, 1);
    l1 += __shfl_xor_sync(0xffffffffu, l1, 2);
    float i0 = 1.0f / l0, i1 = 1.0f / l1;

    int b = bh >> 4, h = bh & 15;
    int row0 = q0 + warpM + (lane >> 2);
    size_t ob0 = (size_t)(b * LQ_ + row0) * (H_ * DQK_) + h * DQK_;
    size_t ob1 = ob0 + (size_t)8 * (H_ * DQK_);
    #pragma unroll
    for (int nv = 0; nv < 8; nv++) {
        int col = nv * 8 + (lane & 3) * 2;
        float a0 = acc[nv][0] * i0, a1 = acc[nv][1] * i0;
        float a2 = acc[nv][2] * i1, a3 = acc[nv][3] * i1;
        float h0 = __bfloat162float(__float2bfloat16(a0));
        float h1 = __bfloat162float(__float2bfloat16(a1));
        float h2 = __bfloat162float(__float2bfloat16(a2));
        float h3 = __bfloat162float(__float2bfloat16(a3));
        *(uint32_t*)(oh + ob0 + col) = packbf(a0, a1);
        *(uint32_t*)(ol + ob0 + col) = packbf(a0 - h0, a1 - h1);
        *(uint32_t*)(oh + ob1 + col) = packbf(a2, a3);
        *(uint32_t*)(ol + ob1 + col) = packbf(a2 - h2, a3 - h3);
    }
}

// ---------------- launch ----------------
extern "C" void kernel_launch(void* const* d_in, const int* in_sizes, int n_in,
                              void* d_out, int out_size)
{
    (void)in_sizes; (void)n_in; (void)out_size;
    const float* x      = (const float*)d_in[0];
    const float* norm_w = (const float*)d_in[1];
    const float* wq_w   = (const float*)d_in[2];
    const float* wq_b   = (const float*)d_in[3];
    const float* wkv_w  = (const float*)d_in[4];
    const float* wkv_b  = (const float*)d_in[5];
    const float* wout_w = (const float*)d_in[6];
    const float* wout_b = (const float*)d_in[7];
    const float* wbyp_w = (const float*)d_in[8];
    float* out = (float*)d_out;

    float *p_qproj, *p_kvproj;
    cudaGetSymbolAddress((void**)&p_qproj,  g_qproj);
    cudaGetSymbolAddress((void**)&p_kvproj, g_kvproj);

    __half *nh, *wqh, *wkvh, *pqh, *pkh, *pvh;
    cudaGetSymbolAddress((void**)&nh,    g_nh);
    cudaGetSymbolAddress((void**)&wqh,   g_wqh);
    cudaGetSymbolAddress((void**)&wkvh,  g_wkvh);
    cudaGetSymbolAddress((void**)&pqh,   g_qh);
    cudaGetSymbolAddress((void**)&pkh,   g_kh);
    cudaGetSymbolAddress((void**)&pvh,   g_vh);

    __nv_bfloat16 *xh, *xl, *wouth, *woutl, *wbyph, *wbypl, *ath, *atl;
    cudaGetSymbolAddress((void**)&xh,    g_xh);
    cudaGetSymbolAddress((void**)&xl,    g_xl);
    cudaGetSymbolAddress((void**)&wouth, g_wouth);
    cudaGetSymbolAddress((void**)&woutl, g_woutl);
    cudaGetSymbolAddress((void**)&wbyph, g_wbyph);
    cudaGetSymbolAddress((void**)&wbypl, g_wbypl);
    cudaGetSymbolAddress((void**)&ath,   g_attnh);
    cudaGetSymbolAddress((void**)&atl,   g_attnl);

    cudaFuncSetAttribute(flash_mma, cudaFuncAttributeMaxDynamicSharedMemorySize, FSMEM);
    cudaFuncSetAttribute(gemm_f16, cudaFuncAttributeMaxDynamicSharedMemorySize, G1_SMEM);

    // 1. RMSNorm -> single fp16
    rmsnorm_kernel<<<B_ * S_, 128>>>(x, norm_w, nh);

    // 2. operand conversions / splits
    convh_kernel<<<(BPL_ * D_ * H_ * DQK_ / 4) / 256, 256>>>(wq_w, wqh, BPL_ * D_ * H_ * DQK_ / 4);
    convh_kernel<<<(D_ * 2 * H_ * DQK_ / 4) / 256, 256>>>(wkv_w, wkvh, D_ * 2 * H_ * DQK_ / 4);
    split_kernel<<<(B_ * S_ * D_ / 4) / 256, 256>>>(x, xh, xl, B_ * S_ * D_ / 4);
    split_kernel<<<(H_ * DQK_ * DLAT_ / 4) / 256, 256>>>(wout_w, wouth, woutl, H_ * DQK_ * DLAT_ / 4);
    split_kernel<<<(BPL_ * D_ * DLAT_ / 4) / 256, 256>>>(wbyp_w, wbyph, wbypl, BPL_ * D_ * DLAT_ / 4);

    // 3. Q projection (fp16 single-term)
    gemm_f16<<<dim3((H_ * DQK_) / 128, (B_ * LQ_) / 128), 256, G1_SMEM>>>(
        B_ * LQ_, H_ * DQK_, BPL_ * D_, nh, wqh, wq_b, p_qproj);

    // 4. KV projection (fp16 single-term)
    gemm_f16<<<dim3((2 * H_ * DQK_) / 128, (B_ * S_) / 128), 256, G1_SMEM>>>(
        B_ * S_, 2 * H_ * DQK_, D_, nh, wkvh, wkv_b, p_kvproj);

    // 5. RoPE + transposes -> fp16
    rope_q_kernel<<<(B_ * LQ_ * H_ * 32) / 256, 256>>>(p_qproj, pqh);
    rope_k_kernel<<<(B_ * S_ * H_ * 32) / 256, 256>>>(p_kvproj, pkh);
    vtrans_kernel<<<(B_ * S_ * H_ * 16) / 256, 256>>>(p_kvproj, pvh);

    // 6. Flash attention (fp16 single-term) -> attn bf16 hi/lo
    flash_mma<<<dim3(LQ_ / 128, B_ * H_), 256, FSMEM>>>(pqh, pkh, pvh, ath, atl);

    // 7. Bypass GEMM (bf16 3-term)
    gemm_mma<<<dim3(DLAT_ / 128, (B_ * LQ_) / 128), 256>>>(
        B_ * LQ_, DLAT_, BPL_ * D_, xh, xl, wbyph, wbypl, nullptr, out, 0);

    // 8. Out projection (bf16 3-term, accumulate)
    gemm_mma<<<dim3(DLAT_ / 128, (B_ * LQ_) / 128), 256>>>(
        B_ * LQ_, DLAT_, H_ * DQK_, ath, atl, wouth, woutl, wout_b, out, 1);
}

// round 9
// speedup vs baseline: 2.1932x; 1.2377x over previous
#include <cuda_runtime.h>
#include <cuda_bf16.h>
#include <cuda_fp16.h>
#include <math.h>
#include <stdint.h>

// ---------------- problem constants ----------------
#define B_   2
#define S_   4096
#define D_   512
#define BPL_ 4
#define H_   16
#define DQK_ 64
#define DLAT_ 1024
#define LQ_  (S_ / BPL_)          // 1024
#define EPS_ 1.1920929e-07f

// ---------------- scratch (device globals; no allocation allowed) ----------------
__device__ float g_qproj [B_ * LQ_ * H_ * DQK_];
__device__ float g_kvproj[B_ * S_ * 2 * H_ * DQK_];

// fp16 operands
__device__ __half g_nh   [B_ * S_ * D_];
__device__ __half g_wqh  [BPL_ * D_ * H_ * DQK_];
__device__ __half g_wkvh [D_ * 2 * H_ * DQK_];
__device__ __half g_qh   [B_ * H_ * LQ_ * DQK_];          // pre-scaled by 0.125
__device__ __half g_kh   [B_ * H_ * S_ * DQK_];
__device__ __half g_vh   [B_ * H_ * S_ * DQK_];
__device__ __half g_x16  [B_ * S_ * D_];                  // x quantized fp16
__device__ __half g_attn16[B_ * LQ_ * H_ * DQK_];         // attn out fp16
// fp16 hi/lo weights for the 2-term output GEMMs
__device__ __half g_wouth[H_ * DQK_ * DLAT_], g_woutl[H_ * DQK_ * DLAT_];
__device__ __half g_wbyph[BPL_ * D_ * DLAT_], g_wbypl[BPL_ * D_ * DLAT_];

// ---------------- helpers ----------------
__device__ __forceinline__ uint32_t smem_to_u32(const void* p) {
    uint32_t a;
    asm("{ .reg .u64 t; cvta.to.shared.u64 t, %1; cvt.u32.u64 %0, t; }" : "=r"(a) : "l"(p));
    return a;
}

#define CP_ASYNC16(dst, src) \
    asm volatile("cp.async.cg.shared.global [%0], [%1], 16;" :: "r"(dst), "l"(src))
#define CP_COMMIT()  asm volatile("cp.async.commit_group;" ::: "memory")
#define CP_WAIT0()   asm volatile("cp.async.wait_group 0;" ::: "memory")
#define CP_WAIT1()   asm volatile("cp.async.wait_group 1;" ::: "memory")

__device__ __forceinline__ void ldmA(uint32_t* r, uint32_t addr) {
    asm volatile("ldmatrix.sync.aligned.m8n8.x4.shared.b16 {%0,%1,%2,%3}, [%4];"
                 : "=r"(r[0]), "=r"(r[1]), "=r"(r[2]), "=r"(r[3]) : "r"(addr));
}
__device__ __forceinline__ void ldmBT(uint32_t* r, uint32_t addr) {
    asm volatile("ldmatrix.sync.aligned.m8n8.x4.trans.shared.b16 {%0,%1,%2,%3}, [%4];"
                 : "=r"(r[0]), "=r"(r[1]), "=r"(r[2]), "=r"(r[3]) : "r"(addr));
}
// fp16 mma
__device__ __forceinline__ void mma16816h(float* d, const uint32_t* a, uint32_t b0, uint32_t b1) {
    asm volatile(
        "mma.sync.aligned.m16n8k16.row.col.f32.f16.f16.f32 "
        "{%0,%1,%2,%3}, {%4,%5,%6,%7}, {%8,%9}, {%0,%1,%2,%3};"
        : "+f"(d[0]), "+f"(d[1]), "+f"(d[2]), "+f"(d[3])
        : "r"(a[0]), "r"(a[1]), "r"(a[2]), "r"(a[3]), "r"(b0), "r"(b1));
}

__device__ __forceinline__ uint32_t packhf(float x, float y) {
    union { __half2 h; uint32_t u; } c;
    c.h = __halves2half2(__float2half(x), __float2half(y));
    return c.u;
}

__device__ __forceinline__ void split4h(float4 v, uint2& hi, uint2& lo) {
    __half hx = __float2half(v.x);
    __half hy = __float2half(v.y);
    __half hz = __float2half(v.z);
    __half hw = __float2half(v.w);
    union { __half2 h[2]; uint2 u; } c;
    c.h[0] = __halves2half2(hx, hy);
    c.h[1] = __halves2half2(hz, hw);
    hi = c.u;
    c.h[0] = __halves2half2(__float2half(v.x - __half2float(hx)),
                            __float2half(v.y - __half2float(hy)));
    c.h[1] = __halves2half2(__float2half(v.z - __half2float(hz)),
                            __float2half(v.w - __half2float(hw)));
    lo = c.u;
}

__device__ __forceinline__ uint2 conv4h(float4 v) {
    union { __half2 h[2]; uint2 u; } c;
    c.h[0] = __halves2half2(__float2half(v.x), __float2half(v.y));
    c.h[1] = __halves2half2(__float2half(v.z), __float2half(v.w));
    return c.u;
}

// ---------------- elementwise kernels ----------------
__global__ __launch_bounds__(256) void splith_kernel(          // fp16 hi/lo
    const float* __restrict__ src, __half* __restrict__ hi,
    __half* __restrict__ lo, int n4)
{
    int i = blockIdx.x * blockDim.x + threadIdx.x;
    if (i >= n4) return;
    float4 v = ((const float4*)src)[i];
    uint2 h, l;
    split4h(v, h, l);
    ((uint2*)hi)[i] = h;
    ((uint2*)lo)[i] = l;
}

__global__ __launch_bounds__(256) void convh_kernel(           // fp32 -> fp16
    const float* __restrict__ src, __half* __restrict__ dst, int n4)
{
    int i = blockIdx.x * blockDim.x + threadIdx.x;
    if (i >= n4) return;
    ((uint2*)dst)[i] = conv4h(((const float4*)src)[i]);
}

// RMSNorm -> single fp16
__global__ __launch_bounds__(128) void rmsnorm_kernel(
    const float* __restrict__ x, const float* __restrict__ w,
    __half* __restrict__ outh)
{
    int row = blockIdx.x;
    const float4* xr = (const float4*)(x + (size_t)row * D_);
    const float4* wr = (const float4*)w;
    int tid = threadIdx.x;

    float4 v = xr[tid];
    float s = v.x * v.x + v.y * v.y + v.z * v.z + v.w * v.w;
    #pragma unroll
    for (int o = 16; o > 0; o >>= 1) s += __shfl_xor_sync(0xffffffffu, s, o);
    __shared__ float red[4];
    int warp = tid >> 5, lane = tid & 31;
    if (lane == 0) red[warp] = s;
    __syncthreads();
    float total = red[0] + red[1] + red[2] + red[3];
    float inv = rsqrtf(total / (float)D_ + EPS_);
    float4 wv = wr[tid];
    float4 o4 = make_float4(v.x * inv * wv.x, v.y * inv * wv.y,
                            v.z * inv * wv.z, v.w * inv * wv.w);
    ((uint2*)outh)[row * (D_ / 4) + tid] = conv4h(o4);
}

// ---------------- fp16 single-term GEMM: C = A@B + bias ----------------
#define BKF  32
#define ASTR 40
#define BSTR 136
#define G1_A_B (128 * ASTR * 2)            // 10240
#define G1_B_B (BKF * BSTR * 2)            // 8704
#define G1_STG (G1_A_B + G1_B_B)           // 18944
#define G1_SMEM (2 * G1_STG)               // 37888

__global__ __launch_bounds__(256) void gemm_f16(
    int M, int N, int K,
    const __half* __restrict__ A, const __half* __restrict__ Bm,
    const float* __restrict__ bias, float* __restrict__ C)
{
    extern __shared__ char gsm[];
    const uint32_t sBase = smem_to_u32(gsm);

    const int tid = threadIdx.x;
    const int wid = tid >> 5, lane = tid & 31;
    const int mBase = blockIdx.y * 128;
    const int nBase = blockIdx.x * 128;
    const int warpM = (wid >> 1) * 32;
    const int warpN = (wid & 1) * 64;

    const int cpk = K / BKF;
    const int arow0 = tid >> 2, aseg = (tid & 3) * 8;
    const int brow0 = tid >> 4, bseg = (tid & 15) * 8;

    float acc[2][8][4];
    #pragma unroll
    for (int mi = 0; mi < 2; mi++)
        #pragma unroll
        for (int ni = 0; ni < 8; ni++)
            #pragma unroll
            for (int c = 0; c < 4; c++) acc[mi][ni][c] = 0.0f;

    auto issue = [&](int chunk) {
        int buf = chunk & 1;
        int k0 = chunk * BKF;
        uint32_t da = sBase + buf * G1_STG;
        uint32_t db = da + G1_A_B;
        const __half* aptr = A  + (size_t)mBase * K + k0 + aseg;
        const __half* bptr = Bm + (size_t)k0 * N + nBase + bseg;
        #pragma unroll
        for (int it = 0; it < 2; it++) {
            int row = arow0 + it * 64;
            CP_ASYNC16(da + row * (ASTR * 2) + aseg * 2, aptr + (size_t)row * K);
        }
        #pragma unroll
        for (int it = 0; it < 2; it++) {
            int row = brow0 + it * 16;
            CP_ASYNC16(db + row * (BSTR * 2) + bseg * 2, bptr + (size_t)row * N);
        }
        CP_COMMIT();
    };

    issue(0);

    for (int i = 0; i < cpk; i++) {
        if (i + 1 < cpk) { issue(i + 1); CP_WAIT1(); }
        else             { CP_WAIT0(); }
        __syncthreads();

        const uint32_t aBase = sBase + (i & 1) * G1_STG;
        const uint32_t bBase = aBase + G1_A_B;

        #pragma unroll
        for (int kk = 0; kk < 2; kk++) {
            uint32_t afrag[2][4];
            #pragma unroll
            for (int mi = 0; mi < 2; mi++) {
                uint32_t addr = aBase
                    + (warpM + mi * 16 + (lane & 15)) * (ASTR * 2)
                    + ((lane >> 4) << 4) + kk * 32;
                ldmA(afrag[mi], addr);
            }
            uint32_t bf[4][4];
            int grp = lane >> 3, r = lane & 7;
            #pragma unroll
            for (int p = 0; p < 4; p++) {
                uint32_t addr = bBase
                    + (kk * 16 + (grp & 1) * 8 + r) * (BSTR * 2)
                    + (warpN + p * 16 + (grp >> 1) * 8) * 2;
                ldmBT(bf[p], addr);
            }
            #pragma unroll
            for (int mi = 0; mi < 2; mi++)
                #pragma unroll
                for (int ni = 0; ni < 8; ni++) {
                    int g = ni >> 1, s = (ni & 1) * 2;
                    mma16816h(acc[mi][ni], afrag[mi], bf[g][s], bf[g][s + 1]);
                }
        }
        __syncthreads();
    }

    #pragma unroll
    for (int mi = 0; mi < 2; mi++) {
        #pragma unroll
        for (int ni = 0; ni < 8; ni++) {
            int r0 = mBase + warpM + mi * 16 + (lane >> 2);
            int c  = nBase + warpN + ni * 8 + (lane & 3) * 2;
            float2 v0 = make_float2(acc[mi][ni][0], acc[mi][ni][1]);
            float2 v1 = make_float2(acc[mi][ni][2], acc[mi][ni][3]);
            float2 bb = *(const float2*)(bias + c);
            v0.x += bb.x; v0.y += bb.y;
            v1.x += bb.x; v1.y += bb.y;
            *(float2*)(C + (size_t)r0 * N + c) = v0;
            *(float2*)(C + (size_t)(r0 + 8) * N + c) = v1;
        }
    }
}

// ---------------- fp16 2-term GEMM: C (+)= A@(Bh+Bl) (+bias) ----------------
#define G2_STG (G1_A_B + 2 * G1_B_B)       // 27648
#define G2_SMEM (2 * G2_STG)               // 55296

__global__ __launch_bounds__(256) void gemm_f16_2t(
    int M, int N, int K,
    const __half* __restrict__ A,
    const __half* __restrict__ Bh, const __half* __restrict__ Bl,
    const float* __restrict__ bias, float* __restrict__ C, int accum)
{
    extern __shared__ char gsm[];
    const uint32_t sBase = smem_to_u32(gsm);

    const int tid = threadIdx.x;
    const int wid = tid >> 5, lane = tid & 31;
    const int mBase = blockIdx.y * 128;
    const int nBase = blockIdx.x * 128;
    const int warpM = (wid >> 1) * 32;
    const int warpN = (wid & 1) * 64;

    const int cpk = K / BKF;
    const int arow0 = tid >> 2, aseg = (tid & 3) * 8;
    const int brow0 = tid >> 4, bseg = (tid & 15) * 8;

    float acc[2][8][4];
    #pragma unroll
    for (int mi = 0; mi < 2; mi++)
        #pragma unroll
        for (int ni = 0; ni < 8; ni++)
            #pragma unroll
            for (int c = 0; c < 4; c++) acc[mi][ni][c] = 0.0f;

    auto issue = [&](int chunk) {
        int buf = chunk & 1;
        int k0 = chunk * BKF;
        uint32_t da  = sBase + buf * G2_STG;
        uint32_t dbh = da + G1_A_B;
        uint32_t dbl = dbh + G1_B_B;
        const __half* aptr  = A  + (size_t)mBase * K + k0 + aseg;
        const __half* bhptr = Bh + (size_t)k0 * N + nBase + bseg;
        const __half* blptr = Bl + (size_t)k0 * N + nBase + bseg;
        #pragma unroll
        for (int it = 0; it < 2; it++) {
            int row = arow0 + it * 64;
            CP_ASYNC16(da + row * (ASTR * 2) + aseg * 2, aptr + (size_t)row * K);
        }
        #pragma unroll
        for (int it = 0; it < 2; it++) {
            int row = brow0 + it * 16;
            CP_ASYNC16(dbh + row * (BSTR * 2) + bseg * 2, bhptr + (size_t)row * N);
            CP_ASYNC16(dbl + row * (BSTR * 2) + bseg * 2, blptr + (size_t)row * N);
        }
        CP_COMMIT();
    };

    issue(0);

    for (int i = 0; i < cpk; i++) {
        if (i + 1 < cpk) { issue(i + 1); CP_WAIT1(); }
        else             { CP_WAIT0(); }
        __syncthreads();

        const uint32_t aBase  = sBase + (i & 1) * G2_STG;
        const uint32_t bhBase = aBase + G1_A_B;
        const uint32_t blBase = bhBase + G1_B_B;

        #pragma unroll
        for (int kk = 0; kk < 2; kk++) {
            uint32_t afrag[2][4];
            #pragma unroll
            for (int mi = 0; mi < 2; mi++) {
                uint32_t addr = aBase
                    + (warpM + mi * 16 + (lane & 15)) * (ASTR * 2)
                    + ((lane >> 4) << 4) + kk * 32;
                ldmA(afrag[mi], addr);
            }
            uint32_t bh[4][4], bl[4][4];
            int grp = lane >> 3, r = lane & 7;
            #pragma unroll
            for (int p = 0; p < 4; p++) {
                uint32_t off = (kk * 16 + (grp & 1) * 8 + r) * (BSTR * 2)
                    + (warpN + p * 16 + (grp >> 1) * 8) * 2;
                ldmBT(bh[p], bhBase + off);
                ldmBT(bl[p], blBase + off);
            }
            #pragma unroll
            for (int mi = 0; mi < 2; mi++)
                #pragma unroll
                for (int ni = 0; ni < 8; ni++) {
                    int g = ni >> 1, s = (ni & 1) * 2;
                    mma16816h(acc[mi][ni], afrag[mi], bh[g][s], bh[g][s + 1]);
                    mma16816h(acc[mi][ni], afrag[mi], bl[g][s], bl[g][s + 1]);
                }
        }
        __syncthreads();
    }

    #pragma unroll
    for (int mi = 0; mi < 2; mi++) {
        #pragma unroll
        for (int ni = 0; ni < 8; ni++) {
            int r0 = mBase + warpM + mi * 16 + (lane >> 2);
            int c  = nBase + warpN + ni * 8 + (lane & 3) * 2;
            float2 v0 = make_float2(acc[mi][ni][0], acc[mi][ni][1]);
            float2 v1 = make_float2(acc[mi][ni][2], acc[mi][ni][3]);
            if (bias) {
                float2 bb = *(const float2*)(bias + c);
                v0.x += bb.x; v0.y += bb.y;
                v1.x += bb.x; v1.y += bb.y;
            }
            float* p0 = C + (size_t)r0 * N + c;
            float* p1 = C + (size_t)(r0 + 8) * N + c;
            if (accum) {
                float2 c0 = *(float2*)p0, c1 = *(float2*)p1;
                v0.x += c0.x; v0.y += c0.y;
                v1.x += c1.x; v1.y += c1.y;
            }
            *(float2*)p0 = v0;
            *(float2*)p1 = v1;
        }
    }
}

// ---------------- RoPE: emit fp16 ----------------
__device__ __forceinline__ float inv_freq_f(int d)
{
    return (float)pow(10000.0, -(double)d / 32.0);
}

__global__ __launch_bounds__(256) void rope_q_kernel(
    const float* __restrict__ qp, __half* __restrict__ qh)
{
    int idx = blockIdx.x * blockDim.x + threadIdx.x;
    int d  = idx & 31;
    int h  = (idx >> 5) & 15;
    int qi = (idx >> 9) & 1023;
    int b  = idx >> 19;
    const float* src = qp + ((size_t)(b * LQ_ + qi) * (H_ * DQK_)) + h * DQK_;
    float x1 = src[d], x2 = src[d + 32];
    float pos = (float)(qi * BPL_);
    float ang = pos * inv_freq_f(d);
    float c = cosf(ang), s = sinf(ang);
    size_t base = (((size_t)(b * H_ + h) * LQ_) + qi) * DQK_;
    qh[base + d]      = __float2half((x1 * c - x2 * s) * 0.125f);
    qh[base + d + 32] = __float2half((x1 * s + x2 * c) * 0.125f);
}

__global__ __launch_bounds__(256) void rope_k_kernel(
    const float* __restrict__ kvp, __half* __restrict__ khi)
{
    int idx = blockIdx.x * blockDim.x + threadIdx.x;
    int d  = idx & 31;
    int h  = (idx >> 5) & 15;
    int s  = (idx >> 9) & 4095;
    int b  = idx >> 21;
    const float* src = kvp + ((size_t)(b * S_ + s) * (2 * H_ * DQK_)) + h * DQK_;
    float x1 = src[d], x2 = src[d + 32];
    float pos = (float)s;
    float ang = pos * inv_freq_f(d);
    float c = cosf(ang), sn = sinf(ang);
    size_t base = (((size_t)(b * H_ + h) * S_) + s) * DQK_;
    khi[base + d]      = __float2half(x1 * c - x2 * sn);
    khi[base + d + 32] = __float2half(x1 * sn + x2 * c);
}

__global__ __launch_bounds__(256) void vtrans_kernel(
    const float* __restrict__ kvp, __half* __restrict__ vhi)
{
    int idx = blockIdx.x * blockDim.x + threadIdx.x;
    int d4 = idx & 15;
    int h  = (idx >> 4) & 15;
    int s  = (idx >> 8) & 4095;
    int b  = idx >> 20;
    const float4* src = (const float4*)(kvp + ((size_t)(b * S_ + s) * (2 * H_ * DQK_))
                                        + H_ * DQK_ + h * DQK_);
    size_t base = (((size_t)(b * H_ + h) * S_) + s) * DQK_;
    ((uint2*)(vhi + base))[d4] = conv4h(src[d4]);
}

// ---------------- flash attention via fp16 mma (single-term) ----------------
#define FSTG 18432
#define FSMEM (2 * FSTG)

__global__ __launch_bounds__(256) void flash_mma(
    const __half* __restrict__ qh,
    const __half* __restrict__ kh, const __half* __restrict__ vh,
    __half* __restrict__ oh)
{
    extern __shared__ char sm[];
    const uint32_t sb = smem_to_u32(sm);
    const int tid = threadIdx.x, wid = tid >> 5, lane = tid & 31;
    const int bh = blockIdx.y;
    const int q0 = blockIdx.x * 128;
    const int warpM = wid * 16;
    const size_t qoff = ((size_t)bh * LQ_ + q0) * DQK_;
    const size_t koff = (size_t)bh * S_ * DQK_;

    {
        #pragma unroll
        for (int it = 0; it < 4; it++) {
            int e = it * 256 + tid;
            int row = e >> 3, seg = (e & 7) * 8;
            CP_ASYNC16(sb + FSTG + row * 144 + seg * 2, qh + qoff + (size_t)row * DQK_ + seg);
        }
        CP_COMMIT();
    }

    auto issueKV = [&](int tile, int stage) {
        int sk = tile * 64;
        uint32_t dst = sb + stage * FSTG;
        #pragma unroll
        for (int it = 0; it < 2; it++) {
            int e = it * 256 + tid;
            int row = e >> 3, seg = (e & 7) * 8;
            size_t g = koff + (size_t)(sk + row) * DQK_ + seg;
            uint32_t so = row * 144 + seg * 2;
            CP_ASYNC16(dst + so,        kh + g);
            CP_ASYNC16(dst + 9216 + so, vh + g);
        }
    };

    issueKV(0, 0); CP_COMMIT();
    CP_WAIT1(); __syncthreads();

    uint32_t Qf[4][4];
    #pragma unroll
    for (int kt = 0; kt < 4; kt++) {
        uint32_t ad = sb + FSTG + (warpM + (lane & 15)) * 144 + ((lane >> 4) << 4) + kt * 32;
        ldmA(Qf[kt], ad);
    }
    __syncthreads();
    issueKV(1, 1); CP_COMMIT();

    float acc[8][4];
    #pragma unroll
    for (int n = 0; n < 8; n++)
        #pragma unroll
        for (int c = 0; c < 4; c++) acc[n][c] = 0.0f;
    float m0 = -1e30f, m1 = -1e30f, l0 = 0.0f, l1 = 0.0f;

    for (int i = 0; i < S_ / 64; i++) {
        CP_WAIT1(); __syncthreads();
        const uint32_t kb = sb + (i & 1) * FSTG;

        float sc[8][4];
        #pragma unroll
        for (int n = 0; n < 8; n++)
            #pragma unroll
            for (int c = 0; c < 4; c++) sc[n][c] = 0.0f;

        #pragma unroll
        for (int kt = 0; kt < 4; kt++) {
            uint32_t Bh[4][4];
            #pragma unroll
            for (int p = 0; p < 4; p++) {
                uint32_t ad = kb + (p * 16 + (lane & 15)) * 144 + ((lane >> 4) << 4) + kt * 32;
                ldmA(Bh[p], ad);
            }
            #pragma unroll
            for (int ni = 0; ni < 8; ni++) {
                int g = ni >> 1, s = ni & 1;
                mma16816h(sc[ni], Qf[kt], Bh[g][s], Bh[g][s + 2]);
            }
        }

        float r0 = -1e30f, r1 = -1e30f;
        #pragma unroll
        for (int ni = 0; ni < 8; ni++) {
            r0 = fmaxf(r0, fmaxf(sc[ni][0], sc[ni][1]));
            r1 = fmaxf(r1, fmaxf(sc[ni][2], sc[ni][3]));
        }
        r0 = fmaxf(r0, __shfl_xor_sync(0xffffffffu, r0, 1));
        r0 = fmaxf(r0, __shfl_xor_sync(0xffffffffu, r0, 2));
        r1 = fmaxf(r1, __shfl_xor_sync(0xffffffffu, r1, 1));
        r1 = fmaxf(r1, __shfl_xor_sync(0xffffffffu, r1, 2));
        float mn0 = fmaxf(m0, r0), mn1 = fmaxf(m1, r1);
        float c0 = __expf(m0 - mn0), c1 = __expf(m1 - mn1);
        l0 *= c0; l1 *= c1;
        #pragma unroll
        for (int ni = 0; ni < 8; ni++) {
            acc[ni][0] *= c0; acc[ni][1] *= c0;
            acc[ni][2] *= c1; acc[ni][3] *= c1;
        }
        m0 = mn0; m1 = mn1;

        #pragma unroll
        for (int kt = 0; kt < 4; kt++) {
            uint32_t ph[4];
            #pragma unroll
            for (int j = 0; j < 2; j++) {
                int ni = 2 * kt + j;
                float p0 = __expf(sc[ni][0] - m0);
                float p1 = __expf(sc[ni][1] - m0);
                float p2 = __expf(sc[ni][2] - m1);
                float p3 = __expf(sc[ni][3] - m1);
                l0 += p0 + p1; l1 += p2 + p3;
                ph[2 * j]     = packhf(p0, p1);
                ph[2 * j + 1] = packhf(p2, p3);
            }
            uint32_t Vf[4][4];
            int grp = lane >> 3, rr = lane & 7;
            #pragma unroll
            for (int p = 0; p < 4; p++) {
                uint32_t ad = kb + 9216
                    + (kt * 16 + (grp & 1) * 8 + rr) * 144
                    + (p * 16 + (grp >> 1) * 8) * 2;
                ldmBT(Vf[p], ad);
            }
            #pragma unroll
            for (int nv = 0; nv < 8; nv++) {
                int g = nv >> 1, s = (nv & 1) * 2;
                mma16816h(acc[nv], ph, Vf[g][s], Vf[g][s + 1]);
            }
        }

        __syncthreads();
        if (i + 2 < S_ / 64) issueKV(i + 2, i & 1);
        CP_COMMIT();
    }

    l0 += __shfl_xor_sync(0xffffffffu, l0, 1);
    l0 += __shfl_xor_sync(0xffffffffu, l0, 2);
    l1 += __shfl_xor_sync(0xffffffffu, l1, 1);
    l1 += __shfl_xor_sync(0xffffffffu, l1, 2);
    float i0 = 1.0f / l0, i1 = 1.0f / l1;

    int b = bh >> 4, h = bh & 15;
    int row0 = q0 + warpM + (lane >> 2);
    size_t ob0 = (size_t)(b * LQ_ + row0) * (H_ * DQK_) + h * DQK_;
    size_t ob1 = ob0 + (size_t)8 * (H_ * DQK_);
    #pragma unroll
    for (int nv = 0; nv < 8; nv++) {
        int col = nv * 8 + (lane & 3) * 2;
        *(uint32_t*)(oh + ob0 + col) = packhf(acc[nv][0] * i0, acc[nv][1] * i0);
        *(uint32_t*)(oh + ob1 + col) = packhf(acc[nv][2] * i1, acc[nv][3] * i1);
    }
}

// ---------------- launch ----------------
extern "C" void kernel_launch(void* const* d_in, const int* in_sizes, int n_in,
                              void* d_out, int out_size)
{
    (void)in_sizes; (void)n_in; (void)out_size;
    const float* x      = (const float*)d_in[0];
    const float* norm_w = (const float*)d_in[1];
    const float* wq_w   = (const float*)d_in[2];
    const float* wq_b   = (const float*)d_in[3];
    const float* wkv_w  = (const float*)d_in[4];
    const float* wkv_b  = (const float*)d_in[5];
    const float* wout_w = (const float*)d_in[6];
    const float* wout_b = (const float*)d_in[7];
    const float* wbyp_w = (const float*)d_in[8];
    float* out = (float*)d_out;

    float *p_qproj, *p_kvproj;
    cudaGetSymbolAddress((void**)&p_qproj,  g_qproj);
    cudaGetSymbolAddress((void**)&p_kvproj, g_kvproj);

    __half *nh, *wqh, *wkvh, *pqh, *pkh, *pvh, *x16, *at16,
           *wouth, *woutl, *wbyph, *wbypl;
    cudaGetSymbolAddress((void**)&nh,    g_nh);
    cudaGetSymbolAddress((void**)&wqh,   g_wqh);
    cudaGetSymbolAddress((void**)&wkvh,  g_wkvh);
    cudaGetSymbolAddress((void**)&pqh,   g_qh);
    cudaGetSymbolAddress((void**)&pkh,   g_kh);
    cudaGetSymbolAddress((void**)&pvh,   g_vh);
    cudaGetSymbolAddress((void**)&x16,   g_x16);
    cudaGetSymbolAddress((void**)&at16,  g_attn16);
    cudaGetSymbolAddress((void**)&wouth, g_wouth);
    cudaGetSymbolAddress((void**)&woutl, g_woutl);
    cudaGetSymbolAddress((void**)&wbyph, g_wbyph);
    cudaGetSymbolAddress((void**)&wbypl, g_wbypl);

    cudaFuncSetAttribute(flash_mma, cudaFuncAttributeMaxDynamicSharedMemorySize, FSMEM);
    cudaFuncSetAttribute(gemm_f16, cudaFuncAttributeMaxDynamicSharedMemorySize, G1_SMEM);
    cudaFuncSetAttribute(gemm_f16_2t, cudaFuncAttributeMaxDynamicSharedMemorySize, G2_SMEM);

    // 1. RMSNorm -> single fp16
    rmsnorm_kernel<<<B_ * S_, 128>>>(x, norm_w, nh);

    // 2. operand conversions / splits
    convh_kernel<<<(BPL_ * D_ * H_ * DQK_ / 4) / 256, 256>>>(wq_w, wqh, BPL_ * D_ * H_ * DQK_ / 4);
    convh_kernel<<<(D_ * 2 * H_ * DQK_ / 4) / 256, 256>>>(wkv_w, wkvh, D_ * 2 * H_ * DQK_ / 4);
    convh_kernel<<<(B_ * S_ * D_ / 4) / 256, 256>>>(x, x16, B_ * S_ * D_ / 4);
    splith_kernel<<<(H_ * DQK_ * DLAT_ / 4) / 256, 256>>>(wout_w, wouth, woutl, H_ * DQK_ * DLAT_ / 4);
    splith_kernel<<<(BPL_ * D_ * DLAT_ / 4) / 256, 256>>>(wbyp_w, wbyph, wbypl, BPL_ * D_ * DLAT_ / 4);

    // 3. Q projection (fp16 single-term)
    gemm_f16<<<dim3((H_ * DQK_) / 128, (B_ * LQ_) / 128), 256, G1_SMEM>>>(
        B_ * LQ_, H_ * DQK_, BPL_ * D_, nh, wqh, wq_b, p_qproj);

    // 4. KV projection (fp16 single-term)
    gemm_f16<<<dim3((2 * H_ * DQK_) / 128, (B_ * S_) / 128), 256, G1_SMEM>>>(
        B_ * S_, 2 * H_ * DQK_, D_, nh, wkvh, wkv_b, p_kvproj);

    // 5. RoPE + transposes -> fp16
    rope_q_kernel<<<(B_ * LQ_ * H_ * 32) / 256, 256>>>(p_qproj, pqh);
    rope_k_kernel<<<(B_ * S_ * H_ * 32) / 256, 256>>>(p_kvproj, pkh);
    vtrans_kernel<<<(B_ * S_ * H_ * 16) / 256, 256>>>(p_kvproj, pvh);

    // 6. Flash attention (fp16 single-term) -> attn fp16
    flash_mma<<<dim3(LQ_ / 128, B_ * H_), 256, FSMEM>>>(pqh, pkh, pvh, at16);

    // 7. Bypass GEMM (fp16 2-term)
    gemm_f16_2t<<<dim3(DLAT_ / 128, (B_ * LQ_) / 128), 256, G2_SMEM>>>(
        B_ * LQ_, DLAT_, BPL_ * D_, x16, wbyph, wbypl, nullptr, out, 0);

    // 8. Out projection (fp16 2-term, accumulate)
    gemm_f16_2t<<<dim3(DLAT_ / 128, (B_ * LQ_) / 128), 256, G2_SMEM>>>(
        B_ * LQ_, DLAT_, H_ * DQK_, at16, wouth, woutl, wout_b, out, 1);
}

// round 11
// speedup vs baseline: 2.3963x; 1.0926x over previous
#include <cuda_runtime.h>
#include <cuda_bf16.h>
#include <cuda_fp16.h>
#include <math.h>
#include <stdint.h>

// ---------------- problem constants ----------------
#define B_   2
#define S_   4096
#define D_   512
#define BPL_ 4
#define H_   16
#define DQK_ 64
#define DLAT_ 1024
#define LQ_  (S_ / BPL_)          // 1024
#define EPS_ 1.1920929e-07f

// ---------------- scratch (device globals; no allocation allowed) ----------------
__device__ __half g_qproj [B_ * LQ_ * H_ * DQK_];         // fp16 proj outputs
__device__ __half g_kvproj[B_ * S_ * 2 * H_ * DQK_];

// fp16 operands
__device__ __half g_nh    [B_ * S_ * D_];
__device__ __half g_wqh   [BPL_ * D_ * H_ * DQK_];
__device__ __half g_wkvh  [D_ * 2 * H_ * DQK_];
__device__ __half g_qh    [B_ * H_ * LQ_ * DQK_];         // pre-scaled by 0.125
__device__ __half g_kh    [B_ * H_ * S_ * DQK_];
__device__ __half g_vh    [B_ * H_ * S_ * DQK_];
__device__ __half g_x16   [B_ * S_ * D_];                 // x quantized fp16
__device__ __half g_attn16[B_ * LQ_ * H_ * DQK_];         // attn out fp16
__device__ __half g_wout16[H_ * DQK_ * DLAT_];
__device__ __half g_wbyp16[BPL_ * D_ * DLAT_];

// ---------------- helpers ----------------
__device__ __forceinline__ uint32_t smem_to_u32(const void* p) {
    uint32_t a;
    asm("{ .reg .u64 t; cvta.to.shared.u64 t, %1; cvt.u32.u64 %0, t; }" : "=r"(a) : "l"(p));
    return a;
}

#define CP_ASYNC16(dst, src) \
    asm volatile("cp.async.cg.shared.global [%0], [%1], 16;" :: "r"(dst), "l"(src))
#define CP_COMMIT()  asm volatile("cp.async.commit_group;" ::: "memory")
#define CP_WAIT0()   asm volatile("cp.async.wait_group 0;" ::: "memory")
#define CP_WAIT1()   asm volatile("cp.async.wait_group 1;" ::: "memory")

__device__ __forceinline__ void ldmA(uint32_t* r, uint32_t addr) {
    asm volatile("ldmatrix.sync.aligned.m8n8.x4.shared.b16 {%0,%1,%2,%3}, [%4];"
                 : "=r"(r[0]), "=r"(r[1]), "=r"(r[2]), "=r"(r[3]) : "r"(addr));
}
__device__ __forceinline__ void ldmBT(uint32_t* r, uint32_t addr) {
    asm volatile("ldmatrix.sync.aligned.m8n8.x4.trans.shared.b16 {%0,%1,%2,%3}, [%4];"
                 : "=r"(r[0]), "=r"(r[1]), "=r"(r[2]), "=r"(r[3]) : "r"(addr));
}
// fp16 mma
__device__ __forceinline__ void mma16816h(float* d, const uint32_t* a, uint32_t b0, uint32_t b1) {
    asm volatile(
        "mma.sync.aligned.m16n8k16.row.col.f32.f16.f16.f32 "
        "{%0,%1,%2,%3}, {%4,%5,%6,%7}, {%8,%9}, {%0,%1,%2,%3};"
        : "+f"(d[0]), "+f"(d[1]), "+f"(d[2]), "+f"(d[3])
        : "r"(a[0]), "r"(a[1]), "r"(a[2]), "r"(a[3]), "r"(b0), "r"(b1));
}

__device__ __forceinline__ uint32_t packhf(float x, float y) {
    union { __half2 h; uint32_t u; } c;
    c.h = __halves2half2(__float2half(x), __float2half(y));
    return c.u;
}

__device__ __forceinline__ uint2 conv4h(float4 v) {
    union { __half2 h[2]; uint2 u; } c;
    c.h[0] = __halves2half2(__float2half(v.x), __float2half(v.y));
    c.h[1] = __halves2half2(__float2half(v.z), __float2half(v.w));
    return c.u;
}

// ---------------- elementwise kernels ----------------
__global__ __launch_bounds__(256) void convh_kernel(           // fp32 -> fp16
    const float* __restrict__ src, __half* __restrict__ dst, int n4)
{
    int i = blockIdx.x * blockDim.x + threadIdx.x;
    if (i >= n4) return;
    ((uint2*)dst)[i] = conv4h(((const float4*)src)[i]);
}

// RMSNorm -> single fp16
__global__ __launch_bounds__(128) void rmsnorm_kernel(
    const float* __restrict__ x, const float* __restrict__ w,
    __half* __restrict__ outh)
{
    int row = blockIdx.x;
    const float4* xr = (const float4*)(x + (size_t)row * D_);
    const float4* wr = (const float4*)w;
    int tid = threadIdx.x;

    float4 v = xr[tid];
    float s = v.x * v.x + v.y * v.y + v.z * v.z + v.w * v.w;
    #pragma unroll
    for (int o = 16; o > 0; o >>= 1) s += __shfl_xor_sync(0xffffffffu, s, o);
    __shared__ float red[4];
    int warp = tid >> 5, lane = tid & 31;
    if (lane == 0) red[warp] = s;
    __syncthreads();
    float total = red[0] + red[1] + red[2] + red[3];
    float inv = rsqrtf(total / (float)D_ + EPS_);
    float4 wv = wr[tid];
    float4 o4 = make_float4(v.x * inv * wv.x, v.y * inv * wv.y,
                            v.z * inv * wv.z, v.w * inv * wv.w);
    ((uint2*)outh)[row * (D_ / 4) + tid] = conv4h(o4);
}

// ---------------- fp16 single-term GEMM core ----------------
// OUTM: 0 = fp16 out (+bias), 1 = fp32 out (no accum), 2 = fp32 out accumulate (+bias)
#define BKF  32
#define ASTR 40
#define BSTR 136
#define G1_A_B (128 * ASTR * 2)            // 10240
#define G1_B_B (BKF * BSTR * 2)            // 8704
#define G1_STG (G1_A_B + G1_B_B)           // 18944
#define G1_SMEM (2 * G1_STG)               // 37888

template <int OUTM, typename OutT>
__global__ __launch_bounds__(256) void gemm_f16(
    int M, int N, int K,
    const __half* __restrict__ A, const __half* __restrict__ Bm,
    const float* __restrict__ bias, OutT* __restrict__ C)
{
    extern __shared__ char gsm[];
    const uint32_t sBase = smem_to_u32(gsm);

    const int tid = threadIdx.x;
    const int wid = tid >> 5, lane = tid & 31;
    const int mBase = blockIdx.y * 128;
    const int nBase = blockIdx.x * 128;
    const int warpM = (wid >> 1) * 32;
    const int warpN = (wid & 1) * 64;

    const int cpk = K / BKF;
    const int arow0 = tid >> 2, aseg = (tid & 3) * 8;
    const int brow0 = tid >> 4, bseg = (tid & 15) * 8;

    float acc[2][8][4];
    #pragma unroll
    for (int mi = 0; mi < 2; mi++)
        #pragma unroll
        for (int ni = 0; ni < 8; ni++)
            #pragma unroll
            for (int c = 0; c < 4; c++) acc[mi][ni][c] = 0.0f;

    auto issue = [&](int chunk) {
        int buf = chunk & 1;
        int k0 = chunk * BKF;
        uint32_t da = sBase + buf * G1_STG;
        uint32_t db = da + G1_A_B;
        const __half* aptr = A  + (size_t)mBase * K + k0 + aseg;
        const __half* bptr = Bm + (size_t)k0 * N + nBase + bseg;
        #pragma unroll
        for (int it = 0; it < 2; it++) {
            int row = arow0 + it * 64;
            CP_ASYNC16(da + row * (ASTR * 2) + aseg * 2, aptr + (size_t)row * K);
        }
        #pragma unroll
        for (int it = 0; it < 2; it++) {
            int row = brow0 + it * 16;
            CP_ASYNC16(db + row * (BSTR * 2) + bseg * 2, bptr + (size_t)row * N);
        }
        CP_COMMIT();
    };

    issue(0);

    for (int i = 0; i < cpk; i++) {
        if (i + 1 < cpk) { issue(i + 1); CP_WAIT1(); }
        else             { CP_WAIT0(); }
        __syncthreads();

        const uint32_t aBase = sBase + (i & 1) * G1_STG;
        const uint32_t bBase = aBase + G1_A_B;

        #pragma unroll
        for (int kk = 0; kk < 2; kk++) {
            uint32_t afrag[2][4];
            #pragma unroll
            for (int mi = 0; mi < 2; mi++) {
                uint32_t addr = aBase
                    + (warpM + mi * 16 + (lane & 15)) * (ASTR * 2)
                    + ((lane >> 4) << 4) + kk * 32;
                ldmA(afrag[mi], addr);
            }
            uint32_t bf[4][4];
            int grp = lane >> 3, r = lane & 7;
            #pragma unroll
            for (int p = 0; p < 4; p++) {
                uint32_t addr = bBase
                    + (kk * 16 + (grp & 1) * 8 + r) * (BSTR * 2)
                    + (warpN + p * 16 + (grp >> 1) * 8) * 2;
                ldmBT(bf[p], addr);
            }
            #pragma unroll
            for (int mi = 0; mi < 2; mi++)
                #pragma unroll
                for (int ni = 0; ni < 8; ni++) {
                    int g = ni >> 1, s = (ni & 1) * 2;
                    mma16816h(acc[mi][ni], afrag[mi], bf[g][s], bf[g][s + 1]);
                }
        }
        __syncthreads();
    }

    #pragma unroll
    for (int mi = 0; mi < 2; mi++) {
        #pragma unroll
        for (int ni = 0; ni < 8; ni++) {
            int r0 = mBase + warpM + mi * 16 + (lane >> 2);
            int c  = nBase + warpN + ni * 8 + (lane & 3) * 2;
            float2 v0 = make_float2(acc[mi][ni][0], acc[mi][ni][1]);
            float2 v1 = make_float2(acc[mi][ni][2], acc[mi][ni][3]);
            if (bias) {
                float2 bb = *(const float2*)(bias + c);
                v0.x += bb.x; v0.y += bb.y;
                v1.x += bb.x; v1.y += bb.y;
            }
            OutT* p0 = C + (size_t)r0 * N + c;
            OutT* p1 = C + (size_t)(r0 + 8) * N + c;
            if (OUTM == 0) {
                *(uint32_t*)p0 = packhf(v0.x, v0.y);
                *(uint32_t*)p1 = packhf(v1.x, v1.y);
            } else {
                float* f0 = (float*)p0;
                float* f1 = (float*)p1;
                if (OUTM == 2) {
                    float2 c0 = *(float2*)f0, c1 = *(float2*)f1;
                    v0.x += c0.x; v0.y += c0.y;
                    v1.x += c1.x; v1.y += c1.y;
                }
                *(float2*)f0 = v0;
                *(float2*)f1 = v1;
            }
        }
    }
}

// ---------------- RoPE: fp16 in, fp16 out ----------------
__device__ __forceinline__ float inv_freq_f(int d)
{
    return (float)pow(10000.0, -(double)d / 32.0);
}

__global__ __launch_bounds__(256) void rope_q_kernel(
    const __half* __restrict__ qp, __half* __restrict__ qh)
{
    int idx = blockIdx.x * blockDim.x + threadIdx.x;
    int d  = idx & 31;
    int h  = (idx >> 5) & 15;
    int qi = (idx >> 9) & 1023;
    int b  = idx >> 19;
    const __half* src = qp + ((size_t)(b * LQ_ + qi) * (H_ * DQK_)) + h * DQK_;
    float x1 = __half2float(src[d]), x2 = __half2float(src[d + 32]);
    float pos = (float)(qi * BPL_);
    float ang = pos * inv_freq_f(d);
    float c = cosf(ang), s = sinf(ang);
    size_t base = (((size_t)(b * H_ + h) * LQ_) + qi) * DQK_;
    qh[base + d]      = __float2half((x1 * c - x2 * s) * 0.125f);
    qh[base + d + 32] = __float2half((x1 * s + x2 * c) * 0.125f);
}

__global__ __launch_bounds__(256) void rope_k_kernel(
    const __half* __restrict__ kvp, __half* __restrict__ khi)
{
    int idx = blockIdx.x * blockDim.x + threadIdx.x;
    int d  = idx & 31;
    int h  = (idx >> 5) & 15;
    int s  = (idx >> 9) & 4095;
    int b  = idx >> 21;
    const __half* src = kvp + ((size_t)(b * S_ + s) * (2 * H_ * DQK_)) + h * DQK_;
    float x1 = __half2float(src[d]), x2 = __half2float(src[d + 32]);
    float pos = (float)s;
    float ang = pos * inv_freq_f(d);
    float c = cosf(ang), sn = sinf(ang);
    size_t base = (((size_t)(b * H_ + h) * S_) + s) * DQK_;
    khi[base + d]      = __float2half(x1 * c - x2 * sn);
    khi[base + d + 32] = __float2half(x1 * sn + x2 * c);
}

// FIXED: 16 work items per row, each copying uint2 (8B = 4 halves) -> full 64 halves
__global__ __launch_bounds__(256) void vtrans_kernel(
    const __half* __restrict__ kvp, __half* __restrict__ vhi)
{
    int idx = blockIdx.x * blockDim.x + threadIdx.x;
    int d4 = idx & 15;          // 16 x uint2 (8B = 4 halves) = 64 halves
    int h  = (idx >> 4) & 15;
    int s  = (idx >> 8) & 4095;
    int b  = idx >> 20;
    const uint2* src = (const uint2*)(kvp + ((size_t)(b * S_ + s) * (2 * H_ * DQK_))
                                      + H_ * DQK_ + h * DQK_);
    uint2* dst = (uint2*)(vhi + (((size_t)(b * H_ + h) * S_) + s) * DQK_);
    dst[d4] = src[d4];
}

// ---------------- flash attention via fp16 mma (single-term) ----------------
#define FSTG 18432
#define FSMEM (2 * FSTG)

__global__ __launch_bounds__(256) void flash_mma(
    const __half* __restrict__ qh,
    const __half* __restrict__ kh, const __half* __restrict__ vh,
    __half* __restrict__ oh)
{
    extern __shared__ char sm[];
    const uint32_t sb = smem_to_u32(sm);
    const int tid = threadIdx.x, wid = tid >> 5, lane = tid & 31;
    const int bh = blockIdx.y;
    const int q0 = blockIdx.x * 128;
    const int warpM = wid * 16;
    const size_t qoff = ((size_t)bh * LQ_ + q0) * DQK_;
    const size_t koff = (size_t)bh * S_ * DQK_;

    {
        #pragma unroll
        for (int it = 0; it < 4; it++) {
            int e = it * 256 + tid;
            int row = e >> 3, seg = (e & 7) * 8;
            CP_ASYNC16(sb + FSTG + row * 144 + seg * 2, qh + qoff + (size_t)row * DQK_ + seg);
        }
        CP_COMMIT();
    }

    auto issueKV = [&](int tile, int stage) {
        int sk = tile * 64;
        uint32_t dst = sb + stage * FSTG;
        #pragma unroll
        for (int it = 0; it < 2; it++) {
            int e = it * 256 + tid;
            int row = e >> 3, seg = (e & 7) * 8;
            size_t g = koff + (size_t)(sk + row) * DQK_ + seg;
            uint32_t so = row * 144 + seg * 2;
            CP_ASYNC16(dst + so,        kh + g);
            CP_ASYNC16(dst + 9216 + so, vh + g);
        }
    };

    issueKV(0, 0); CP_COMMIT();
    CP_WAIT1(); __syncthreads();

    uint32_t Qf[4][4];
    #pragma unroll
    for (int kt = 0; kt < 4; kt++) {
        uint32_t ad = sb + FSTG + (warpM + (lane & 15)) * 144 + ((lane >> 4) << 4) + kt * 32;
        ldmA(Qf[kt], ad);
    }
    __syncthreads();
    issueKV(1, 1); CP_COMMIT();

    float acc[8][4];
    #pragma unroll
    for (int n = 0; n < 8; n++)
        #pragma unroll
        for (int c = 0; c < 4; c++) acc[n][c] = 0.0f;
    float m0 = -1e30f, m1 = -1e30f, l0 = 0.0f, l1 = 0.0f;

    for (int i = 0; i < S_ / 64; i++) {
        CP_WAIT1(); __syncthreads();
        const uint32_t kb = sb + (i & 1) * FSTG;

        float sc[8][4];
        #pragma unroll
        for (int n = 0; n < 8; n++)
            #pragma unroll
            for (int c = 0; c < 4; c++) sc[n][c] = 0.0f;

        #pragma unroll
        for (int kt = 0; kt < 4; kt++) {
            uint32_t Bh[4][4];
            #pragma unroll
            for (int p = 0; p < 4; p++) {
                uint32_t ad = kb + (p * 16 + (lane & 15)) * 144 + ((lane >> 4) << 4) + kt * 32;
                ldmA(Bh[p], ad);
            }
            #pragma unroll
            for (int ni = 0; ni < 8; ni++) {
                int g = ni >> 1, s = ni & 1;
                mma16816h(sc[ni], Qf[kt], Bh[g][s], Bh[g][s + 2]);
            }
        }

        float r0 = -1e30f, r1 = -1e30f;
        #pragma unroll
        for (int ni = 0; ni < 8; ni++) {
            r0 = fmaxf(r0, fmaxf(sc[ni][0], sc[ni][1]));
            r1 = fmaxf(r1, fmaxf(sc[ni][2], sc[ni][3]));
        }
        r0 = fmaxf(r0, __shfl_xor_sync(0xffffffffu, r0, 1));
        r0 = fmaxf(r0, __shfl_xor_sync(0xffffffffu, r0, 2));
        r1 = fmaxf(r1, __shfl_xor_sync(0xffffffffu, r1, 1));
        r1 = fmaxf(r1, __shfl_xor_sync(0xffffffffu, r1, 2));
        float mn0 = fmaxf(m0, r0), mn1 = fmaxf(m1, r1);
        float c0 = __expf(m0 - mn0), c1 = __expf(m1 - mn1);
        l0 *= c0; l1 *= c1;
        #pragma unroll
        for (int ni = 0; ni < 8; ni++) {
            acc[ni][0] *= c0; acc[ni][1] *= c0;
            acc[ni][2] *= c1; acc[ni][3] *= c1;
        }
        m0 = mn0; m1 = mn1;

        #pragma unroll
        for (int kt = 0; kt < 4; kt++) {
            uint32_t ph[4];
            #pragma unroll
            for (int j = 0; j < 2; j++) {
                int ni = 2 * kt + j;
                float p0 = __expf(sc[ni][0] - m0);
                float p1 = __expf(sc[ni][1] - m0);
                float p2 = __expf(sc[ni][2] - m1);
                float p3 = __expf(sc[ni][3] - m1);
                l0 += p0 + p1; l1 += p2 + p3;
                ph[2 * j]     = packhf(p0, p1);
                ph[2 * j + 1] = packhf(p2, p3);
            }
            uint32_t Vf[4][4];
            int grp = lane >> 3, rr = lane & 7;
            #pragma unroll
            for (int p = 0; p < 4; p++) {
                uint32_t ad = kb + 9216
                    + (kt * 16 + (grp & 1) * 8 + rr) * 144
                    + (p * 16 + (grp >> 1) * 8) * 2;
                ldmBT(Vf[p], ad);
            }
            #pragma unroll
            for (int nv = 0; nv < 8; nv++) {
                int g = nv >> 1, s = (nv & 1) * 2;
                mma16816h(acc[nv], ph, Vf[g][s], Vf[g][s + 1]);
            }
        }

        __syncthreads();
        if (i + 2 < S_ / 64) issueKV(i + 2, i & 1);
        CP_COMMIT();
    }

    l0 += __shfl_xor_sync(0xffffffffu, l0, 1);
    l0 += __shfl_xor_sync(0xffffffffu, l0, 2);
    l1 += __shfl_xor_sync(0xffffffffu, l1, 1);
    l1 += __shfl_xor_sync(0xffffffffu, l1, 2);
    float i0 = 1.0f / l0, i1 = 1.0f / l1;

    int b = bh >> 4, h = bh & 15;
    int row0 = q0 + warpM + (lane >> 2);
    size_t ob0 = (size_t)(b * LQ_ + row0) * (H_ * DQK_) + h * DQK_;
    size_t ob1 = ob0 + (size_t)8 * (H_ * DQK_);
    #pragma unroll
    for (int nv = 0; nv < 8; nv++) {
        int col = nv * 8 + (lane & 3) * 2;
        *(uint32_t*)(oh + ob0 + col) = packhf(acc[nv][0] * i0, acc[nv][1] * i0);
        *(uint32_t*)(oh + ob1 + col) = packhf(acc[nv][2] * i1, acc[nv][3] * i1);
    }
}

// ---------------- launch ----------------
extern "C" void kernel_launch(void* const* d_in, const int* in_sizes, int n_in,
                              void* d_out, int out_size)
{
    (void)in_sizes; (void)n_in; (void)out_size;
    const float* x      = (const float*)d_in[0];
    const float* norm_w = (const float*)d_in[1];
    const float* wq_w   = (const float*)d_in[2];
    const float* wq_b   = (const float*)d_in[3];
    const float* wkv_w  = (const float*)d_in[4];
    const float* wkv_b  = (const float*)d_in[5];
    const float* wout_w = (const float*)d_in[6];
    const float* wout_b = (const float*)d_in[7];
    const float* wbyp_w = (const float*)d_in[8];
    float* out = (float*)d_out;

    __half *p_qproj, *p_kvproj, *nh, *wqh, *wkvh, *pqh, *pkh, *pvh, *x16, *at16,
           *wout16, *wbyp16;
    cudaGetSymbolAddress((void**)&p_qproj,  g_qproj);
    cudaGetSymbolAddress((void**)&p_kvproj, g_kvproj);
    cudaGetSymbolAddress((void**)&nh,     g_nh);
    cudaGetSymbolAddress((void**)&wqh,    g_wqh);
    cudaGetSymbolAddress((void**)&wkvh,   g_wkvh);
    cudaGetSymbolAddress((void**)&pqh,    g_qh);
    cudaGetSymbolAddress((void**)&pkh,    g_kh);
    cudaGetSymbolAddress((void**)&pvh,    g_vh);
    cudaGetSymbolAddress((void**)&x16,    g_x16);
    cudaGetSymbolAddress((void**)&at16,   g_attn16);
    cudaGetSymbolAddress((void**)&wout16, g_wout16);
    cudaGetSymbolAddress((void**)&wbyp16, g_wbyp16);

    cudaFuncSetAttribute(flash_mma, cudaFuncAttributeMaxDynamicSharedMemorySize, FSMEM);
    cudaFuncSetAttribute(gemm_f16<0, __half>, cudaFuncAttributeMaxDynamicSharedMemorySize, G1_SMEM);
    cudaFuncSetAttribute(gemm_f16<1, float>,  cudaFuncAttributeMaxDynamicSharedMemorySize, G1_SMEM);
    cudaFuncSetAttribute(gemm_f16<2, float>,  cudaFuncAttributeMaxDynamicSharedMemorySize, G1_SMEM);

    // 1. RMSNorm -> single fp16
    rmsnorm_kernel<<<B_ * S_, 128>>>(x, norm_w, nh);

    // 2. operand conversions
    convh_kernel<<<(BPL_ * D_ * H_ * DQK_ / 4) / 256, 256>>>(wq_w, wqh, BPL_ * D_ * H_ * DQK_ / 4);
    convh_kernel<<<(D_ * 2 * H_ * DQK_ / 4) / 256, 256>>>(wkv_w, wkvh, D_ * 2 * H_ * DQK_ / 4);
    convh_kernel<<<(B_ * S_ * D_ / 4) / 256, 256>>>(x, x16, B_ * S_ * D_ / 4);
    convh_kernel<<<(H_ * DQK_ * DLAT_ / 4) / 256, 256>>>(wout_w, wout16, H_ * DQK_ * DLAT_ / 4);
    convh_kernel<<<(BPL_ * D_ * DLAT_ / 4) / 256, 256>>>(wbyp_w, wbyp16, BPL_ * D_ * DLAT_ / 4);

    // 3. Q projection -> fp16
    gemm_f16<0, __half><<<dim3((H_ * DQK_) / 128, (B_ * LQ_) / 128), 256, G1_SMEM>>>(
        B_ * LQ_, H_ * DQK_, BPL_ * D_, nh, wqh, wq_b, p_qproj);

    // 4. KV projection -> fp16
    gemm_f16<0, __half><<<dim3((2 * H_ * DQK_) / 128, (B_ * S_) / 128), 256, G1_SMEM>>>(
        B_ * S_, 2 * H_ * DQK_, D_, nh, wkvh, wkv_b, p_kvproj);

    // 5. RoPE + transposes
    rope_q_kernel<<<(B_ * LQ_ * H_ * 32) / 256, 256>>>(p_qproj, pqh);
    rope_k_kernel<<<(B_ * S_ * H_ * 32) / 256, 256>>>(p_kvproj, pkh);
    vtrans_kernel<<<(B_ * S_ * H_ * 16) / 256, 256>>>(p_kvproj, pvh);

    // 6. Flash attention -> attn fp16
    flash_mma<<<dim3(LQ_ / 128, B_ * H_), 256, FSMEM>>>(pqh, pkh, pvh, at16);

    // 7. Bypass GEMM -> out (fp32, no accum, no bias)
    gemm_f16<1, float><<<dim3(DLAT_ / 128, (B_ * LQ_) / 128), 256, G1_SMEM>>>(
        B_ * LQ_, DLAT_, BPL_ * D_, x16, wbyp16, nullptr, out);

    // 8. Out projection (fp32 accumulate + bias)
    gemm_f16<2, float><<<dim3(DLAT_ / 128, (B_ * LQ_) / 128), 256, G1_SMEM>>>(
        B_ * LQ_, DLAT_, H_ * DQK_, at16, wout16, wout_b, out);
}

// round 13
// speedup vs baseline: 2.4577x; 1.0256x over previous
#include <cuda_runtime.h>
#include <cuda_bf16.h>
#include <cuda_fp16.h>
#include <math.h>
#include <stdint.h>

// ---------------- problem constants ----------------
#define B_   2
#define S_   4096
#define D_   512
#define BPL_ 4
#define H_   16
#define DQK_ 64
#define DLAT_ 1024
#define LQ_  (S_ / BPL_)          // 1024
#define EPS_ 1.1920929e-07f

// ---------------- scratch (device globals; no allocation allowed) ----------------
__device__ __half g_nh    [B_ * S_ * D_];
__device__ __half g_wqh   [BPL_ * D_ * H_ * DQK_];
__device__ __half g_wkvh  [D_ * 2 * H_ * DQK_];
__device__ __half g_qh    [B_ * H_ * LQ_ * DQK_];         // pre-scaled by 0.125
__device__ __half g_kh    [B_ * H_ * S_ * DQK_];
__device__ __half g_vh    [B_ * H_ * S_ * DQK_];
__device__ __half g_x16   [B_ * S_ * D_];
__device__ __half g_attn16[B_ * LQ_ * H_ * DQK_];
__device__ __half g_wout16[H_ * DQK_ * DLAT_];
__device__ __half g_wbyp16[BPL_ * D_ * DLAT_];

// ---------------- helpers ----------------
__device__ __forceinline__ uint32_t smem_to_u32(const void* p) {
    uint32_t a;
    asm("{ .reg .u64 t; cvta.to.shared.u64 t, %1; cvt.u32.u64 %0, t; }" : "=r"(a) : "l"(p));
    return a;
}

#define CP_ASYNC16(dst, src) \
    asm volatile("cp.async.cg.shared.global [%0], [%1], 16;" :: "r"(dst), "l"(src))
#define CP_COMMIT()  asm volatile("cp.async.commit_group;" ::: "memory")
#define CP_WAIT0()   asm volatile("cp.async.wait_group 0;" ::: "memory")
#define CP_WAIT1()   asm volatile("cp.async.wait_group 1;" ::: "memory")

__device__ __forceinline__ void ldmA(uint32_t* r, uint32_t addr) {
    asm volatile("ldmatrix.sync.aligned.m8n8.x4.shared.b16 {%0,%1,%2,%3}, [%4];"
                 : "=r"(r[0]), "=r"(r[1]), "=r"(r[2]), "=r"(r[3]) : "r"(addr));
}
__device__ __forceinline__ void ldmBT(uint32_t* r, uint32_t addr) {
    asm volatile("ldmatrix.sync.aligned.m8n8.x4.trans.shared.b16 {%0,%1,%2,%3}, [%4];"
                 : "=r"(r[0]), "=r"(r[1]), "=r"(r[2]), "=r"(r[3]) : "r"(addr));
}
__device__ __forceinline__ void mma16816h(float* d, const uint32_t* a, uint32_t b0, uint32_t b1) {
    asm volatile(
        "mma.sync.aligned.m16n8k16.row.col.f32.f16.f16.f32 "
        "{%0,%1,%2,%3}, {%4,%5,%6,%7}, {%8,%9}, {%0,%1,%2,%3};"
        : "+f"(d[0]), "+f"(d[1]), "+f"(d[2]), "+f"(d[3])
        : "r"(a[0]), "r"(a[1]), "r"(a[2]), "r"(a[3]), "r"(b0), "r"(b1));
}

__device__ __forceinline__ uint32_t packhf(float x, float y) {
    union { __half2 h; uint32_t u; } c;
    c.h = __halves2half2(__float2half(x), __float2half(y));
    return c.u;
}

__device__ __forceinline__ uint2 conv4h(float4 v) {
    union { __half2 h[2]; uint2 u; } c;
    c.h[0] = __halves2half2(__float2half(v.x), __float2half(v.y));
    c.h[1] = __halves2half2(__float2half(v.z), __float2half(v.w));
    return c.u;
}

__device__ __forceinline__ float inv_freq_f(int d)
{
    return (float)pow(10000.0, -(double)d / 32.0);
}

// ---------------- elementwise kernels ----------------
__global__ __launch_bounds__(256) void convh_kernel(
    const float* __restrict__ src, __half* __restrict__ dst, int n4)
{
    int i = blockIdx.x * blockDim.x + threadIdx.x;
    if (i >= n4) return;
    ((uint2*)dst)[i] = conv4h(((const float4*)src)[i]);
}

__global__ __launch_bounds__(128) void rmsnorm_kernel(
    const float* __restrict__ x, const float* __restrict__ w,
    __half* __restrict__ outh)
{
    int row = blockIdx.x;
    const float4* xr = (const float4*)(x + (size_t)row * D_);
    const float4* wr = (const float4*)w;
    int tid = threadIdx.x;

    float4 v = xr[tid];
    float s = v.x * v.x + v.y * v.y + v.z * v.z + v.w * v.w;
    #pragma unroll
    for (int o = 16; o > 0; o >>= 1) s += __shfl_xor_sync(0xffffffffu, s, o);
    __shared__ float red[4];
    int warp = tid >> 5, lane = tid & 31;
    if (lane == 0) red[warp] = s;
    __syncthreads();
    float total = red[0] + red[1] + red[2] + red[3];
    float inv = rsqrtf(total / (float)D_ + EPS_);
    float4 wv = wr[tid];
    float4 o4 = make_float4(v.x * inv * wv.x, v.y * inv * wv.y,
                            v.z * inv * wv.z, v.w * inv * wv.w);
    ((uint2*)outh)[row * (D_ / 4) + tid] = conv4h(o4);
}

// ---------------- shared GEMM mainloop ----------------
#define BKF  32
#define ASTR 40
#define BSTR 136
#define G1_A_B (128 * ASTR * 2)            // 10240
#define G1_B_B (BKF * BSTR * 2)            // 8704
#define G1_STG (G1_A_B + G1_B_B)           // 18944
#define G1_SMEM (2 * G1_STG)               // 37888

// Runs the full K loop, leaving results (+bias) in acc[2][8][4].
__device__ __forceinline__ void gemm_mainloop(
    uint32_t sBase, int N, int K,
    const __half* __restrict__ A, const __half* __restrict__ Bm,
    const float* __restrict__ bias,
    int mBase, int nBase, int warpM, int warpN, int tid, int lane,
    float acc[2][8][4])
{
    const int cpk = K / BKF;
    const int arow0 = tid >> 2, aseg = (tid & 3) * 8;
    const int brow0 = tid >> 4, bseg = (tid & 15) * 8;

    #pragma unroll
    for (int mi = 0; mi < 2; mi++)
        #pragma unroll
        for (int ni = 0; ni < 8; ni++)
            #pragma unroll
            for (int c = 0; c < 4; c++) acc[mi][ni][c] = 0.0f;

    auto issue = [&](int chunk) {
        int buf = chunk & 1;
        int k0 = chunk * BKF;
        uint32_t da = sBase + buf * G1_STG;
        uint32_t db = da + G1_A_B;
        const __half* aptr = A  + (size_t)mBase * K + k0 + aseg;
        const __half* bptr = Bm + (size_t)k0 * N + nBase + bseg;
        #pragma unroll
        for (int it = 0; it < 2; it++) {
            int row = arow0 + it * 64;
            CP_ASYNC16(da + row * (ASTR * 2) + aseg * 2, aptr + (size_t)row * K);
        }
        #pragma unroll
        for (int it = 0; it < 2; it++) {
            int row = brow0 + it * 16;
            CP_ASYNC16(db + row * (BSTR * 2) + bseg * 2, bptr + (size_t)row * N);
        }
        CP_COMMIT();
    };

    issue(0);

    for (int i = 0; i < cpk; i++) {
        if (i + 1 < cpk) { issue(i + 1); CP_WAIT1(); }
        else             { CP_WAIT0(); }
        __syncthreads();

        const uint32_t aBase = sBase + (i & 1) * G1_STG;
        const uint32_t bBase = aBase + G1_A_B;

        #pragma unroll
        for (int kk = 0; kk < 2; kk++) {
            uint32_t afrag[2][4];
            #pragma unroll
            for (int mi = 0; mi < 2; mi++) {
                uint32_t addr = aBase
                    + (warpM + mi * 16 + (lane & 15)) * (ASTR * 2)
                    + ((lane >> 4) << 4) + kk * 32;
                ldmA(afrag[mi], addr);
            }
            uint32_t bf[4][4];
            int grp = lane >> 3, r = lane & 7;
            #pragma unroll
            for (int p = 0; p < 4; p++) {
                uint32_t addr = bBase
                    + (kk * 16 + (grp & 1) * 8 + r) * (BSTR * 2)
                    + (warpN + p * 16 + (grp >> 1) * 8) * 2;
                ldmBT(bf[p], addr);
            }
            #pragma unroll
            for (int mi = 0; mi < 2; mi++)
                #pragma unroll
                for (int ni = 0; ni < 8; ni++) {
                    int g = ni >> 1, s = (ni & 1) * 2;
                    mma16816h(acc[mi][ni], afrag[mi], bf[g][s], bf[g][s + 1]);
                }
        }
        __syncthreads();
    }

    if (bias) {
        #pragma unroll
        for (int ni = 0; ni < 8; ni++) {
            int c = nBase + warpN + ni * 8 + (lane & 3) * 2;
            float2 bb = *(const float2*)(bias + c);
            #pragma unroll
            for (int mi = 0; mi < 2; mi++) {
                acc[mi][ni][0] += bb.x; acc[mi][ni][1] += bb.y;
                acc[mi][ni][2] += bb.x; acc[mi][ni][3] += bb.y;
            }
        }
    }
}

// ---------------- generic fp16 GEMM (fp32 out; OUTM 1 = store, 2 = accumulate) ----------------
template <int OUTM>
__global__ __launch_bounds__(256) void gemm_f16(
    int M, int N, int K,
    const __half* __restrict__ A, const __half* __restrict__ Bm,
    const float* __restrict__ bias, float* __restrict__ C)
{
    extern __shared__ char gsm[];
    const uint32_t sBase = smem_to_u32(gsm);
    const int tid = threadIdx.x;
    const int wid = tid >> 5, lane = tid & 31;
    const int mBase = blockIdx.y * 128;
    const int nBase = blockIdx.x * 128;
    const int warpM = (wid >> 1) * 32;
    const int warpN = (wid & 1) * 64;

    float acc[2][8][4];
    gemm_mainloop(sBase, N, K, A, Bm, bias, mBase, nBase, warpM, warpN, tid, lane, acc);

    #pragma unroll
    for (int mi = 0; mi < 2; mi++) {
        #pragma unroll
        for (int ni = 0; ni < 8; ni++) {
            int r0 = mBase + warpM + mi * 16 + (lane >> 2);
            int c  = nBase + warpN + ni * 8 + (lane & 3) * 2;
            float2 v0 = make_float2(acc[mi][ni][0], acc[mi][ni][1]);
            float2 v1 = make_float2(acc[mi][ni][2], acc[mi][ni][3]);
            float* f0 = C + (size_t)r0 * N + c;
            float* f1 = C + (size_t)(r0 + 8) * N + c;
            if (OUTM == 2) {
                float2 c0 = *(float2*)f0, c1 = *(float2*)f1;
                v0.x += c0.x; v0.y += c0.y;
                v1.x += c1.x; v1.y += c1.y;
            }
            *(float2*)f0 = v0;
            *(float2*)f1 = v1;
        }
    }
}

// ---------------- Q projection GEMM with fused RoPE epilogue ----------------
// A = normalized (2048 x 2048), B = wq (2048 x 1024), out -> qh (B,H,LQ,64) * 0.125
__global__ __launch_bounds__(256) void gemm_qproj(
    const __half* __restrict__ A, const __half* __restrict__ Bm,
    const float* __restrict__ bias, __half* __restrict__ qh)
{
    extern __shared__ char gsm[];
    const uint32_t sBase = smem_to_u32(gsm);
    const int tid = threadIdx.x;
    const int wid = tid >> 5, lane = tid & 31;
    const int mBase = blockIdx.y * 128;
    const int nBase = blockIdx.x * 128;
    const int warpM = (wid >> 1) * 32;
    const int warpN = (wid & 1) * 64;
    const int N = H_ * DQK_, K = BPL_ * D_;

    float acc[2][8][4];
    gemm_mainloop(sBase, N, K, A, Bm, bias, mBase, nBase, warpM, warpN, tid, lane, acc);

    const int hcol = (nBase + warpN) >> 6;   // head index (64-col aligned)

    #pragma unroll
    for (int mi = 0; mi < 2; mi++) {
        int r0 = mBase + warpM + mi * 16 + (lane >> 2);
        int r1 = r0 + 8;
        int qi0 = r0 & (LQ_ - 1), b0 = r0 >> 10;
        int qi1 = r1 & (LQ_ - 1), b1 = r1 >> 10;
        float pos0 = (float)(qi0 * BPL_), pos1 = (float)(qi1 * BPL_);
        size_t base0 = (((size_t)(b0 * H_ + hcol) * LQ_) + qi0) * DQK_;
        size_t base1 = (((size_t)(b1 * H_ + hcol) * LQ_) + qi1) * DQK_;
        #pragma unroll
        for (int ni = 0; ni < 4; ni++) {
            int d0 = ni * 8 + (lane & 3) * 2;
            float f0 = inv_freq_f(d0), f1 = inv_freq_f(d0 + 1);
            // row r0: elements [0],[1]; partners acc[mi][ni+4]
            {
                float a0 = pos0 * f0, a1 = pos0 * f1;
                float c0 = cosf(a0), s0 = sinf(a0), c1 = cosf(a1), s1 = sinf(a1);
                float x1a = acc[mi][ni][0],     x1b = acc[mi][ni][1];
                float x2a = acc[mi][ni + 4][0], x2b = acc[mi][ni + 4][1];
                *(uint32_t*)(qh + base0 + d0) =
                    packhf((x1a * c0 - x2a * s0) * 0.125f, (x1b * c1 - x2b * s1) * 0.125f);
                *(uint32_t*)(qh + base0 + d0 + 32) =
                    packhf((x1a * s0 + x2a * c0) * 0.125f, (x1b * s1 + x2b * c1) * 0.125f);
            }
            // row r1: elements [2],[3]
            {
                float a0 = pos1 * f0, a1 = pos1 * f1;
                float c0 = cosf(a0), s0 = sinf(a0), c1 = cosf(a1), s1 = sinf(a1);
                float x1a = acc[mi][ni][2],     x1b = acc[mi][ni][3];
                float x2a = acc[mi][ni + 4][2], x2b = acc[mi][ni + 4][3];
                *(uint32_t*)(qh + base1 + d0) =
                    packhf((x1a * c0 - x2a * s0) * 0.125f, (x1b * c1 - x2b * s1) * 0.125f);
                *(uint32_t*)(qh + base1 + d0 + 32) =
                    packhf((x1a * s0 + x2a * c0) * 0.125f, (x1b * s1 + x2b * c1) * 0.125f);
            }
        }
    }
}

// ---------------- KV projection GEMM with fused RoPE-K / transpose-V epilogue ----------------
// A = normalized (8192 x 512), B = wkv (512 x 2048); K half ropes -> kh, V half -> vh
__global__ __launch_bounds__(256) void gemm_kvproj(
    const __half* __restrict__ A, const __half* __restrict__ Bm,
    const float* __restrict__ bias,
    __half* __restrict__ kh, __half* __restrict__ vh)
{
    extern __shared__ char gsm[];
    const uint32_t sBase = smem_to_u32(gsm);
    const int tid = threadIdx.x;
    const int wid = tid >> 5, lane = tid & 31;
    const int mBase = blockIdx.y * 128;
    const int nBase = blockIdx.x * 128;
    const int warpM = (wid >> 1) * 32;
    const int warpN = (wid & 1) * 64;
    const int N = 2 * H_ * DQK_, K = D_;

    float acc[2][8][4];
    gemm_mainloop(sBase, N, K, A, Bm, bias, mBase, nBase, warpM, warpN, tid, lane, acc);

    const int colBase = nBase + warpN;
    const bool isK = colBase < H_ * DQK_;
    const int hcol = (colBase & (H_ * DQK_ - 1)) >> 6;

    #pragma unroll
    for (int mi = 0; mi < 2; mi++) {
        int r0 = mBase + warpM + mi * 16 + (lane >> 2);
        int r1 = r0 + 8;
        int s0 = r0 & (S_ - 1), b0 = r0 >> 12;
        int s1 = r1 & (S_ - 1), b1 = r1 >> 12;
        size_t base0 = (((size_t)(b0 * H_ + hcol) * S_) + s0) * DQK_;
        size_t base1 = (((size_t)(b1 * H_ + hcol) * S_) + s1) * DQK_;

        if (isK) {
            float pos0 = (float)s0, pos1 = (float)s1;
            #pragma unroll
            for (int ni = 0; ni < 4; ni++) {
                int d0 = ni * 8 + (lane & 3) * 2;
                float f0 = inv_freq_f(d0), f1 = inv_freq_f(d0 + 1);
                {
                    float a0 = pos0 * f0, a1 = pos0 * f1;
                    float c0 = cosf(a0), sn0 = sinf(a0), c1 = cosf(a1), sn1 = sinf(a1);
                    float x1a = acc[mi][ni][0],     x1b = acc[mi][ni][1];
                    float x2a = acc[mi][ni + 4][0], x2b = acc[mi][ni + 4][1];
                    *(uint32_t*)(kh + base0 + d0) =
                        packhf(x1a * c0 - x2a * sn0, x1b * c1 - x2b * sn1);
                    *(uint32_t*)(kh + base0 + d0 + 32) =
                        packhf(x1a * sn0 + x2a * c0, x1b * sn1 + x2b * c1);
                }
                {
                    float a0 = pos1 * f0, a1 = pos1 * f1;
                    float c0 = cosf(a0), sn0 = sinf(a0), c1 = cosf(a1), sn1 = sinf(a1);
                    float x1a = acc[mi][ni][2],     x1b = acc[mi][ni][3];
                    float x2a = acc[mi][ni + 4][2], x2b = acc[mi][ni + 4][3];
                    *(uint32_t*)(kh + base1 + d0) =
                        packhf(x1a * c0 - x2a * sn0, x1b * c1 - x2b * sn1);
                    *(uint32_t*)(kh + base1 + d0 + 32) =
                        packhf(x1a * sn0 + x2a * c0, x1b * sn1 + x2b * c1);
                }
            }
        } else {
            #pragma unroll
            for (int ni = 0; ni < 8; ni++) {
                int d0 = ni * 8 + (lane & 3) * 2;
                *(uint32_t*)(vh + base0 + d0) = packhf(acc[mi][ni][0], acc[mi][ni][1]);
                *(uint32_t*)(vh + base1 + d0) = packhf(acc[mi][ni][2], acc[mi][ni][3]);
            }
        }
    }
}

// ---------------- flash attention via fp16 mma (single-term) ----------------
#define FSTG 18432
#define FSMEM (2 * FSTG)

__global__ __launch_bounds__(256) void flash_mma(
    const __half* __restrict__ qh,
    const __half* __restrict__ kh, const __half* __restrict__ vh,
    __half* __restrict__ oh)
{
    extern __shared__ char sm[];
    const uint32_t sb = smem_to_u32(sm);
    const int tid = threadIdx.x, wid = tid >> 5, lane = tid & 31;
    const int bh = blockIdx.y;
    const int q0 = blockIdx.x * 128;
    const int warpM = wid * 16;
    const size_t qoff = ((size_t)bh * LQ_ + q0) * DQK_;
    const size_t koff = (size_t)bh * S_ * DQK_;

    {
        #pragma unroll
        for (int it = 0; it < 4; it++) {
            int e = it * 256 + tid;
            int row = e >> 3, seg = (e & 7) * 8;
            CP_ASYNC16(sb + FSTG + row * 144 + seg * 2, qh + qoff + (size_t)row * DQK_ + seg);
        }
        CP_COMMIT();
    }

    auto issueKV = [&](int tile, int stage) {
        int sk = tile * 64;
        uint32_t dst = sb + stage * FSTG;
        #pragma unroll
        for (int it = 0; it < 2; it++) {
            int e = it * 256 + tid;
            int row = e >> 3, seg = (e & 7) * 8;
            size_t g = koff + (size_t)(sk + row) * DQK_ + seg;
            uint32_t so = row * 144 + seg * 2;
            CP_ASYNC16(dst + so,        kh + g);
            CP_ASYNC16(dst + 9216 + so, vh + g);
        }
    };

    issueKV(0, 0); CP_COMMIT();
    CP_WAIT1(); __syncthreads();

    uint32_t Qf[4][4];
    #pragma unroll
    for (int kt = 0; kt < 4; kt++) {
        uint32_t ad = sb + FSTG + (warpM + (lane & 15)) * 144 + ((lane >> 4) << 4) + kt * 32;
        ldmA(Qf[kt], ad);
    }
    __syncthreads();
    issueKV(1, 1); CP_COMMIT();

    float acc[8][4];
    #pragma unroll
    for (int n = 0; n < 8; n++)
        #pragma unroll
        for (int c = 0; c < 4; c++) acc[n][c] = 0.0f;
    float m0 = -1e30f, m1 = -1e30f, l0 = 0.0f, l1 = 0.0f;

    for (int i = 0; i < S_ / 64; i++) {
        CP_WAIT1(); __syncthreads();
        const uint32_t kb = sb + (i & 1) * FSTG;

        float sc[8][4];
        #pragma unroll
        for (int n = 0; n < 8; n++)
            #pragma unroll
            for (int c = 0; c < 4; c++) sc[n][c] = 0.0f;

        #pragma unroll
        for (int kt = 0; kt < 4; kt++) {
            uint32_t Bh[4][4];
            #pragma unroll
            for (int p = 0; p < 4; p++) {
                uint32_t ad = kb + (p * 16 + (lane & 15)) * 144 + ((lane >> 4) << 4) + kt * 32;
                ldmA(Bh[p], ad);
            }
            #pragma unroll
            for (int ni = 0; ni < 8; ni++) {
                int g = ni >> 1, s = ni & 1;
                mma16816h(sc[ni], Qf[kt], Bh[g][s], Bh[g][s + 2]);
            }
        }

        float r0 = -1e30f, r1 = -1e30f;
        #pragma unroll
        for (int ni = 0; ni < 8; ni++) {
            r0 = fmaxf(r0, fmaxf(sc[ni][0], sc[ni][1]));
            r1 = fmaxf(r1, fmaxf(sc[ni][2], sc[ni][3]));
        }
        r0 = fmaxf(r0, __shfl_xor_sync(0xffffffffu, r0, 1));
        r0 = fmaxf(r0, __shfl_xor_sync(0xffffffffu, r0, 2));
        r1 = fmaxf(r1, __shfl_xor_sync(0xffffffffu, r1, 1));
        r1 = fmaxf(r1, __shfl_xor_sync(0xffffffffu, r1, 2));
        float mn0 = fmaxf(m0, r0), mn1 = fmaxf(m1, r1);
        float c0 = __expf(m0 - mn0), c1 = __expf(m1 - mn1);
        l0 *= c0; l1 *= c1;
        #pragma unroll
        for (int ni = 0; ni < 8; ni++) {
            acc[ni][0] *= c0; acc[ni][1] *= c0;
            acc[ni][2] *= c1; acc[ni][3] *= c1;
        }
        m0 = mn0; m1 = mn1;

        #pragma unroll
        for (int kt = 0; kt < 4; kt++) {
            uint32_t ph[4];
            #pragma unroll
            for (int j = 0; j < 2; j++) {
                int ni = 2 * kt + j;
                float p0 = __expf(sc[ni][0] - m0);
                float p1 = __expf(sc[ni][1] - m0);
                float p2 = __expf(sc[ni][2] - m1);
                float p3 = __expf(sc[ni][3] - m1);
                l0 += p0 + p1; l1 += p2 + p3;
                ph[2 * j]     = packhf(p0, p1);
                ph[2 * j + 1] = packhf(p2, p3);
            }
            uint32_t Vf[4][4];
            int grp = lane >> 3, rr = lane & 7;
            #pragma unroll
            for (int p = 0; p < 4; p++) {
                uint32_t ad = kb + 9216
                    + (kt * 16 + (grp & 1) * 8 + rr) * 144
                    + (p * 16 + (grp >> 1) * 8) * 2;
                ldmBT(Vf[p], ad);
            }
            #pragma unroll
            for (int nv = 0; nv < 8; nv++) {
                int g = nv >> 1, s = (nv & 1) * 2;
                mma16816h(acc[nv], ph, Vf[g][s], Vf[g][s + 1]);
            }
        }

        __syncthreads();
        if (i + 2 < S_ / 64) issueKV(i + 2, i & 1);
        CP_COMMIT();
    }

    l0 += __shfl_xor_sync(0xffffffffu, l0, 1);
    l0 += __shfl_xor_sync(0xffffffffu, l0, 2);
    l1 += __shfl_xor_sync(0xffffffffu, l1, 1);
    l1 += __shfl_xor_sync(0xffffffffu, l1, 2);
    float i0 = 1.0f / l0, i1 = 1.0f / l1;

    int b = bh >> 4, h = bh & 15;
    int row0 = q0 + warpM + (lane >> 2);
    size_t ob0 = (size_t)(b * LQ_ + row0) * (H_ * DQK_) + h * DQK_;
    size_t ob1 = ob0 + (size_t)8 * (H_ * DQK_);
    #pragma unroll
    for (int nv = 0; nv < 8; nv++) {
        int col = nv * 8 + (lane & 3) * 2;
        *(uint32_t*)(oh + ob0 + col) = packhf(acc[nv][0] * i0, acc[nv][1] * i0);
        *(uint32_t*)(oh + ob1 + col) = packhf(acc[nv][2] * i1, acc[nv][3] * i1);
    }
}

// ---------------- launch ----------------
extern "C" void kernel_launch(void* const* d_in, const int* in_sizes, int n_in,
                              void* d_out, int out_size)
{
    (void)in_sizes; (void)n_in; (void)out_size;
    const float* x      = (const float*)d_in[0];
    const float* norm_w = (const float*)d_in[1];
    const float* wq_w   = (const float*)d_in[2];
    const float* wq_b   = (const float*)d_in[3];
    const float* wkv_w  = (const float*)d_in[4];
    const float* wkv_b  = (const float*)d_in[5];
    const float* wout_w = (const float*)d_in[6];
    const float* wout_b = (const float*)d_in[7];
    const float* wbyp_w = (const float*)d_in[8];
    float* out = (float*)d_out;

    __half *nh, *wqh, *wkvh, *pqh, *pkh, *pvh, *x16, *at16, *wout16, *wbyp16;
    cudaGetSymbolAddress((void**)&nh,     g_nh);
    cudaGetSymbolAddress((void**)&wqh,    g_wqh);
    cudaGetSymbolAddress((void**)&wkvh,   g_wkvh);
    cudaGetSymbolAddress((void**)&pqh,    g_qh);
    cudaGetSymbolAddress((void**)&pkh,    g_kh);
    cudaGetSymbolAddress((void**)&pvh,    g_vh);
    cudaGetSymbolAddress((void**)&x16,    g_x16);
    cudaGetSymbolAddress((void**)&at16,   g_attn16);
    cudaGetSymbolAddress((void**)&wout16, g_wout16);
    cudaGetSymbolAddress((void**)&wbyp16, g_wbyp16);

    cudaFuncSetAttribute(flash_mma, cudaFuncAttributeMaxDynamicSharedMemorySize, FSMEM);
    cudaFuncSetAttribute(gemm_f16<1>, cudaFuncAttributeMaxDynamicSharedMemorySize, G1_SMEM);
    cudaFuncSetAttribute(gemm_f16<2>, cudaFuncAttributeMaxDynamicSharedMemorySize, G1_SMEM);
    cudaFuncSetAttribute(gemm_qproj,  cudaFuncAttributeMaxDynamicSharedMemorySize, G1_SMEM);
    cudaFuncSetAttribute(gemm_kvproj, cudaFuncAttributeMaxDynamicSharedMemorySize, G1_SMEM);

    // 1. RMSNorm -> single fp16
    rmsnorm_kernel<<<B_ * S_, 128>>>(x, norm_w, nh);

    // 2. operand conversions
    convh_kernel<<<(BPL_ * D_ * H_ * DQK_ / 4) / 256, 256>>>(wq_w, wqh, BPL_ * D_ * H_ * DQK_ / 4);
    convh_kernel<<<(D_ * 2 * H_ * DQK_ / 4) / 256, 256>>>(wkv_w, wkvh, D_ * 2 * H_ * DQK_ / 4);
    convh_kernel<<<(B_ * S_ * D_ / 4) / 256, 256>>>(x, x16, B_ * S_ * D_ / 4);
    convh_kernel<<<(H_ * DQK_ * DLAT_ / 4) / 256, 256>>>(wout_w, wout16, H_ * DQK_ * DLAT_ / 4);
    convh_kernel<<<(BPL_ * D_ * DLAT_ / 4) / 256, 256>>>(wbyp_w, wbyp16, BPL_ * D_ * DLAT_ / 4);

    // 3. Q projection + fused RoPE -> qh
    gemm_qproj<<<dim3((H_ * DQK_) / 128, (B_ * LQ_) / 128), 256, G1_SMEM>>>(
        nh, wqh, wq_b, pqh);

    // 4. KV projection + fused RoPE-K / transpose-V -> kh, vh
    gemm_kvproj<<<dim3((2 * H_ * DQK_) / 128, (B_ * S_) / 128), 256, G1_SMEM>>>(
        nh, wkvh, wkv_b, pkh, pvh);

    // 5. Flash attention -> attn fp16
    flash_mma<<<dim3(LQ_ / 128, B_ * H_), 256, FSMEM>>>(pqh, pkh, pvh, at16);

    // 6. Bypass GEMM -> out
    gemm_f16<1><<<dim3(DLAT_ / 128, (B_ * LQ_) / 128), 256, G1_SMEM>>>(
        B_ * LQ_, DLAT_, BPL_ * D_, x16, wbyp16, nullptr, out);

    // 7. Out projection (accumulate + bias)
    gemm_f16<2><<<dim3(DLAT_ / 128, (B_ * LQ_) / 128), 256, G1_SMEM>>>(
        B_ * LQ_, DLAT_, H_ * DQK_, at16, wout16, wout_b, out);
}

// round 14
// speedup vs baseline: 2.5057x; 1.0195x over previous
#include <cuda_runtime.h>
#include <cuda_bf16.h>
#include <cuda_fp16.h>
#include <math.h>
#include <stdint.h>

// ---------------- problem constants ----------------
#define B_   2
#define S_   4096
#define D_   512
#define BPL_ 4
#define H_   16
#define DQK_ 64
#define DLAT_ 1024
#define LQ_  (S_ / BPL_)          // 1024
#define EPS_ 1.1920929e-07f

// ---------------- scratch (device globals; no allocation allowed) ----------------
__device__ __half g_nh    [B_ * S_ * D_];
__device__ __half g_wqh   [BPL_ * D_ * H_ * DQK_];
__device__ __half g_wkvh  [D_ * 2 * H_ * DQK_];
__device__ __half g_qh    [B_ * H_ * LQ_ * DQK_];         // pre-scaled by 0.125
__device__ __half g_kh    [B_ * H_ * S_ * DQK_];
__device__ __half g_vh    [B_ * H_ * S_ * DQK_];
__device__ __half g_x16   [B_ * S_ * D_];
__device__ __half g_attn16[B_ * LQ_ * H_ * DQK_];
__device__ __half g_wout16[H_ * DQK_ * DLAT_];
__device__ __half g_wbyp16[BPL_ * D_ * DLAT_];

// ---------------- helpers ----------------
__device__ __forceinline__ uint32_t smem_to_u32(const void* p) {
    uint32_t a;
    asm("{ .reg .u64 t; cvta.to.shared.u64 t, %1; cvt.u32.u64 %0, t; }" : "=r"(a) : "l"(p));
    return a;
}

#define CP_ASYNC16(dst, src) \
    asm volatile("cp.async.cg.shared.global [%0], [%1], 16;" :: "r"(dst), "l"(src))
#define CP_COMMIT()  asm volatile("cp.async.commit_group;" ::: "memory")
#define CP_WAIT0()   asm volatile("cp.async.wait_group 0;" ::: "memory")
#define CP_WAIT1()   asm volatile("cp.async.wait_group 1;" ::: "memory")

__device__ __forceinline__ void ldmA(uint32_t* r, uint32_t addr) {
    asm volatile("ldmatrix.sync.aligned.m8n8.x4.shared.b16 {%0,%1,%2,%3}, [%4];"
                 : "=r"(r[0]), "=r"(r[1]), "=r"(r[2]), "=r"(r[3]) : "r"(addr));
}
__device__ __forceinline__ void ldmBT(uint32_t* r, uint32_t addr) {
    asm volatile("ldmatrix.sync.aligned.m8n8.x4.trans.shared.b16 {%0,%1,%2,%3}, [%4];"
                 : "=r"(r[0]), "=r"(r[1]), "=r"(r[2]), "=r"(r[3]) : "r"(addr));
}
__device__ __forceinline__ void mma16816h(float* d, const uint32_t* a, uint32_t b0, uint32_t b1) {
    asm volatile(
        "mma.sync.aligned.m16n8k16.row.col.f32.f16.f16.f32 "
        "{%0,%1,%2,%3}, {%4,%5,%6,%7}, {%8,%9}, {%0,%1,%2,%3};"
        : "+f"(d[0]), "+f"(d[1]), "+f"(d[2]), "+f"(d[3])
        : "r"(a[0]), "r"(a[1]), "r"(a[2]), "r"(a[3]), "r"(b0), "r"(b1));
}

__device__ __forceinline__ uint32_t packhf(float x, float y) {
    union { __half2 h; uint32_t u; } c;
    c.h = __halves2half2(__float2half(x), __float2half(y));
    return c.u;
}

__device__ __forceinline__ uint2 conv4h(float4 v) {
    union { __half2 h[2]; uint2 u; } c;
    c.h[0] = __halves2half2(__float2half(v.x), __float2half(v.y));
    c.h[1] = __halves2half2(__float2half(v.z), __float2half(v.w));
    return c.u;
}

__device__ __forceinline__ float inv_freq_f(int d)
{
    return (float)pow(10000.0, -(double)d / 32.0);
}

// ---------------- elementwise kernels ----------------
__global__ __launch_bounds__(256) void convh_kernel(
    const float* __restrict__ src, __half* __restrict__ dst, int n4)
{
    int i = blockIdx.x * blockDim.x + threadIdx.x;
    if (i >= n4) return;
    ((uint2*)dst)[i] = conv4h(((const float4*)src)[i]);
}

// RMSNorm -> nh (normalized fp16) AND x16 (raw x fp16)
__global__ __launch_bounds__(128) void rmsnorm_kernel(
    const float* __restrict__ x, const float* __restrict__ w,
    __half* __restrict__ outh, __half* __restrict__ xh)
{
    int row = blockIdx.x;
    const float4* xr = (const float4*)(x + (size_t)row * D_);
    const float4* wr = (const float4*)w;
    int tid = threadIdx.x;

    float4 v = xr[tid];
    ((uint2*)xh)[row * (D_ / 4) + tid] = conv4h(v);

    float s = v.x * v.x + v.y * v.y + v.z * v.z + v.w * v.w;
    #pragma unroll
    for (int o = 16; o > 0; o >>= 1) s += __shfl_xor_sync(0xffffffffu, s, o);
    __shared__ float red[4];
    int warp = tid >> 5, lane = tid & 31;
    if (lane == 0) red[warp] = s;
    __syncthreads();
    float total = red[0] + red[1] + red[2] + red[3];
    float inv = rsqrtf(total / (float)D_ + EPS_);
    float4 wv = wr[tid];
    float4 o4 = make_float4(v.x * inv * wv.x, v.y * inv * wv.y,
                            v.z * inv * wv.z, v.w * inv * wv.w);
    ((uint2*)outh)[row * (D_ / 4) + tid] = conv4h(o4);
}

// ---------------- shared GEMM mainloop ----------------
#define BKF  32
#define ASTR 40
#define BSTR 136
#define G1_A_B (128 * ASTR * 2)            // 10240
#define G1_B_B (BKF * BSTR * 2)            // 8704
#define G1_STG (G1_A_B + G1_B_B)           // 18944
#define G1_SMEM (2 * G1_STG)               // 37888

// Runs the full K loop, leaving results (+bias) in acc[2][8][4].
__device__ __forceinline__ void gemm_mainloop(
    uint32_t sBase, int N, int K,
    const __half* __restrict__ A, const __half* __restrict__ Bm,
    const float* __restrict__ bias,
    int mBase, int nBase, int warpM, int warpN, int tid, int lane,
    float acc[2][8][4])
{
    const int cpk = K / BKF;
    const int arow0 = tid >> 2, aseg = (tid & 3) * 8;
    const int brow0 = tid >> 4, bseg = (tid & 15) * 8;

    #pragma unroll
    for (int mi = 0; mi < 2; mi++)
        #pragma unroll
        for (int ni = 0; ni < 8; ni++)
            #pragma unroll
            for (int c = 0; c < 4; c++) acc[mi][ni][c] = 0.0f;

    auto issue = [&](int chunk) {
        int buf = chunk & 1;
        int k0 = chunk * BKF;
        uint32_t da = sBase + buf * G1_STG;
        uint32_t db = da + G1_A_B;
        const __half* aptr = A  + (size_t)mBase * K + k0 + aseg;
        const __half* bptr = Bm + (size_t)k0 * N + nBase + bseg;
        #pragma unroll
        for (int it = 0; it < 2; it++) {
            int row = arow0 + it * 64;
            CP_ASYNC16(da + row * (ASTR * 2) + aseg * 2, aptr + (size_t)row * K);
        }
        #pragma unroll
        for (int it = 0; it < 2; it++) {
            int row = brow0 + it * 16;
            CP_ASYNC16(db + row * (BSTR * 2) + bseg * 2, bptr + (size_t)row * N);
        }
        CP_COMMIT();
    };

    issue(0);

    for (int i = 0; i < cpk; i++) {
        if (i + 1 < cpk) { issue(i + 1); CP_WAIT1(); }
        else             { CP_WAIT0(); }
        __syncthreads();

        const uint32_t aBase = sBase + (i & 1) * G1_STG;
        const uint32_t bBase = aBase + G1_A_B;

        #pragma unroll
        for (int kk = 0; kk < 2; kk++) {
            uint32_t afrag[2][4];
            #pragma unroll
            for (int mi = 0; mi < 2; mi++) {
                uint32_t addr = aBase
                    + (warpM + mi * 16 + (lane & 15)) * (ASTR * 2)
                    + ((lane >> 4) << 4) + kk * 32;
                ldmA(afrag[mi], addr);
            }
            uint32_t bf[4][4];
            int grp = lane >> 3, r = lane & 7;
            #pragma unroll
            for (int p = 0; p < 4; p++) {
                uint32_t addr = bBase
                    + (kk * 16 + (grp & 1) * 8 + r) * (BSTR * 2)
                    + (warpN + p * 16 + (grp >> 1) * 8) * 2;
                ldmBT(bf[p], addr);
            }
            #pragma unroll
            for (int mi = 0; mi < 2; mi++)
                #pragma unroll
                for (int ni = 0; ni < 8; ni++) {
                    int g = ni >> 1, s = (ni & 1) * 2;
                    mma16816h(acc[mi][ni], afrag[mi], bf[g][s], bf[g][s + 1]);
                }
        }
        __syncthreads();
    }

    if (bias) {
        #pragma unroll
        for (int ni = 0; ni < 8; ni++) {
            int c = nBase + warpN + ni * 8 + (lane & 3) * 2;
            float2 bb = *(const float2*)(bias + c);
            #pragma unroll
            for (int mi = 0; mi < 2; mi++) {
                acc[mi][ni][0] += bb.x; acc[mi][ni][1] += bb.y;
                acc[mi][ni][2] += bb.x; acc[mi][ni][3] += bb.y;
            }
        }
    }
}

// ---------------- Q projection GEMM with fused RoPE epilogue ----------------
__global__ __launch_bounds__(256) void gemm_qproj(
    const __half* __restrict__ A, const __half* __restrict__ Bm,
    const float* __restrict__ bias, __half* __restrict__ qh)
{
    extern __shared__ char gsm[];
    const uint32_t sBase = smem_to_u32(gsm);
    const int tid = threadIdx.x;
    const int wid = tid >> 5, lane = tid & 31;
    const int mBase = blockIdx.y * 128;
    const int nBase = blockIdx.x * 128;
    const int warpM = (wid >> 1) * 32;
    const int warpN = (wid & 1) * 64;
    const int N = H_ * DQK_, K = BPL_ * D_;

    float acc[2][8][4];
    gemm_mainloop(sBase, N, K, A, Bm, bias, mBase, nBase, warpM, warpN, tid, lane, acc);

    const int hcol = (nBase + warpN) >> 6;

    #pragma unroll
    for (int mi = 0; mi < 2; mi++) {
        int r0 = mBase + warpM + mi * 16 + (lane >> 2);
        int r1 = r0 + 8;
        int qi0 = r0 & (LQ_ - 1), b0 = r0 >> 10;
        int qi1 = r1 & (LQ_ - 1), b1 = r1 >> 10;
        float pos0 = (float)(qi0 * BPL_), pos1 = (float)(qi1 * BPL_);
        size_t base0 = (((size_t)(b0 * H_ + hcol) * LQ_) + qi0) * DQK_;
        size_t base1 = (((size_t)(b1 * H_ + hcol) * LQ_) + qi1) * DQK_;
        #pragma unroll
        for (int ni = 0; ni < 4; ni++) {
            int d0 = ni * 8 + (lane & 3) * 2;
            float f0 = inv_freq_f(d0), f1 = inv_freq_f(d0 + 1);
            {
                float a0 = pos0 * f0, a1 = pos0 * f1;
                float c0 = cosf(a0), s0 = sinf(a0), c1 = cosf(a1), s1 = sinf(a1);
                float x1a = acc[mi][ni][0],     x1b = acc[mi][ni][1];
                float x2a = acc[mi][ni + 4][0], x2b = acc[mi][ni + 4][1];
                *(uint32_t*)(qh + base0 + d0) =
                    packhf((x1a * c0 - x2a * s0) * 0.125f, (x1b * c1 - x2b * s1) * 0.125f);
                *(uint32_t*)(qh + base0 + d0 + 32) =
                    packhf((x1a * s0 + x2a * c0) * 0.125f, (x1b * s1 + x2b * c1) * 0.125f);
            }
            {
                float a0 = pos1 * f0, a1 = pos1 * f1;
                float c0 = cosf(a0), s0 = sinf(a0), c1 = cosf(a1), s1 = sinf(a1);
                float x1a = acc[mi][ni][2],     x1b = acc[mi][ni][3];
                float x2a = acc[mi][ni + 4][2], x2b = acc[mi][ni + 4][3];
                *(uint32_t*)(qh + base1 + d0) =
                    packhf((x1a * c0 - x2a * s0) * 0.125f, (x1b * c1 - x2b * s1) * 0.125f);
                *(uint32_t*)(qh + base1 + d0 + 32) =
                    packhf((x1a * s0 + x2a * c0) * 0.125f, (x1b * s1 + x2b * c1) * 0.125f);
            }
        }
    }
}

// ---------------- KV projection GEMM with fused RoPE-K / transpose-V epilogue ----------------
__global__ __launch_bounds__(256) void gemm_kvproj(
    const __half* __restrict__ A, const __half* __restrict__ Bm,
    const float* __restrict__ bias,
    __half* __restrict__ kh, __half* __restrict__ vh)
{
    extern __shared__ char gsm[];
    const uint32_t sBase = smem_to_u32(gsm);
    const int tid = threadIdx.x;
    const int wid = tid >> 5, lane = tid & 31;
    const int mBase = blockIdx.y * 128;
    const int nBase = blockIdx.x * 128;
    const int warpM = (wid >> 1) * 32;
    const int warpN = (wid & 1) * 64;
    const int N = 2 * H_ * DQK_, K = D_;

    float acc[2][8][4];
    gemm_mainloop(sBase, N, K, A, Bm, bias, mBase, nBase, warpM, warpN, tid, lane, acc);

    const int colBase = nBase + warpN;
    const bool isK = colBase < H_ * DQK_;
    const int hcol = (colBase & (H_ * DQK_ - 1)) >> 6;

    #pragma unroll
    for (int mi = 0; mi < 2; mi++) {
        int r0 = mBase + warpM + mi * 16 + (lane >> 2);
        int r1 = r0 + 8;
        int s0 = r0 & (S_ - 1), b0 = r0 >> 12;
        int s1 = r1 & (S_ - 1), b1 = r1 >> 12;
        size_t base0 = (((size_t)(b0 * H_ + hcol) * S_) + s0) * DQK_;
        size_t base1 = (((size_t)(b1 * H_ + hcol) * S_) + s1) * DQK_;

        if (isK) {
            float pos0 = (float)s0, pos1 = (float)s1;
            #pragma unroll
            for (int ni = 0; ni < 4; ni++) {
                int d0 = ni * 8 + (lane & 3) * 2;
                float f0 = inv_freq_f(d0), f1 = inv_freq_f(d0 + 1);
                {
                    float a0 = pos0 * f0, a1 = pos0 * f1;
                    float c0 = cosf(a0), sn0 = sinf(a0), c1 = cosf(a1), sn1 = sinf(a1);
                    float x1a = acc[mi][ni][0],     x1b = acc[mi][ni][1];
                    float x2a = acc[mi][ni + 4][0], x2b = acc[mi][ni + 4][1];
                    *(uint32_t*)(kh + base0 + d0) =
                        packhf(x1a * c0 - x2a * sn0, x1b * c1 - x2b * sn1);
                    *(uint32_t*)(kh + base0 + d0 + 32) =
                        packhf(x1a * sn0 + x2a * c0, x1b * sn1 + x2b * c1);
                }
                {
                    float a0 = pos1 * f0, a1 = pos1 * f1;
                    float c0 = cosf(a0), sn0 = sinf(a0), c1 = cosf(a1), sn1 = sinf(a1);
                    float x1a = acc[mi][ni][2],     x1b = acc[mi][ni][3];
                    float x2a = acc[mi][ni + 4][2], x2b = acc[mi][ni + 4][3];
                    *(uint32_t*)(kh + base1 + d0) =
                        packhf(x1a * c0 - x2a * sn0, x1b * c1 - x2b * sn1);
                    *(uint32_t*)(kh + base1 + d0 + 32) =
                        packhf(x1a * sn0 + x2a * c0, x1b * sn1 + x2b * c1);
                }
            }
        } else {
            #pragma unroll
            for (int ni = 0; ni < 8; ni++) {
                int d0 = ni * 8 + (lane & 3) * 2;
                *(uint32_t*)(vh + base0 + d0) = packhf(acc[mi][ni][0], acc[mi][ni][1]);
                *(uint32_t*)(vh + base1 + d0) = packhf(acc[mi][ni][2], acc[mi][ni][3]);
            }
        }
    }
}

// ---------------- fused final GEMM: out = x16@wbyp + attn16@wout + wout_b ----------------
// K = 3072 split at 2048 (chunk-aligned). One fp32 accumulation chain.
__global__ __launch_bounds__(256) void gemm_final(
    const __half* __restrict__ Ax,   // x16 [2048, 2048]
    const __half* __restrict__ Aat,  // attn16 [2048, 1024]
    const __half* __restrict__ Bbyp, // [2048, 1024]
    const __half* __restrict__ Bout, // [1024, 1024]
    const float* __restrict__ bias, float* __restrict__ C)
{
    extern __shared__ char gsm[];
    const uint32_t sBase = smem_to_u32(gsm);
    const int tid = threadIdx.x;
    const int wid = tid >> 5, lane = tid & 31;
    const int mBase = blockIdx.y * 128;
    const int nBase = blockIdx.x * 128;
    const int warpM = (wid >> 1) * 32;
    const int warpN = (wid & 1) * 64;

    const int N  = DLAT_;           // 1024
    const int KA = BPL_ * D_;       // 2048 (segment boundary)
    const int KT = KA + H_ * DQK_;  // 3072
    const int cpk = KT / BKF;       // 96

    const int arow0 = tid >> 2, aseg = (tid & 3) * 8;
    const int brow0 = tid >> 4, bseg = (tid & 15) * 8;

    float acc[2][8][4];
    #pragma unroll
    for (int mi = 0; mi < 2; mi++)
        #pragma unroll
        for (int ni = 0; ni < 8; ni++)
            #pragma unroll
            for (int c = 0; c < 4; c++) acc[mi][ni][c] = 0.0f;

    auto issue = [&](int chunk) {
        int buf = chunk & 1;
        int k0 = chunk * BKF;
        uint32_t da = sBase + buf * G1_STG;
        uint32_t db = da + G1_A_B;
        const __half* aptr;
        size_t astr;
        const __half* bptr;
        if (k0 < KA) {
            aptr = Ax + (size_t)mBase * KA + k0 + aseg;
            astr = KA;
            bptr = Bbyp + (size_t)k0 * N + nBase + bseg;
        } else {
            int k1 = k0 - KA;
            aptr = Aat + (size_t)mBase * (H_ * DQK_) + k1 + aseg;
            astr = H_ * DQK_;
            bptr = Bout + (size_t)k1 * N + nBase + bseg;
        }
        #pragma unroll
        for (int it = 0; it < 2; it++) {
            int row = arow0 + it * 64;
            CP_ASYNC16(da + row * (ASTR * 2) + aseg * 2, aptr + (size_t)row * astr);
        }
        #pragma unroll
        for (int it = 0; it < 2; it++) {
            int row = brow0 + it * 16;
            CP_ASYNC16(db + row * (BSTR * 2) + bseg * 2, bptr + (size_t)row * N);
        }
        CP_COMMIT();
    };

    issue(0);

    for (int i = 0; i < cpk; i++) {
        if (i + 1 < cpk) { issue(i + 1); CP_WAIT1(); }
        else             { CP_WAIT0(); }
        __syncthreads();

        const uint32_t aBase = sBase + (i & 1) * G1_STG;
        const uint32_t bBase = aBase + G1_A_B;

        #pragma unroll
        for (int kk = 0; kk < 2; kk++) {
            uint32_t afrag[2][4];
            #pragma unroll
            for (int mi = 0; mi < 2; mi++) {
                uint32_t addr = aBase
                    + (warpM + mi * 16 + (lane & 15)) * (ASTR * 2)
                    + ((lane >> 4) << 4) + kk * 32;
                ldmA(afrag[mi], addr);
            }
            uint32_t bf[4][4];
            int grp = lane >> 3, r = lane & 7;
            #pragma unroll
            for (int p = 0; p < 4; p++) {
                uint32_t addr = bBase
                    + (kk * 16 + (grp & 1) * 8 + r) * (BSTR * 2)
                    + (warpN + p * 16 + (grp >> 1) * 8) * 2;
                ldmBT(bf[p], addr);
            }
            #pragma unroll
            for (int mi = 0; mi < 2; mi++)
                #pragma unroll
                for (int ni = 0; ni < 8; ni++) {
                    int g = ni >> 1, s = (ni & 1) * 2;
                    mma16816h(acc[mi][ni], afrag[mi], bf[g][s], bf[g][s + 1]);
                }
        }
        __syncthreads();
    }

    #pragma unroll
    for (int mi = 0; mi < 2; mi++) {
        #pragma unroll
        for (int ni = 0; ni < 8; ni++) {
            int r0 = mBase + warpM + mi * 16 + (lane >> 2);
            int c  = nBase + warpN + ni * 8 + (lane & 3) * 2;
            float2 bb = *(const float2*)(bias + c);
            float2 v0 = make_float2(acc[mi][ni][0] + bb.x, acc[mi][ni][1] + bb.y);
            float2 v1 = make_float2(acc[mi][ni][2] + bb.x, acc[mi][ni][3] + bb.y);
            *(float2*)(C + (size_t)r0 * N + c) = v0;
            *(float2*)(C + (size_t)(r0 + 8) * N + c) = v1;
        }
    }
}

// ---------------- flash attention via fp16 mma (single-term) ----------------
#define FSTG 18432
#define FSMEM (2 * FSTG)

__global__ __launch_bounds__(256) void flash_mma(
    const __half* __restrict__ qh,
    const __half* __restrict__ kh, const __half* __restrict__ vh,
    __half* __restrict__ oh)
{
    extern __shared__ char sm[];
    const uint32_t sb = smem_to_u32(sm);
    const int tid = threadIdx.x, wid = tid >> 5, lane = tid & 31;
    const int bh = blockIdx.y;
    const int q0 = blockIdx.x * 128;
    const int warpM = wid * 16;
    const size_t qoff = ((size_t)bh * LQ_ + q0) * DQK_;
    const size_t koff = (size_t)bh * S_ * DQK_;

    {
        #pragma unroll
        for (int it = 0; it < 4; it++) {
            int e = it * 256 + tid;
            int row = e >> 3, seg = (e & 7) * 8;
            CP_ASYNC16(sb + FSTG + row * 144 + seg * 2, qh + qoff + (size_t)row * DQK_ + seg);
        }
        CP_COMMIT();
    }

    auto issueKV = [&](int tile, int stage) {
        int sk = tile * 64;
        uint32_t dst = sb + stage * FSTG;
        #pragma unroll
        for (int it = 0; it < 2; it++) {
            int e = it * 256 + tid;
            int row = e >> 3, seg = (e & 7) * 8;
            size_t g = koff + (size_t)(sk + row) * DQK_ + seg;
            uint32_t so = row * 144 + seg * 2;
            CP_ASYNC16(dst + so,        kh + g);
            CP_ASYNC16(dst + 9216 + so, vh + g);
        }
    };

    issueKV(0, 0); CP_COMMIT();
    CP_WAIT1(); __syncthreads();

    uint32_t Qf[4][4];
    #pragma unroll
    for (int kt = 0; kt < 4; kt++) {
        uint32_t ad = sb + FSTG + (warpM + (lane & 15)) * 144 + ((lane >> 4) << 4) + kt * 32;
        ldmA(Qf[kt], ad);
    }
    __syncthreads();
    issueKV(1, 1); CP_COMMIT();

    float acc[8][4];
    #pragma unroll
    for (int n = 0; n < 8; n++)
        #pragma unroll
        for (int c = 0; c < 4; c++) acc[n][c] = 0.0f;
    float m0 = -1e30f, m1 = -1e30f, l0 = 0.0f, l1 = 0.0f;

    for (int i = 0; i < S_ / 64; i++) {
        CP_WAIT1(); __syncthreads();
        const uint32_t kb = sb + (i & 1) * FSTG;

        float sc[8][4];
        #pragma unroll
        for (int n = 0; n < 8; n++)
            #pragma unroll
            for (int c = 0; c < 4; c++) sc[n][c] = 0.0f;

        #pragma unroll
        for (int kt = 0; kt < 4; kt++) {
            uint32_t Bh[4][4];
            #pragma unroll
            for (int p = 0; p < 4; p++) {
                uint32_t ad = kb + (p * 16 + (lane & 15)) * 144 + ((lane >> 4) << 4) + kt * 32;
                ldmA(Bh[p], ad);
            }
            #pragma unroll
            for (int ni = 0; ni < 8; ni++) {
                int g = ni >> 1, s = ni & 1;
                mma16816h(sc[ni], Qf[kt], Bh[g][s], Bh[g][s + 2]);
            }
        }

        float r0 = -1e30f, r1 = -1e30f;
        #pragma unroll
        for (int ni = 0; ni < 8; ni++) {
            r0 = fmaxf(r0, fmaxf(sc[ni][0], sc[ni][1]));
            r1 = fmaxf(r1, fmaxf(sc[ni][2], sc[ni][3]));
        }
        r0 = fmaxf(r0, __shfl_xor_sync(0xffffffffu, r0, 1));
        r0 = fmaxf(r0, __shfl_xor_sync(0xffffffffu, r0, 2));
        r1 = fmaxf(r1, __shfl_xor_sync(0xffffffffu, r1, 1));
        r1 = fmaxf(r1, __shfl_xor_sync(0xffffffffu, r1, 2));
        float mn0 = fmaxf(m0, r0), mn1 = fmaxf(m1, r1);
        float c0 = __expf(m0 - mn0), c1 = __expf(m1 - mn1);
        l0 *= c0; l1 *= c1;
        #pragma unroll
        for (int ni = 0; ni < 8; ni++) {
            acc[ni][0] *= c0; acc[ni][1] *= c0;
            acc[ni][2] *= c1; acc[ni][3] *= c1;
        }
        m0 = mn0; m1 = mn1;

        #pragma unroll
        for (int kt = 0; kt < 4; kt++) {
            uint32_t ph[4];
            #pragma unroll
            for (int j = 0; j < 2; j++) {
                int ni = 2 * kt + j;
                float p0 = __expf(sc[ni][0] - m0);
                float p1 = __expf(sc[ni][1] - m0);
                float p2 = __expf(sc[ni][2] - m1);
                float p3 = __expf(sc[ni][3] - m1);
                l0 += p0 + p1; l1 += p2 + p3;
                ph[2 * j]     = packhf(p0, p1);
                ph[2 * j + 1] = packhf(p2, p3);
            }
            uint32_t Vf[4][4];
            int grp = lane >> 3, rr = lane & 7;
            #pragma unroll
            for (int p = 0; p < 4; p++) {
                uint32_t ad = kb + 9216
                    + (kt * 16 + (grp & 1) * 8 + rr) * 144
                    + (p * 16 + (grp >> 1) * 8) * 2;
                ldmBT(Vf[p], ad);
            }
            #pragma unroll
            for (int nv = 0; nv < 8; nv++) {
                int g = nv >> 1, s = (nv & 1) * 2;
                mma16816h(acc[nv], ph, Vf[g][s], Vf[g][s + 1]);
            }
        }

        __syncthreads();
        if (i + 2 < S_ / 64) issueKV(i + 2, i & 1);
        CP_COMMIT();
    }

    l0 += __shfl_xor_sync(0xffffffffu, l0, 1);
    l0 += __shfl_xor_sync(0xffffffffu, l0, 2);
    l1 += __shfl_xor_sync(0xffffffffu, l1, 1);
    l1 += __shfl_xor_sync(0xffffffffu, l1, 2);
    float i0 = 1.0f / l0, i1 = 1.0f / l1;

    int b = bh >> 4, h = bh & 15;
    int row0 = q0 + warpM + (lane >> 2);
    size_t ob0 = (size_t)(b * LQ_ + row0) * (H_ * DQK_) + h * DQK_;
    size_t ob1 = ob0 + (size_t)8 * (H_ * DQK_);
    #pragma unroll
    for (int nv = 0; nv < 8; nv++) {
        int col = nv * 8 + (lane & 3) * 2;
        *(uint32_t*)(oh + ob0 + col) = packhf(acc[nv][0] * i0, acc[nv][1] * i0);
        *(uint32_t*)(oh + ob1 + col) = packhf(acc[nv][2] * i1, acc[nv][3] * i1);
    }
}

// ---------------- launch ----------------
extern "C" void kernel_launch(void* const* d_in, const int* in_sizes, int n_in,
                              void* d_out, int out_size)
{
    (void)in_sizes; (void)n_in; (void)out_size;
    const float* x      = (const float*)d_in[0];
    const float* norm_w = (const float*)d_in[1];
    const float* wq_w   = (const float*)d_in[2];
    const float* wq_b   = (const float*)d_in[3];
    const float* wkv_w  = (const float*)d_in[4];
    const float* wkv_b  = (const float*)d_in[5];
    const float* wout_w = (const float*)d_in[6];
    const float* wout_b = (const float*)d_in[7];
    const float* wbyp_w = (const float*)d_in[8];
    float* out = (float*)d_out;

    __half *nh, *wqh, *wkvh, *pqh, *pkh, *pvh, *x16, *at16, *wout16, *wbyp16;
    cudaGetSymbolAddress((void**)&nh,     g_nh);
    cudaGetSymbolAddress((void**)&wqh,    g_wqh);
    cudaGetSymbolAddress((void**)&wkvh,   g_wkvh);
    cudaGetSymbolAddress((void**)&pqh,    g_qh);
    cudaGetSymbolAddress((void**)&pkh,    g_kh);
    cudaGetSymbolAddress((void**)&pvh,    g_vh);
    cudaGetSymbolAddress((void**)&x16,    g_x16);
    cudaGetSymbolAddress((void**)&at16,   g_attn16);
    cudaGetSymbolAddress((void**)&wout16, g_wout16);
    cudaGetSymbolAddress((void**)&wbyp16, g_wbyp16);

    cudaFuncSetAttribute(flash_mma,   cudaFuncAttributeMaxDynamicSharedMemorySize, FSMEM);
    cudaFuncSetAttribute(gemm_qproj,  cudaFuncAttributeMaxDynamicSharedMemorySize, G1_SMEM);
    cudaFuncSetAttribute(gemm_kvproj, cudaFuncAttributeMaxDynamicSharedMemorySize, G1_SMEM);
    cudaFuncSetAttribute(gemm_final,  cudaFuncAttributeMaxDynamicSharedMemorySize, G1_SMEM);

    // 1. RMSNorm -> nh (fp16) + x16 (fp16)
    rmsnorm_kernel<<<B_ * S_, 128>>>(x, norm_w, nh, x16);

    // 2. weight conversions
    convh_kernel<<<(BPL_ * D_ * H_ * DQK_ / 4) / 256, 256>>>(wq_w, wqh, BPL_ * D_ * H_ * DQK_ / 4);
    convh_kernel<<<(D_ * 2 * H_ * DQK_ / 4) / 256, 256>>>(wkv_w, wkvh, D_ * 2 * H_ * DQK_ / 4);
    convh_kernel<<<(H_ * DQK_ * DLAT_ / 4) / 256, 256>>>(wout_w, wout16, H_ * DQK_ * DLAT_ / 4);
    convh_kernel<<<(BPL_ * D_ * DLAT_ / 4) / 256, 256>>>(wbyp_w, wbyp16, BPL_ * D_ * DLAT_ / 4);

    // 3. Q projection + fused RoPE -> qh
    gemm_qproj<<<dim3((H_ * DQK_) / 128, (B_ * LQ_) / 128), 256, G1_SMEM>>>(
        nh, wqh, wq_b, pqh);

    // 4. KV projection + fused RoPE-K / transpose-V -> kh, vh
    gemm_kvproj<<<dim3((2 * H_ * DQK_) / 128, (B_ * S_) / 128), 256, G1_SMEM>>>(
        nh, wkvh, wkv_b, pkh, pvh);

    // 5. Flash attention -> attn fp16
    flash_mma<<<dim3(LQ_ / 128, B_ * H_), 256, FSMEM>>>(pqh, pkh, pvh, at16);

    // 6. Fused final GEMM: out = x16@wbyp + attn16@wout + wout_b
    gemm_final<<<dim3(DLAT_ / 128, (B_ * LQ_) / 128), 256, G1_SMEM>>>(
        x16, at16, wbyp16, wout16, wout_b, out);
}

// round 15
// speedup vs baseline: 2.6108x; 1.0420x over previous
#include <cuda_runtime.h>
#include <cuda_bf16.h>
#include <cuda_fp16.h>
#include <math.h>
#include <stdint.h>

// ---------------- problem constants ----------------
#define B_   2
#define S_   4096
#define D_   512
#define BPL_ 4
#define H_   16
#define DQK_ 64
#define DLAT_ 1024
#define LQ_  (S_ / BPL_)          // 1024
#define EPS_ 1.1920929e-07f

// ---------------- scratch (device globals; no allocation allowed) ----------------
__device__ __half g_nh    [B_ * S_ * D_];
__device__ __half g_wqh   [BPL_ * D_ * H_ * DQK_];
__device__ __half g_wkvh  [D_ * 2 * H_ * DQK_];
__device__ __half g_qh    [B_ * H_ * LQ_ * DQK_];         // pre-scaled by 0.125
__device__ __half g_kh    [B_ * H_ * S_ * DQK_];
__device__ __half g_vh    [B_ * H_ * S_ * DQK_];
__device__ __half g_x16   [B_ * S_ * D_];
__device__ __half g_attn16[B_ * LQ_ * H_ * DQK_];
__device__ __half g_wout16[H_ * DQK_ * DLAT_];
__device__ __half g_wbyp16[BPL_ * D_ * DLAT_];

// ---------------- helpers ----------------
__device__ __forceinline__ uint32_t smem_to_u32(const void* p) {
    uint32_t a;
    asm("{ .reg .u64 t; cvta.to.shared.u64 t, %1; cvt.u32.u64 %0, t; }" : "=r"(a) : "l"(p));
    return a;
}

#define CP_ASYNC16(dst, src) \
    asm volatile("cp.async.cg.shared.global [%0], [%1], 16;" :: "r"(dst), "l"(src))
#define CP_COMMIT()  asm volatile("cp.async.commit_group;" ::: "memory")
#define CP_WAIT0()   asm volatile("cp.async.wait_group 0;" ::: "memory")
#define CP_WAIT1()   asm volatile("cp.async.wait_group 1;" ::: "memory")

__device__ __forceinline__ void ldmA(uint32_t* r, uint32_t addr) {
    asm volatile("ldmatrix.sync.aligned.m8n8.x4.shared.b16 {%0,%1,%2,%3}, [%4];"
                 : "=r"(r[0]), "=r"(r[1]), "=r"(r[2]), "=r"(r[3]) : "r"(addr));
}
__device__ __forceinline__ void ldmBT(uint32_t* r, uint32_t addr) {
    asm volatile("ldmatrix.sync.aligned.m8n8.x4.trans.shared.b16 {%0,%1,%2,%3}, [%4];"
                 : "=r"(r[0]), "=r"(r[1]), "=r"(r[2]), "=r"(r[3]) : "r"(addr));
}
__device__ __forceinline__ void mma16816h(float* d, const uint32_t* a, uint32_t b0, uint32_t b1) {
    asm volatile(
        "mma.sync.aligned.m16n8k16.row.col.f32.f16.f16.f32 "
        "{%0,%1,%2,%3}, {%4,%5,%6,%7}, {%8,%9}, {%0,%1,%2,%3};"
        : "+f"(d[0]), "+f"(d[1]), "+f"(d[2]), "+f"(d[3])
        : "r"(a[0]), "r"(a[1]), "r"(a[2]), "r"(a[3]), "r"(b0), "r"(b1));
}

__device__ __forceinline__ uint32_t packhf(float x, float y) {
    union { __half2 h; uint32_t u; } c;
    c.h = __halves2half2(__float2half(x), __float2half(y));
    return c.u;
}

__device__ __forceinline__ uint2 conv4h(float4 v) {
    union { __half2 h[2]; uint2 u; } c;
    c.h[0] = __halves2half2(__float2half(v.x), __float2half(v.y));
    c.h[1] = __halves2half2(__float2half(v.z), __float2half(v.w));
    return c.u;
}

__device__ __forceinline__ float inv_freq_f(int d)
{
    return (float)pow(10000.0, -(double)d / 32.0);
}

// ---------------- elementwise kernels ----------------
// Single kernel converting all 4 weight tensors (segments in float4 units).
#define WQ4   (BPL_ * D_ * H_ * DQK_ / 4)     // 524288
#define WKV4  (D_ * 2 * H_ * DQK_ / 4)        // 262144
#define WOUT4 (H_ * DQK_ * DLAT_ / 4)         // 262144
#define WBYP4 (BPL_ * D_ * DLAT_ / 4)         // 524288
#define WTOT4 (WQ4 + WKV4 + WOUT4 + WBYP4)    // 1572864

__global__ __launch_bounds__(256) void convw_kernel(
    const float* __restrict__ wq, const float* __restrict__ wkv,
    const float* __restrict__ wout, const float* __restrict__ wbyp,
    __half* __restrict__ wqh, __half* __restrict__ wkvh,
    __half* __restrict__ wouth, __half* __restrict__ wbyph)
{
    int i = blockIdx.x * blockDim.x + threadIdx.x;
    if (i >= WTOT4) return;
    const float* src;
    __half* dst;
    int j = i;
    if (j < WQ4)                       { src = wq;   dst = wqh; }
    else if ((j -= WQ4) < WKV4)        { src = wkv;  dst = wkvh; }
    else if ((j -= WKV4) < WOUT4)      { src = wout; dst = wouth; }
    else { j -= WOUT4;                   src = wbyp; dst = wbyph; }
    ((uint2*)dst)[j] = conv4h(((const float4*)src)[j]);
}

// RMSNorm -> nh (normalized fp16) AND x16 (raw x fp16)
__global__ __launch_bounds__(128) void rmsnorm_kernel(
    const float* __restrict__ x, const float* __restrict__ w,
    __half* __restrict__ outh, __half* __restrict__ xh)
{
    int row = blockIdx.x;
    const float4* xr = (const float4*)(x + (size_t)row * D_);
    const float4* wr = (const float4*)w;
    int tid = threadIdx.x;

    float4 v = xr[tid];
    ((uint2*)xh)[row * (D_ / 4) + tid] = conv4h(v);

    float s = v.x * v.x + v.y * v.y + v.z * v.z + v.w * v.w;
    #pragma unroll
    for (int o = 16; o > 0; o >>= 1) s += __shfl_xor_sync(0xffffffffu, s, o);
    __shared__ float red[4];
    int warp = tid >> 5, lane = tid & 31;
    if (lane == 0) red[warp] = s;
    __syncthreads();
    float total = red[0] + red[1] + red[2] + red[3];
    float inv = rsqrtf(total / (float)D_ + EPS_);
    float4 wv = wr[tid];
    float4 o4 = make_float4(v.x * inv * wv.x, v.y * inv * wv.y,
                            v.z * inv * wv.z, v.w * inv * wv.w);
    ((uint2*)outh)[row * (D_ / 4) + tid] = conv4h(o4);
}

// ---------------- shared GEMM mainloop ----------------
#define BKF  32
#define ASTR 40
#define BSTR 136
#define G1_A_B (128 * ASTR * 2)            // 10240
#define G1_B_B (BKF * BSTR * 2)            // 8704
#define G1_STG (G1_A_B + G1_B_B)           // 18944
#define G1_SMEM (2 * G1_STG)               // 37888

__device__ __forceinline__ void gemm_mainloop(
    uint32_t sBase, int N, int K,
    const __half* __restrict__ A, const __half* __restrict__ Bm,
    const float* __restrict__ bias,
    int mBase, int nBase, int warpM, int warpN, int tid, int lane,
    float acc[2][8][4])
{
    const int cpk = K / BKF;
    const int arow0 = tid >> 2, aseg = (tid & 3) * 8;
    const int brow0 = tid >> 4, bseg = (tid & 15) * 8;

    #pragma unroll
    for (int mi = 0; mi < 2; mi++)
        #pragma unroll
        for (int ni = 0; ni < 8; ni++)
            #pragma unroll
            for (int c = 0; c < 4; c++) acc[mi][ni][c] = 0.0f;

    auto issue = [&](int chunk) {
        int buf = chunk & 1;
        int k0 = chunk * BKF;
        uint32_t da = sBase + buf * G1_STG;
        uint32_t db = da + G1_A_B;
        const __half* aptr = A  + (size_t)mBase * K + k0 + aseg;
        const __half* bptr = Bm + (size_t)k0 * N + nBase + bseg;
        #pragma unroll
        for (int it = 0; it < 2; it++) {
            int row = arow0 + it * 64;
            CP_ASYNC16(da + row * (ASTR * 2) + aseg * 2, aptr + (size_t)row * K);
        }
        #pragma unroll
        for (int it = 0; it < 2; it++) {
            int row = brow0 + it * 16;
            CP_ASYNC16(db + row * (BSTR * 2) + bseg * 2, bptr + (size_t)row * N);
        }
        CP_COMMIT();
    };

    issue(0);

    for (int i = 0; i < cpk; i++) {
        if (i + 1 < cpk) { issue(i + 1); CP_WAIT1(); }
        else             { CP_WAIT0(); }
        __syncthreads();

        const uint32_t aBase = sBase + (i & 1) * G1_STG;
        const uint32_t bBase = aBase + G1_A_B;

        #pragma unroll
        for (int kk = 0; kk < 2; kk++) {
            uint32_t afrag[2][4];
            #pragma unroll
            for (int mi = 0; mi < 2; mi++) {
                uint32_t addr = aBase
                    + (warpM + mi * 16 + (lane & 15)) * (ASTR * 2)
                    + ((lane >> 4) << 4) + kk * 32;
                ldmA(afrag[mi], addr);
            }
            uint32_t bf[4][4];
            int grp = lane >> 3, r = lane & 7;
            #pragma unroll
            for (int p = 0; p < 4; p++) {
                uint32_t addr = bBase
                    + (kk * 16 + (grp & 1) * 8 + r) * (BSTR * 2)
                    + (warpN + p * 16 + (grp >> 1) * 8) * 2;
                ldmBT(bf[p], addr);
            }
            #pragma unroll
            for (int mi = 0; mi < 2; mi++)
                #pragma unroll
                for (int ni = 0; ni < 8; ni++) {
                    int g = ni >> 1, s = (ni & 1) * 2;
                    mma16816h(acc[mi][ni], afrag[mi], bf[g][s], bf[g][s + 1]);
                }
        }
        __syncthreads();
    }

    if (bias) {
        #pragma unroll
        for (int ni = 0; ni < 8; ni++) {
            int c = nBase + warpN + ni * 8 + (lane & 3) * 2;
            float2 bb = *(const float2*)(bias + c);
            #pragma unroll
            for (int mi = 0; mi < 2; mi++) {
                acc[mi][ni][0] += bb.x; acc[mi][ni][1] += bb.y;
                acc[mi][ni][2] += bb.x; acc[mi][ni][3] += bb.y;
            }
        }
    }
}

// ---------------- Q projection GEMM with fused RoPE epilogue ----------------
__global__ __launch_bounds__(256) void gemm_qproj(
    const __half* __restrict__ A, const __half* __restrict__ Bm,
    const float* __restrict__ bias, __half* __restrict__ qh)
{
    extern __shared__ char gsm[];
    const uint32_t sBase = smem_to_u32(gsm);
    const int tid = threadIdx.x;
    const int wid = tid >> 5, lane = tid & 31;
    const int mBase = blockIdx.y * 128;
    const int nBase = blockIdx.x * 128;
    const int warpM = (wid >> 1) * 32;
    const int warpN = (wid & 1) * 64;
    const int N = H_ * DQK_, K = BPL_ * D_;

    float acc[2][8][4];
    gemm_mainloop(sBase, N, K, A, Bm, bias, mBase, nBase, warpM, warpN, tid, lane, acc);

    const int hcol = (nBase + warpN) >> 6;

    #pragma unroll
    for (int mi = 0; mi < 2; mi++) {
        int r0 = mBase + warpM + mi * 16 + (lane >> 2);
        int r1 = r0 + 8;
        int qi0 = r0 & (LQ_ - 1), b0 = r0 >> 10;
        int qi1 = r1 & (LQ_ - 1), b1 = r1 >> 10;
        float pos0 = (float)(qi0 * BPL_), pos1 = (float)(qi1 * BPL_);
        size_t base0 = (((size_t)(b0 * H_ + hcol) * LQ_) + qi0) * DQK_;
        size_t base1 = (((size_t)(b1 * H_ + hcol) * LQ_) + qi1) * DQK_;
        #pragma unroll
        for (int ni = 0; ni < 4; ni++) {
            int d0 = ni * 8 + (lane & 3) * 2;
            float f0 = inv_freq_f(d0), f1 = inv_freq_f(d0 + 1);
            {
                float a0 = pos0 * f0, a1 = pos0 * f1;
                float c0 = cosf(a0), s0 = sinf(a0), c1 = cosf(a1), s1 = sinf(a1);
                float x1a = acc[mi][ni][0],     x1b = acc[mi][ni][1];
                float x2a = acc[mi][ni + 4][0], x2b = acc[mi][ni + 4][1];
                *(uint32_t*)(qh + base0 + d0) =
                    packhf((x1a * c0 - x2a * s0) * 0.125f, (x1b * c1 - x2b * s1) * 0.125f);
                *(uint32_t*)(qh + base0 + d0 + 32) =
                    packhf((x1a * s0 + x2a * c0) * 0.125f, (x1b * s1 + x2b * c1) * 0.125f);
            }
            {
                float a0 = pos1 * f0, a1 = pos1 * f1;
                float c0 = cosf(a0), s0 = sinf(a0), c1 = cosf(a1), s1 = sinf(a1);
                float x1a = acc[mi][ni][2],     x1b = acc[mi][ni][3];
                float x2a = acc[mi][ni + 4][2], x2b = acc[mi][ni + 4][3];
                *(uint32_t*)(qh + base1 + d0) =
                    packhf((x1a * c0 - x2a * s0) * 0.125f, (x1b * c1 - x2b * s1) * 0.125f);
                *(uint32_t*)(qh + base1 + d0 + 32) =
                    packhf((x1a * s0 + x2a * c0) * 0.125f, (x1b * s1 + x2b * c1) * 0.125f);
            }
        }
    }
}

// ---------------- KV projection GEMM with fused RoPE-K / transpose-V epilogue ----------------
__global__ __launch_bounds__(256) void gemm_kvproj(
    const __half* __restrict__ A, const __half* __restrict__ Bm,
    const float* __restrict__ bias,
    __half* __restrict__ kh, __half* __restrict__ vh)
{
    extern __shared__ char gsm[];
    const uint32_t sBase = smem_to_u32(gsm);
    const int tid = threadIdx.x;
    const int wid = tid >> 5, lane = tid & 31;
    const int mBase = blockIdx.y * 128;
    const int nBase = blockIdx.x * 128;
    const int warpM = (wid >> 1) * 32;
    const int warpN = (wid & 1) * 64;
    const int N = 2 * H_ * DQK_, K = D_;

    float acc[2][8][4];
    gemm_mainloop(sBase, N, K, A, Bm, bias, mBase, nBase, warpM, warpN, tid, lane, acc);

    const int colBase = nBase + warpN;
    const bool isK = colBase < H_ * DQK_;
    const int hcol = (colBase & (H_ * DQK_ - 1)) >> 6;

    #pragma unroll
    for (int mi = 0; mi < 2; mi++) {
        int r0 = mBase + warpM + mi * 16 + (lane >> 2);
        int r1 = r0 + 8;
        int s0 = r0 & (S_ - 1), b0 = r0 >> 12;
        int s1 = r1 & (S_ - 1), b1 = r1 >> 12;
        size_t base0 = (((size_t)(b0 * H_ + hcol) * S_) + s0) * DQK_;
        size_t base1 = (((size_t)(b1 * H_ + hcol) * S_) + s1) * DQK_;

        if (isK) {
            float pos0 = (float)s0, pos1 = (float)s1;
            #pragma unroll
            for (int ni = 0; ni < 4; ni++) {
                int d0 = ni * 8 + (lane & 3) * 2;
                float f0 = inv_freq_f(d0), f1 = inv_freq_f(d0 + 1);
                {
                    float a0 = pos0 * f0, a1 = pos0 * f1;
                    float c0 = cosf(a0), sn0 = sinf(a0), c1 = cosf(a1), sn1 = sinf(a1);
                    float x1a = acc[mi][ni][0],     x1b = acc[mi][ni][1];
                    float x2a = acc[mi][ni + 4][0], x2b = acc[mi][ni + 4][1];
                    *(uint32_t*)(kh + base0 + d0) =
                        packhf(x1a * c0 - x2a * sn0, x1b * c1 - x2b * sn1);
                    *(uint32_t*)(kh + base0 + d0 + 32) =
                        packhf(x1a * sn0 + x2a * c0, x1b * sn1 + x2b * c1);
                }
                {
                    float a0 = pos1 * f0, a1 = pos1 * f1;
                    float c0 = cosf(a0), sn0 = sinf(a0), c1 = cosf(a1), sn1 = sinf(a1);
                    float x1a = acc[mi][ni][2],     x1b = acc[mi][ni][3];
                    float x2a = acc[mi][ni + 4][2], x2b = acc[mi][ni + 4][3];
                    *(uint32_t*)(kh + base1 + d0) =
                        packhf(x1a * c0 - x2a * sn0, x1b * c1 - x2b * sn1);
                    *(uint32_t*)(kh + base1 + d0 + 32) =
                        packhf(x1a * sn0 + x2a * c0, x1b * sn1 + x2b * c1);
                }
            }
        } else {
            #pragma unroll
            for (int ni = 0; ni < 8; ni++) {
                int d0 = ni * 8 + (lane & 3) * 2;
                *(uint32_t*)(vh + base0 + d0) = packhf(acc[mi][ni][0], acc[mi][ni][1]);
                *(uint32_t*)(vh + base1 + d0) = packhf(acc[mi][ni][2], acc[mi][ni][3]);
            }
        }
    }
}

// ---------------- fused final GEMM: out = x16@wbyp + attn16@wout + wout_b ----------------
__global__ __launch_bounds__(256) void gemm_final(
    const __half* __restrict__ Ax,   // x16 [2048, 2048]
    const __half* __restrict__ Aat,  // attn16 [2048, 1024]
    const __half* __restrict__ Bbyp, // [2048, 1024]
    const __half* __restrict__ Bout, // [1024, 1024]
    const float* __restrict__ bias, float* __restrict__ C)
{
    extern __shared__ char gsm[];
    const uint32_t sBase = smem_to_u32(gsm);
    const int tid = threadIdx.x;
    const int wid = tid >> 5, lane = tid & 31;
    const int mBase = blockIdx.y * 128;
    const int nBase = blockIdx.x * 128;
    const int warpM = (wid >> 1) * 32;
    const int warpN = (wid & 1) * 64;

    const int N  = DLAT_;
    const int KA = BPL_ * D_;       // 2048 (segment boundary)
    const int KT = KA + H_ * DQK_;  // 3072
    const int cpk = KT / BKF;       // 96

    const int arow0 = tid >> 2, aseg = (tid & 3) * 8;
    const int brow0 = tid >> 4, bseg = (tid & 15) * 8;

    float acc[2][8][4];
    #pragma unroll
    for (int mi = 0; mi < 2; mi++)
        #pragma unroll
        for (int ni = 0; ni < 8; ni++)
            #pragma unroll
            for (int c = 0; c < 4; c++) acc[mi][ni][c] = 0.0f;

    auto issue = [&](int chunk) {
        int buf = chunk & 1;
        int k0 = chunk * BKF;
        uint32_t da = sBase + buf * G1_STG;
        uint32_t db = da + G1_A_B;
        const __half* aptr;
        size_t astr;
        const __half* bptr;
        if (k0 < KA) {
            aptr = Ax + (size_t)mBase * KA + k0 + aseg;
            astr = KA;
            bptr = Bbyp + (size_t)k0 * N + nBase + bseg;
        } else {
            int k1 = k0 - KA;
            aptr = Aat + (size_t)mBase * (H_ * DQK_) + k1 + aseg;
            astr = H_ * DQK_;
            bptr = Bout + (size_t)k1 * N + nBase + bseg;
        }
        #pragma unroll
        for (int it = 0; it < 2; it++) {
            int row = arow0 + it * 64;
            CP_ASYNC16(da + row * (ASTR * 2) + aseg * 2, aptr + (size_t)row * astr);
        }
        #pragma unroll
        for (int it = 0; it < 2; it++) {
            int row = brow0 + it * 16;
            CP_ASYNC16(db + row * (BSTR * 2) + bseg * 2, bptr + (size_t)row * N);
        }
        CP_COMMIT();
    };

    issue(0);

    for (int i = 0; i < cpk; i++) {
        if (i + 1 < cpk) { issue(i + 1); CP_WAIT1(); }
        else             { CP_WAIT0(); }
        __syncthreads();

        const uint32_t aBase = sBase + (i & 1) * G1_STG;
        const uint32_t bBase = aBase + G1_A_B;

        #pragma unroll
        for (int kk = 0; kk < 2; kk++) {
            uint32_t afrag[2][4];
            #pragma unroll
            for (int mi = 0; mi < 2; mi++) {
                uint32_t addr = aBase
                    + (warpM + mi * 16 + (lane & 15)) * (ASTR * 2)
                    + ((lane >> 4) << 4) + kk * 32;
                ldmA(afrag[mi], addr);
            }
            uint32_t bf[4][4];
            int grp = lane >> 3, r = lane & 7;
            #pragma unroll
            for (int p = 0; p < 4; p++) {
                uint32_t addr = bBase
                    + (kk * 16 + (grp & 1) * 8 + r) * (BSTR * 2)
                    + (warpN + p * 16 + (grp >> 1) * 8) * 2;
                ldmBT(bf[p], addr);
            }
            #pragma unroll
            for (int mi = 0; mi < 2; mi++)
                #pragma unroll
                for (int ni = 0; ni < 8; ni++) {
                    int g = ni >> 1, s = (ni & 1) * 2;
                    mma16816h(acc[mi][ni], afrag[mi], bf[g][s], bf[g][s + 1]);
                }
        }
        __syncthreads();
    }

    #pragma unroll
    for (int mi = 0; mi < 2; mi++) {
        #pragma unroll
        for (int ni = 0; ni < 8; ni++) {
            int r0 = mBase + warpM + mi * 16 + (lane >> 2);
            int c  = nBase + warpN + ni * 8 + (lane & 3) * 2;
            float2 bb = *(const float2*)(bias + c);
            float2 v0 = make_float2(acc[mi][ni][0] + bb.x, acc[mi][ni][1] + bb.y);
            float2 v1 = make_float2(acc[mi][ni][2] + bb.x, acc[mi][ni][3] + bb.y);
            *(float2*)(C + (size_t)r0 * N + c) = v0;
            *(float2*)(C + (size_t)(r0 + 8) * N + c) = v1;
        }
    }
}

// ---------------- flash attention via fp16 mma (single-term) ----------------
// __launch_bounds__(256, 2): cap regs at 128 so 2 CTAs/SM fit -> 4 warps/SMSP,
// whole 256-CTA grid resident in one wave.
#define FSTG 18432
#define FSMEM (2 * FSTG)

__global__ __launch_bounds__(256, 2) void flash_mma(
    const __half* __restrict__ qh,
    const __half* __restrict__ kh, const __half* __restrict__ vh,
    __half* __restrict__ oh)
{
    extern __shared__ char sm[];
    const uint32_t sb = smem_to_u32(sm);
    const int tid = threadIdx.x, wid = tid >> 5, lane = tid & 31;
    const int bh = blockIdx.y;
    const int q0 = blockIdx.x * 128;
    const int warpM = wid * 16;
    const size_t qoff = ((size_t)bh * LQ_ + q0) * DQK_;
    const size_t koff = (size_t)bh * S_ * DQK_;

    {
        #pragma unroll
        for (int it = 0; it < 4; it++) {
            int e = it * 256 + tid;
            int row = e >> 3, seg = (e & 7) * 8;
            CP_ASYNC16(sb + FSTG + row * 144 + seg * 2, qh + qoff + (size_t)row * DQK_ + seg);
        }
        CP_COMMIT();
    }

    auto issueKV = [&](int tile, int stage) {
        int sk = tile * 64;
        uint32_t dst = sb + stage * FSTG;
        #pragma unroll
        for (int it = 0; it < 2; it++) {
            int e = it * 256 + tid;
            int row = e >> 3, seg = (e & 7) * 8;
            size_t g = koff + (size_t)(sk + row) * DQK_ + seg;
            uint32_t so = row * 144 + seg * 2;
            CP_ASYNC16(dst + so,        kh + g);
            CP_ASYNC16(dst + 9216 + so, vh + g);
        }
    };

    issueKV(0, 0); CP_COMMIT();
    CP_WAIT1(); __syncthreads();

    uint32_t Qf[4][4];
    #pragma unroll
    for (int kt = 0; kt < 4; kt++) {
        uint32_t ad = sb + FSTG + (warpM + (lane & 15)) * 144 + ((lane >> 4) << 4) + kt * 32;
        ldmA(Qf[kt], ad);
    }
    __syncthreads();
    issueKV(1, 1); CP_COMMIT();

    float acc[8][4];
    #pragma unroll
    for (int n = 0; n < 8; n++)
        #pragma unroll
        for (int c = 0; c < 4; c++) acc[n][c] = 0.0f;
    float m0 = -1e30f, m1 = -1e30f, l0 = 0.0f, l1 = 0.0f;

    for (int i = 0; i < S_ / 64; i++) {
        CP_WAIT1(); __syncthreads();
        const uint32_t kb = sb + (i & 1) * FSTG;

        float sc[8][4];
        #pragma unroll
        for (int n = 0; n < 8; n++)
            #pragma unroll
            for (int c = 0; c < 4; c++) sc[n][c] = 0.0f;

        #pragma unroll
        for (int kt = 0; kt < 4; kt++) {
            uint32_t Bh[4][4];
            #pragma unroll
            for (int p = 0; p < 4; p++) {
                uint32_t ad = kb + (p * 16 + (lane & 15)) * 144 + ((lane >> 4) << 4) + kt * 32;
                ldmA(Bh[p], ad);
            }
            #pragma unroll
            for (int ni = 0; ni < 8; ni++) {
                int g = ni >> 1, s = ni & 1;
                mma16816h(sc[ni], Qf[kt], Bh[g][s], Bh[g][s + 2]);
            }
        }

        float r0 = -1e30f, r1 = -1e30f;
        #pragma unroll
        for (int ni = 0; ni < 8; ni++) {
            r0 = fmaxf(r0, fmaxf(sc[ni][0], sc[ni][1]));
            r1 = fmaxf(r1, fmaxf(sc[ni][2], sc[ni][3]));
        }
        r0 = fmaxf(r0, __shfl_xor_sync(0xffffffffu, r0, 1));
        r0 = fmaxf(r0, __shfl_xor_sync(0xffffffffu, r0, 2));
        r1 = fmaxf(r1, __shfl_xor_sync(0xffffffffu, r1, 1));
        r1 = fmaxf(r1, __shfl_xor_sync(0xffffffffu, r1, 2));
        float mn0 = fmaxf(m0, r0), mn1 = fmaxf(m1, r1);
        float c0 = __expf(m0 - mn0), c1 = __expf(m1 - mn1);
        l0 *= c0; l1 *= c1;
        #pragma unroll
        for (int ni = 0; ni < 8; ni++) {
            acc[ni][0] *= c0; acc[ni][1] *= c0;
            acc[ni][2] *= c1; acc[ni][3] *= c1;
        }
        m0 = mn0; m1 = mn1;

        #pragma unroll
        for (int kt = 0; kt < 4; kt++) {
            uint32_t ph[4];
            #pragma unroll
            for (int j = 0; j < 2; j++) {
                int ni = 2 * kt + j;
                float p0 = __expf(sc[ni][0] - m0);
                float p1 = __expf(sc[ni][1] - m0);
                float p2 = __expf(sc[ni][2] - m1);
                float p3 = __expf(sc[ni][3] - m1);
                l0 += p0 + p1; l1 += p2 + p3;
                ph[2 * j]     = packhf(p0, p1);
                ph[2 * j + 1] = packhf(p2, p3);
            }
            uint32_t Vf[4][4];
            int grp = lane >> 3, rr = lane & 7;
            #pragma unroll
            for (int p = 0; p < 4; p++) {
                uint32_t ad = kb + 9216
                    + (kt * 16 + (grp & 1) * 8 + rr) * 144
                    + (p * 16 + (grp >> 1) * 8) * 2;
                ldmBT(Vf[p], ad);
            }
            #pragma unroll
            for (int nv = 0; nv < 8; nv++) {
                int g = nv >> 1, s = (nv & 1) * 2;
                mma16816h(acc[nv], ph, Vf[g][s], Vf[g][s + 1]);
            }
        }

        __syncthreads();
        if (i + 2 < S_ / 64) issueKV(i + 2, i & 1);
        CP_COMMIT();
    }

    l0 += __shfl_xor_sync(0xffffffffu, l0, 1);
    l0 += __shfl_xor_sync(0xffffffffu, l0, 2);
    l1 += __shfl_xor_sync(0xffffffffu, l1, 1);
    l1 += __shfl_xor_sync(0xffffffffu, l1, 2);
    float i0 = 1.0f / l0, i1 = 1.0f / l1;

    int b = bh >> 4, h = bh & 15;
    int row0 = q0 + warpM + (lane >> 2);
    size_t ob0 = (size_t)(b * LQ_ + row0) * (H_ * DQK_) + h * DQK_;
    size_t ob1 = ob0 + (size_t)8 * (H_ * DQK_);
    #pragma unroll
    for (int nv = 0; nv < 8; nv++) {
        int col = nv * 8 + (lane & 3) * 2;
        *(uint32_t*)(oh + ob0 + col) = packhf(acc[nv][0] * i0, acc[nv][1] * i0);
        *(uint32_t*)(oh + ob1 + col) = packhf(acc[nv][2] * i1, acc[nv][3] * i1);
    }
}

// ---------------- launch ----------------
extern "C" void kernel_launch(void* const* d_in, const int* in_sizes, int n_in,
                              void* d_out, int out_size)
{
    (void)in_sizes; (void)n_in; (void)out_size;
    const float* x      = (const float*)d_in[0];
    const float* norm_w = (const float*)d_in[1];
    const float* wq_w   = (const float*)d_in[2];
    const float* wq_b   = (const float*)d_in[3];
    const float* wkv_w  = (const float*)d_in[4];
    const float* wkv_b  = (const float*)d_in[5];
    const float* wout_w = (const float*)d_in[6];
    const float* wout_b = (const float*)d_in[7];
    const float* wbyp_w = (const float*)d_in[8];
    float* out = (float*)d_out;

    __half *nh, *wqh, *wkvh, *pqh, *pkh, *pvh, *x16, *at16, *wout16, *wbyp16;
    cudaGetSymbolAddress((void**)&nh,     g_nh);
    cudaGetSymbolAddress((void**)&wqh,    g_wqh);
    cudaGetSymbolAddress((void**)&wkvh,   g_wkvh);
    cudaGetSymbolAddress((void**)&pqh,    g_qh);
    cudaGetSymbolAddress((void**)&pkh,    g_kh);
    cudaGetSymbolAddress((void**)&pvh,    g_vh);
    cudaGetSymbolAddress((void**)&x16,    g_x16);
    cudaGetSymbolAddress((void**)&at16,   g_attn16);
    cudaGetSymbolAddress((void**)&wout16, g_wout16);
    cudaGetSymbolAddress((void**)&wbyp16, g_wbyp16);

    cudaFuncSetAttribute(flash_mma,   cudaFuncAttributeMaxDynamicSharedMemorySize, FSMEM);
    cudaFuncSetAttribute(gemm_qproj,  cudaFuncAttributeMaxDynamicSharedMemorySize, G1_SMEM);
    cudaFuncSetAttribute(gemm_kvproj, cudaFuncAttributeMaxDynamicSharedMemorySize, G1_SMEM);
    cudaFuncSetAttribute(gemm_final,  cudaFuncAttributeMaxDynamicSharedMemorySize, G1_SMEM);

    // 1. RMSNorm -> nh (fp16) + x16 (fp16)
    rmsnorm_kernel<<<B_ * S_, 128>>>(x, norm_w, nh, x16);

    // 2. all weight conversions in one launch
    convw_kernel<<<(WTOT4 + 255) / 256, 256>>>(
        wq_w, wkv_w, wout_w, wbyp_w, wqh, wkvh, wout16, wbyp16);

    // 3. Q projection + fused RoPE -> qh
    gemm_qproj<<<dim3((H_ * DQK_) / 128, (B_ * LQ_) / 128), 256, G1_SMEM>>>(
        nh, wqh, wq_b, pqh);

    // 4. KV projection + fused RoPE-K / transpose-V -> kh, vh
    gemm_kvproj<<<dim3((2 * H_ * DQK_) / 128, (B_ * S_) / 128), 256, G1_SMEM>>>(
        nh, wkvh, wkv_b, pkh, pvh);

    // 5. Flash attention -> attn fp16
    flash_mma<<<dim3(LQ_ / 128, B_ * H_), 256, FSMEM>>>(pqh, pkh, pvh, at16);

    // 6. Fused final GEMM: out = x16@wbyp + attn16@wout + wout_b
    gemm_final<<<dim3(DLAT_ / 128, (B_ * LQ_) / 128), 256, G1_SMEM>>>(
        x16, at16, wbyp16, wout16, wout_b, out);
}